// round 3
// baseline (speedup 1.0000x reference)
#include <cuda_runtime.h>
#include <math.h>

#define Bn    64
#define Nn    256
#define XDim  118
#define EDim  5
#define Hd    384
#define NHd   8
#define DHd   48
#define DFFd  1536
#define DEPTH 6
#define Mrows (Bn * Nn)            /* 16384 */
#define KCAT  (XDim + Nn * EDim)   /* 1398  */
#define KPAD  1408                 /* KCAT padded to multiple of 32 */
#define EROW  (Nn * EDim)          /* 1280  */

// ---------------- scratch (device globals; no allocation) ----------------
__device__ float g_cat[(size_t)Mrows * KPAD];        // 88MB (zero-padded K)
__device__ float g_wembp[(size_t)KPAD * Hd];         // padded embedding weight
__device__ float g_z  [(size_t)Mrows * Hd];
__device__ float g_q  [(size_t)Mrows * Hd];
__device__ float g_k  [(size_t)Mrows * Hd];
__device__ float g_v  [(size_t)Mrows * Hd];
__device__ float g_y  [(size_t)Mrows * Hd];
__device__ float g_x1 [(size_t)Mrows * Hd];
__device__ float g_ffn[(size_t)Mrows * DFFd];
__device__ float g_att[(size_t)Bn * NHd * Nn * Nn];  // 33.5M
__device__ float g_D  [(size_t)Bn * Nn * Nn];        // 4.2M
__device__ float g_sq [Mrows];

// ---------------- reductions ----------------
__device__ __forceinline__ float blockmax256(float v) {
    __shared__ float red[8];
    #pragma unroll
    for (int o = 16; o > 0; o >>= 1) v = fmaxf(v, __shfl_xor_sync(0xffffffffu, v, o));
    if ((threadIdx.x & 31) == 0) red[threadIdx.x >> 5] = v;
    __syncthreads();
    float m = red[0];
    #pragma unroll
    for (int i = 1; i < 8; i++) m = fmaxf(m, red[i]);
    __syncthreads();
    return m;
}

__device__ __forceinline__ float blocksum256(float v) {
    __shared__ float red[8];
    #pragma unroll
    for (int o = 16; o > 0; o >>= 1) v += __shfl_xor_sync(0xffffffffu, v, o);
    if ((threadIdx.x & 31) == 0) red[threadIdx.x >> 5] = v;
    __syncthreads();
    float s = red[0];
    #pragma unroll
    for (int i = 1; i < 8; i++) s += red[i];
    __syncthreads();
    return s;
}

__device__ __forceinline__ float blocksum128(float v) {
    __shared__ float red[4];
    #pragma unroll
    for (int o = 16; o > 0; o >>= 1) v += __shfl_xor_sync(0xffffffffu, v, o);
    if ((threadIdx.x & 31) == 0) red[threadIdx.x >> 5] = v;
    __syncthreads();
    float s = red[0] + red[1] + red[2] + red[3];
    __syncthreads();
    return s;
}

// ---------------- tf32 helpers ----------------
__device__ __forceinline__ float to_tf32(float x) {
    unsigned u;
    asm("cvt.rna.tf32.f32 %0, %1;" : "=r"(u) : "f"(x));
    return __uint_as_float(u);
}

__device__ __forceinline__ void mma8(float* d, const float4& a, const float2& b) {
    asm volatile(
        "mma.sync.aligned.m16n8k8.row.col.f32.tf32.tf32.f32 "
        "{%0,%1,%2,%3}, {%4,%5,%6,%7}, {%8,%9}, {%0,%1,%2,%3};\n"
        : "+f"(d[0]), "+f"(d[1]), "+f"(d[2]), "+f"(d[3])
        : "r"(__float_as_uint(a.x)), "r"(__float_as_uint(a.y)),
          "r"(__float_as_uint(a.z)), "r"(__float_as_uint(a.w)),
          "r"(__float_as_uint(b.x)), "r"(__float_as_uint(b.y)));
}

// ---------------- concat [x | e_flat | 0-pad] ----------------
__global__ void cat_kernel(const float* __restrict__ x, const float* __restrict__ e) {
    size_t idx = (size_t)blockIdx.x * blockDim.x + threadIdx.x;
    if (idx >= (size_t)Mrows * KPAD) return;
    size_t r = idx / KPAD;
    int    c = (int)(idx - r * KPAD);
    float v;
    if (c < XDim)      v = x[r * XDim + c];
    else if (c < KCAT) v = e[r * (size_t)EROW + (c - XDim)];
    else               v = 0.f;
    g_cat[idx] = v;
}

__global__ void wembpad_kernel(const float* __restrict__ Wemb) {
    size_t idx = (size_t)blockIdx.x * blockDim.x + threadIdx.x;
    if (idx >= (size_t)KPAD * Hd) return;
    size_t row = idx / Hd;
    g_wembp[idx] = (row < KCAT) ? Wemb[idx] : 0.f;
}

// ============================================================================
// tf32 tensor-core SGEMM: C[M,N] = A[M,K] @ B[K,N] (+bias)(+relu)
// BM=128, BN=128, BK=32, 256 threads (8 warps, 2x4 warp grid, 64x32 warp tile)
// Requires: M%128==0, N%128==0, K%32==0, all pointers/ld 16B-aligned.
// Smem staged fragment-major so frag loads are conflict-free LDS.128/LDS.64.
// ============================================================================
__device__ __forceinline__ void stage_store(
    float* __restrict__ Asb, float* __restrict__ Bsb,
    const float4* aS, const float4* bS, int t)
{
    const int aRow = t >> 3, aColB = (t & 7) * 4;
    #pragma unroll
    for (int i = 0; i < 4; i++) {
        int m  = aRow + 32 * i;
        int im = m >> 4, g = m & 7, hi = (m >> 3) & 1;
        float v[4] = {aS[i].x, aS[i].y, aS[i].z, aS[i].w};
        #pragma unroll
        for (int j = 0; j < 4; j++) {
            int k  = aColB + j;
            int ks = k >> 3, c = k & 3, ch2 = (k >> 2) & 1;
            Asb[(im * 128 + ks * 32 + g * 4 + c) * 4 + hi + 2 * ch2] = to_tf32(v[j]);
        }
    }
    const int bRow = t >> 5, bColB = (t & 31) * 4;
    #pragma unroll
    for (int i = 0; i < 4; i++) {
        int k  = bRow + 8 * i;
        int ks = k >> 3, c = k & 3, r = (k >> 2) & 1;
        float v[4] = {bS[i].x, bS[i].y, bS[i].z, bS[i].w};
        #pragma unroll
        for (int j = 0; j < 4; j++) {
            int n  = bColB + j;
            int in = n >> 3, gB = n & 7;
            Bsb[(in * 128 + ks * 32 + gB * 4 + c) * 2 + r] = to_tf32(v[j]);
        }
    }
}

__global__ __launch_bounds__(256) void gemm_tf32_kernel(
    const float* __restrict__ A, int lda,
    const float* __restrict__ Bm, int ldb,
    const float* __restrict__ bias,
    float* __restrict__ C, int ldc,
    int K, int relu)
{
    extern __shared__ float sm[];
    float* Asbuf[2] = { sm,        sm + 4096 };
    float* Bsbuf[2] = { sm + 8192, sm + 12288 };

    const int t    = threadIdx.x;
    const int lane = t & 31, warp = t >> 5;
    const int m0 = blockIdx.y * 128, n0 = blockIdx.x * 128;
    const int imB = (warp >> 2) * 4;   // abs m16-subtile base (0 or 4)
    const int inB = (warp & 3) * 4;    // abs n8-subtile base (0,4,8,12)

    float acc[4][4][4];
    #pragma unroll
    for (int i = 0; i < 4; i++)
        #pragma unroll
        for (int j = 0; j < 4; j++)
            #pragma unroll
            for (int r = 0; r < 4; r++) acc[i][j][r] = 0.f;

    const int aRow = t >> 3, aCol = (t & 7) * 4;
    const int bRow = t >> 5, bCol = (t & 31) * 4;

    float4 aS[4], bS[4];
    #pragma unroll
    for (int i = 0; i < 4; i++)
        aS[i] = *(const float4*)(A + (size_t)(m0 + aRow + 32 * i) * lda + aCol);
    #pragma unroll
    for (int i = 0; i < 4; i++)
        bS[i] = *(const float4*)(Bm + (size_t)(bRow + 8 * i) * ldb + n0 + bCol);
    stage_store(Asbuf[0], Bsbuf[0], aS, bS, t);
    __syncthreads();

    const int nch = K >> 5;
    for (int ch = 0; ch < nch; ++ch) {
        const int buf = ch & 1;
        if (ch + 1 < nch) {
            const int k0 = (ch + 1) << 5;
            #pragma unroll
            for (int i = 0; i < 4; i++)
                aS[i] = *(const float4*)(A + (size_t)(m0 + aRow + 32 * i) * lda + k0 + aCol);
            #pragma unroll
            for (int i = 0; i < 4; i++)
                bS[i] = *(const float4*)(Bm + (size_t)(k0 + bRow + 8 * i) * ldb + n0 + bCol);
        }
        const float4* A4 = (const float4*)Asbuf[buf];
        const float2* B2 = (const float2*)Bsbuf[buf];
        #pragma unroll
        for (int ks = 0; ks < 4; ks++) {
            float4 av[4];
            float2 bv[4];
            #pragma unroll
            for (int i = 0; i < 4; i++) av[i] = A4[(imB + i) * 128 + ks * 32 + lane];
            #pragma unroll
            for (int j = 0; j < 4; j++) bv[j] = B2[(inB + j) * 128 + ks * 32 + lane];
            #pragma unroll
            for (int i = 0; i < 4; i++)
                #pragma unroll
                for (int j = 0; j < 4; j++) mma8(acc[i][j], av[i], bv[j]);
        }
        if (ch + 1 < nch) {
            stage_store(Asbuf[buf ^ 1], Bsbuf[buf ^ 1], aS, bS, t);
            __syncthreads();
        }
    }

    // epilogue
    const int gr = m0 + (warp >> 2) * 64 + (lane >> 2);
    const int gc = n0 + (warp & 3) * 32 + (lane & 3) * 2;
    #pragma unroll
    for (int i = 0; i < 4; i++) {
        const int r0 = gr + i * 16;
        #pragma unroll
        for (int j = 0; j < 4; j++) {
            const int cc = gc + j * 8;
            float b0 = 0.f, b1 = 0.f;
            if (bias) { b0 = bias[cc]; b1 = bias[cc + 1]; }
            float2 v0 = make_float2(acc[i][j][0] + b0, acc[i][j][1] + b1);
            float2 v1 = make_float2(acc[i][j][2] + b0, acc[i][j][3] + b1);
            if (relu) {
                v0.x = fmaxf(v0.x, 0.f); v0.y = fmaxf(v0.y, 0.f);
                v1.x = fmaxf(v1.x, 0.f); v1.y = fmaxf(v1.y, 0.f);
            }
            *(float2*)(C + (size_t)r0 * ldc + cc)       = v0;
            *(float2*)(C + (size_t)(r0 + 8) * ldc + cc) = v1;
        }
    }
}

// ---------------- row squared norms of z ----------------
__global__ void sqnorm_kernel() {
    int r = blockIdx.x;
    float s = 0.f;
    for (int c = threadIdx.x; c < Hd; c += 128) {
        float v = g_z[(size_t)r * Hd + c];
        s += v * v;
    }
    s = blocksum128(s);
    if (threadIdx.x == 0) g_sq[r] = s;
}

// ---------------- masked pairwise distance: g_D = cdist(z,z)*dm ----------------
__global__ __launch_bounds__(256) void dist_kernel(const float* __restrict__ mask) {
    int b  = blockIdx.z;
    int ti = blockIdx.y * 64, tj = blockIdx.x * 64;
    const float* zb = g_z + (size_t)b * Nn * Hd;
    __shared__ float Zi[16][64];
    __shared__ float Zj[16][64];
    int t = threadIdx.x, tx = t & 15, ty = t >> 4;
    float acc[4][4];
    #pragma unroll
    for (int i = 0; i < 4; i++)
        #pragma unroll
        for (int j = 0; j < 4; j++) acc[i][j] = 0.f;

    int l = t * 4, ar = l >> 4, ac = l & 15;
    for (int k0 = 0; k0 < Hd; k0 += 16) {
        #pragma unroll
        for (int u = 0; u < 4; u++) {
            Zi[ac + u][ar] = zb[(size_t)(ti + ar) * Hd + k0 + ac + u];
            Zj[ac + u][ar] = zb[(size_t)(tj + ar) * Hd + k0 + ac + u];
        }
        __syncthreads();
        #pragma unroll
        for (int kk = 0; kk < 16; kk++) {
            float a[4], bb[4];
            #pragma unroll
            for (int i = 0; i < 4; i++) a[i] = Zi[kk][ty * 4 + i];
            #pragma unroll
            for (int j = 0; j < 4; j++) bb[j] = Zj[kk][tx * 4 + j];
            #pragma unroll
            for (int i = 0; i < 4; i++)
                #pragma unroll
                for (int j = 0; j < 4; j++) acc[i][j] = fmaf(a[i], bb[j], acc[i][j]);
        }
        __syncthreads();
    }
    #pragma unroll
    for (int i = 0; i < 4; i++) {
        int gi = ti + ty * 4 + i;
        float sqi = g_sq[b * Nn + gi], mi = mask[b * Nn + gi];
        #pragma unroll
        for (int j = 0; j < 4; j++) {
            int gj = tj + tx * 4 + j;
            float d2 = sqi + g_sq[b * Nn + gj] - 2.f * acc[i][j];
            d2 = fmaxf(d2, 0.f);
            float d  = (d2 > 1e-12f) ? sqrtf(d2) : 0.f;
            float dm = mi * mask[b * Nn + gj];
            g_D[((size_t)b * Nn + gi) * Nn + gj] = d * dm;
        }
    }
}

// ---------------- bias: D = (rowmax - D) masked, diag 0 ----------------
__global__ void distbias_kernel(const float* __restrict__ mask) {
    int r = blockIdx.x;            // b*Nn + i
    int b = r / Nn, i = r - b * Nn;
    float* p = g_D + (size_t)r * Nn;
    int t = threadIdx.x;
    float v  = p[t];
    float bm = blockmax256(v);
    float dm = mask[r] * mask[b * Nn + t];
    p[t] = (t == i) ? 0.f : (bm - v) * dm;
}

// ---------------- scores = QK^T/sqrt(48) + D ----------------
__global__ __launch_bounds__(256) void qk_kernel() {
    int bh = blockIdx.z;
    int b  = bh / NHd, h = bh - b * NHd;
    int ti = blockIdx.y * 64, tj = blockIdx.x * 64;
    const float* qb = g_q + (size_t)b * Nn * Hd + h * DHd;
    const float* kb = g_k + (size_t)b * Nn * Hd + h * DHd;
    __shared__ float Qs[64][49];
    __shared__ float Ks[64][49];
    int t = threadIdx.x, tx = t & 15, ty = t >> 4;
    for (int l = t; l < 64 * 48; l += 256) {
        int r = l / 48, c = l - r * 48;
        Qs[r][c] = qb[(size_t)(ti + r) * Hd + c];
        Ks[r][c] = kb[(size_t)(tj + r) * Hd + c];
    }
    __syncthreads();
    float acc[4][4];
    #pragma unroll
    for (int i = 0; i < 4; i++)
        #pragma unroll
        for (int j = 0; j < 4; j++) acc[i][j] = 0.f;
    #pragma unroll 4
    for (int kk = 0; kk < 48; kk++) {
        float a[4], bb[4];
        #pragma unroll
        for (int i = 0; i < 4; i++) a[i] = Qs[ty * 4 + i][kk];
        #pragma unroll
        for (int j = 0; j < 4; j++) bb[j] = Ks[tx * 4 + j][kk];
        #pragma unroll
        for (int i = 0; i < 4; i++)
            #pragma unroll
            for (int j = 0; j < 4; j++) acc[i][j] = fmaf(a[i], bb[j], acc[i][j]);
    }
    const float scale = 0.144337567297406441f;  // 1/sqrt(48)
    #pragma unroll
    for (int i = 0; i < 4; i++) {
        int gi = ti + ty * 4 + i;
        #pragma unroll
        for (int j = 0; j < 4; j++) {
            int gj = tj + tx * 4 + j;
            g_att[((size_t)bh * Nn + gi) * Nn + gj] =
                acc[i][j] * scale + g_D[((size_t)b * Nn + gi) * Nn + gj];
        }
    }
}

// ---------------- softmax over last dim (rows of 256) ----------------
__global__ void softmax_kernel() {
    float* p = g_att + (size_t)blockIdx.x * Nn;
    int t = threadIdx.x;
    float v  = p[t];
    float bm = blockmax256(v);
    float e  = __expf(v - bm);
    float s  = blocksum256(e);
    p[t] = e / s;
}

// ---------------- y = attn @ V ----------------
__global__ __launch_bounds__(256) void attnv_kernel() {
    int bh = blockIdx.y;
    int b  = bh / NHd, h = bh - b * NHd;
    int ti = blockIdx.x * 64;
    const float* arow = g_att + (size_t)bh * Nn * Nn;
    const float* vb   = g_v + (size_t)b * Nn * Hd + h * DHd;
    __shared__ float As[64][65];
    __shared__ float Vs[64][49];
    int t = threadIdx.x, tx = t & 15, ty = t >> 4;
    float acc[4][3];
    #pragma unroll
    for (int i = 0; i < 4; i++)
        #pragma unroll
        for (int j = 0; j < 3; j++) acc[i][j] = 0.f;

    for (int j0 = 0; j0 < Nn; j0 += 64) {
        for (int l = t; l < 64 * 64; l += 256)
            As[l >> 6][l & 63] = arow[(size_t)(ti + (l >> 6)) * Nn + j0 + (l & 63)];
        for (int l = t; l < 64 * 48; l += 256) {
            int r = l / 48, c = l - r * 48;
            Vs[r][c] = vb[(size_t)(j0 + r) * Hd + c];
        }
        __syncthreads();
        #pragma unroll 4
        for (int kk = 0; kk < 64; kk++) {
            float a[4], bb[3];
            #pragma unroll
            for (int i = 0; i < 4; i++) a[i] = As[ty * 4 + i][kk];
            #pragma unroll
            for (int j = 0; j < 3; j++) bb[j] = Vs[kk][tx * 3 + j];
            #pragma unroll
            for (int i = 0; i < 4; i++)
                #pragma unroll
                for (int j = 0; j < 3; j++) acc[i][j] = fmaf(a[i], bb[j], acc[i][j]);
        }
        __syncthreads();
    }
    #pragma unroll
    for (int i = 0; i < 4; i++) {
        int gi = ti + ty * 4 + i;
        #pragma unroll
        for (int j = 0; j < 3; j++)
            g_y[((size_t)b * Nn + gi) * Hd + h * DHd + tx * 3 + j] = acc[i][j];
    }
}

// ---------------- out = LayerNorm(a + r) ----------------
__global__ void addln_kernel(const float* __restrict__ a, const float* __restrict__ r,
                             const float* __restrict__ g, const float* __restrict__ be,
                             float* __restrict__ out) {
    int row = blockIdx.x;
    int t = threadIdx.x;
    float vals[3];
    float s = 0.f;
    #pragma unroll
    for (int u = 0; u < 3; u++) {
        int c = t + u * 128;
        float v = a[(size_t)row * Hd + c] + r[(size_t)row * Hd + c];
        vals[u] = v;
        s += v;
    }
    float mu = blocksum128(s) * (1.f / Hd);
    float s2 = 0.f;
    #pragma unroll
    for (int u = 0; u < 3; u++) { float d = vals[u] - mu; s2 += d * d; }
    float var  = blocksum128(s2) * (1.f / Hd);
    float rstd = rsqrtf(var + 1e-5f);
    #pragma unroll
    for (int u = 0; u < 3; u++) {
        int c = t + u * 128;
        out[(size_t)row * Hd + c] = (vals[u] - mu) * rstd * g[c] + be[c];
    }
}

// ---------------- masked outputs ----------------
__global__ void out_x_kernel(const float* __restrict__ x, const float* __restrict__ mask,
                             float* __restrict__ out) {
    size_t idx = (size_t)blockIdx.x * blockDim.x + threadIdx.x;
    if (idx >= (size_t)Bn * Nn * XDim) return;
    out[idx] = x[idx] * mask[idx / XDim];
}
__global__ void out_e_kernel(const float* __restrict__ e, const float* __restrict__ mask,
                             float* __restrict__ out) {
    size_t idx = (size_t)blockIdx.x * blockDim.x + threadIdx.x;
    if (idx >= (size_t)Bn * Nn * Nn * EDim) return;
    size_t pair = idx / EDim;
    int j  = (int)(pair % Nn);
    size_t bi = pair / Nn;
    int b  = (int)(bi / Nn);
    out[idx] = e[idx] * mask[bi] * mask[(size_t)b * Nn + j];
}
__global__ void out_z_kernel(const float* __restrict__ mask, float* __restrict__ out) {
    size_t idx = (size_t)blockIdx.x * blockDim.x + threadIdx.x;
    if (idx >= (size_t)Mrows * Hd) return;
    out[idx] = g_z[idx] * mask[idx / Hd];
}

// ---------------- launcher ----------------
extern "C" void kernel_launch(void* const* d_in, const int* in_sizes, int n_in,
                              void* d_out, int out_size) {
    const float* x    = (const float*)d_in[0];
    const float* e    = (const float*)d_in[1];
    const float* mask = (const float*)d_in[2];
    const float* Wemb = (const float*)d_in[3];
    const float* Wq = (const float*)d_in[4];  const float* bq = (const float*)d_in[5];
    const float* Wk = (const float*)d_in[6];  const float* bk = (const float*)d_in[7];
    const float* Wv = (const float*)d_in[8];  const float* bv = (const float*)d_in[9];
    const float* Wo = (const float*)d_in[10]; const float* bo = (const float*)d_in[11];
    const float* g1 = (const float*)d_in[12]; const float* be1 = (const float*)d_in[13];
    const float* W1 = (const float*)d_in[14]; const float* b1  = (const float*)d_in[15];
    const float* W2 = (const float*)d_in[16]; const float* b2  = (const float*)d_in[17];
    const float* g2 = (const float*)d_in[18]; const float* be2 = (const float*)d_in[19];
    float* out = (float*)d_out;

    float *cat, *wembp, *z, *q, *k, *v, *y, *x1, *ffn;
    cudaGetSymbolAddress((void**)&cat,   g_cat);
    cudaGetSymbolAddress((void**)&wembp, g_wembp);
    cudaGetSymbolAddress((void**)&z,     g_z);
    cudaGetSymbolAddress((void**)&q,     g_q);
    cudaGetSymbolAddress((void**)&k,     g_k);
    cudaGetSymbolAddress((void**)&v,     g_v);
    cudaGetSymbolAddress((void**)&y,     g_y);
    cudaGetSymbolAddress((void**)&x1,    g_x1);
    cudaGetSymbolAddress((void**)&ffn,   g_ffn);

    const int SMEM = 16384 * 4;  // 64KB dynamic
    cudaFuncSetAttribute(gemm_tf32_kernel,
                         cudaFuncAttributeMaxDynamicSharedMemorySize, SMEM);

    // embedding (padded K so the GEMM needs no guards)
    {
        size_t tot = (size_t)Mrows * KPAD;
        cat_kernel<<<(unsigned)((tot + 255) / 256), 256>>>(x, e);
        size_t wt = (size_t)KPAD * Hd;
        wembpad_kernel<<<(unsigned)((wt + 255) / 256), 256>>>(Wemb);
        gemm_tf32_kernel<<<dim3(Hd / 128, Mrows / 128), 256, SMEM>>>(
            cat, KPAD, wembp, Hd, nullptr, z, Hd, KPAD, 0);
    }

    for (int l = 0; l < DEPTH; l++) {
        const size_t wofs = (size_t)l * Hd * Hd;
        // distance bias
        sqnorm_kernel<<<Mrows, 128>>>();
        dist_kernel<<<dim3(4, 4, Bn), 256>>>(mask);
        distbias_kernel<<<Mrows, 256>>>(mask);
        // QKV
        gemm_tf32_kernel<<<dim3(Hd / 128, Mrows / 128), 256, SMEM>>>(
            z, Hd, Wq + wofs, Hd, bq + (size_t)l * Hd, q, Hd, Hd, 0);
        gemm_tf32_kernel<<<dim3(Hd / 128, Mrows / 128), 256, SMEM>>>(
            z, Hd, Wk + wofs, Hd, bk + (size_t)l * Hd, k, Hd, Hd, 0);
        gemm_tf32_kernel<<<dim3(Hd / 128, Mrows / 128), 256, SMEM>>>(
            z, Hd, Wv + wofs, Hd, bv + (size_t)l * Hd, v, Hd, Hd, 0);
        // attention
        qk_kernel<<<dim3(4, 4, Bn * NHd), 256>>>();
        softmax_kernel<<<Bn * NHd * Nn, 256>>>();
        attnv_kernel<<<dim3(4, Bn * NHd), 256>>>();
        // output projection (into q as temp) + AddNorm
        gemm_tf32_kernel<<<dim3(Hd / 128, Mrows / 128), 256, SMEM>>>(
            y, Hd, Wo + wofs, Hd, bo + (size_t)l * Hd, q, Hd, Hd, 0);
        addln_kernel<<<Mrows, 128>>>(z, q, g1 + (size_t)l * Hd, be1 + (size_t)l * Hd, x1);
        // FFN
        gemm_tf32_kernel<<<dim3(DFFd / 128, Mrows / 128), 256, SMEM>>>(
            x1, Hd, W1 + (size_t)l * Hd * DFFd, DFFd, b1 + (size_t)l * DFFd,
            ffn, DFFd, Hd, 1);
        gemm_tf32_kernel<<<dim3(Hd / 128, Mrows / 128), 256, SMEM>>>(
            ffn, DFFd, W2 + (size_t)l * DFFd * Hd, Hd, b2 + (size_t)l * Hd,
            q, Hd, DFFd, 0);
        addln_kernel<<<Mrows, 128>>>(x1, q, g2 + (size_t)l * Hd, be2 + (size_t)l * Hd, z);
    }

    // outputs: [X_out | E_out | z_out]
    const size_t XTOT = (size_t)Bn * Nn * XDim;       // 1,933,312
    const size_t ETOT = (size_t)Bn * Nn * Nn * EDim;  // 20,971,520
    const size_t ZTOT = (size_t)Mrows * Hd;           // 6,291,456
    out_x_kernel<<<(unsigned)((XTOT + 255) / 256), 256>>>(x, mask, out);
    out_e_kernel<<<(unsigned)((ETOT + 255) / 256), 256>>>(e, mask, out + XTOT);
    out_z_kernel<<<(unsigned)((ZTOT + 255) / 256), 256>>>(mask, out + XTOT + ETOT);
    (void)in_sizes; (void)n_in; (void)out_size;
}

// round 6
// speedup vs baseline: 1.1101x; 1.1101x over previous
#include <cuda_runtime.h>
#include <math.h>
#include <stdint.h>

#define Bn    64
#define Nn    256
#define XDim  118
#define EDim  5
#define Hd    384
#define NHd   8
#define DHd   48
#define DFFd  1536
#define DEPTH 6
#define Mrows (Bn * Nn)            /* 16384 */
#define KCAT  (XDim + Nn * EDim)   /* 1398  */
#define KPAD  1408                 /* KCAT padded (mult of 16) */
#define EROW  (Nn * EDim)          /* 1280  */

typedef unsigned long long ull;

// ---------------- scratch (device globals; no allocation) ----------------
__device__ float g_cat[(size_t)Mrows * KPAD];
__device__ float g_z  [(size_t)Mrows * Hd];
__device__ float g_q  [(size_t)Mrows * Hd];
__device__ float g_k  [(size_t)Mrows * Hd];
__device__ float g_v  [(size_t)Mrows * Hd];
__device__ float g_y  [(size_t)Mrows * Hd];
__device__ float g_x1 [(size_t)Mrows * Hd];
__device__ float g_ffn[(size_t)Mrows * DFFd];
__device__ float g_att[(size_t)Bn * NHd * Nn * Nn];
__device__ float g_D  [(size_t)Bn * Nn * Nn];
__device__ float g_sq [Mrows];
// transposed weights [N, K] (K-major rows, so GEMM stages A and B identically)
__device__ float g_wembT[(size_t)Hd * KPAD];
__device__ float g_wqT [(size_t)DEPTH * Hd * Hd];
__device__ float g_wkT [(size_t)DEPTH * Hd * Hd];
__device__ float g_wvT [(size_t)DEPTH * Hd * Hd];
__device__ float g_woT [(size_t)DEPTH * Hd * Hd];
__device__ float g_w1T [(size_t)DEPTH * DFFd * Hd];
__device__ float g_w2T [(size_t)DEPTH * Hd * DFFd];

// ---------------- packed fp32x2 FMA (sm_100+ base ISA; exact fp32) ----------------
#if defined(__CUDA_ARCH__) && (__CUDA_ARCH__ >= 1000)
#define FMA2(d, a, b) asm("fma.rn.f32x2 %0, %1, %2, %0;" : "+l"(d) : "l"(a), "l"(b))
#else
#define FMA2(d, a, b) do {                                                   \
    float2* _dp = (float2*)&(d);                                             \
    const float2* _ap = (const float2*)&(a);                                 \
    const float2* _bp = (const float2*)&(b);                                 \
    _dp->x = fmaf(_ap->x, _bp->x, _dp->x);                                   \
    _dp->y = fmaf(_ap->y, _bp->y, _dp->y);                                   \
} while (0)
#endif
#define UNPACK2(lo, hi, v) \
    asm("mov.b64 {%0,%1}, %2;" : "=f"(lo), "=f"(hi) : "l"(v))

// ---------------- reductions ----------------
__device__ __forceinline__ float blockmax256(float v) {
    __shared__ float red[8];
    #pragma unroll
    for (int o = 16; o > 0; o >>= 1) v = fmaxf(v, __shfl_xor_sync(0xffffffffu, v, o));
    if ((threadIdx.x & 31) == 0) red[threadIdx.x >> 5] = v;
    __syncthreads();
    float m = red[0];
    #pragma unroll
    for (int i = 1; i < 8; i++) m = fmaxf(m, red[i]);
    __syncthreads();
    return m;
}
__device__ __forceinline__ float blocksum256(float v) {
    __shared__ float red[8];
    #pragma unroll
    for (int o = 16; o > 0; o >>= 1) v += __shfl_xor_sync(0xffffffffu, v, o);
    if ((threadIdx.x & 31) == 0) red[threadIdx.x >> 5] = v;
    __syncthreads();
    float s = red[0];
    #pragma unroll
    for (int i = 1; i < 8; i++) s += red[i];
    __syncthreads();
    return s;
}
__device__ __forceinline__ float blocksum128(float v) {
    __shared__ float red[4];
    #pragma unroll
    for (int o = 16; o > 0; o >>= 1) v += __shfl_xor_sync(0xffffffffu, v, o);
    if ((threadIdx.x & 31) == 0) red[threadIdx.x >> 5] = v;
    __syncthreads();
    float s = red[0] + red[1] + red[2] + red[3];
    __syncthreads();
    return s;
}

// ---------------- concat [x | e_flat | 0-pad] ----------------
__global__ void cat_kernel(const float* __restrict__ x, const float* __restrict__ e) {
    size_t idx = (size_t)blockIdx.x * blockDim.x + threadIdx.x;
    if (idx >= (size_t)Mrows * KPAD) return;
    size_t r = idx / KPAD;
    int    c = (int)(idx - r * KPAD);
    float v;
    if (c < XDim)      v = x[r * XDim + c];
    else if (c < KCAT) v = e[r * (size_t)EROW + (c - XDim)];
    else               v = 0.f;
    g_cat[idx] = v;
}

// ---------------- tiled transpose: out[c][r] = in[r][c], zero-pad rows >= R ----------------
__global__ void transpose_kernel(const float* __restrict__ in, float* __restrict__ out,
                                 int R, int C, int outLd,
                                 size_t inStride, size_t outStride) {
    __shared__ float tile[32][33];
    const float* ip = in + (size_t)blockIdx.z * inStride;
    float* op = out + (size_t)blockIdx.z * outStride;
    int c0 = blockIdx.x * 32, r0 = blockIdx.y * 32;
    int tx = threadIdx.x, ty = threadIdx.y;  // 32 x 8
    #pragma unroll
    for (int i = 0; i < 32; i += 8) {
        int r = r0 + ty + i, c = c0 + tx;
        tile[ty + i][tx] = (r < R && c < C) ? ip[(size_t)r * C + c] : 0.f;
    }
    __syncthreads();
    #pragma unroll
    for (int i = 0; i < 32; i += 8) {
        int oc = c0 + ty + i, orow = r0 + tx;
        if (oc < C && orow < outLd) op[(size_t)oc * outLd + orow] = tile[tx][ty + i];
    }
}

// ============================================================================
// fp32 SGEMM with packed FFMA2: C[M,N] = A[M,K] @ BT[N,K]^T (+bias)(+relu)
// BM=BN=128, BK=16, 256 threads, 8x8 per thread, A duplicated in smem so
// packed (a,a) multiplicands come straight from LDS.128.
// Requires M%128==0, N%128==0, K%16==0, 16B-aligned rows.
// ============================================================================
#define ASTR 264          /* dup-A row stride: 2*128 + 8 pad (floats) */
#define BSTR 132          /* B row stride: 128 + 4 pad (floats) */
#define ABUF_F (16 * ASTR)            /* 4224 floats per A buffer */
#define BBUF_F (16 * BSTR)            /* 2112 floats per B buffer */
#define GSMEM_F (2 * (ABUF_F + BBUF_F))  /* 12672 floats */
#define GSMEM_B (GSMEM_F * 4)            /* 50688 bytes */

__global__ __launch_bounds__(256, 2)
void gemm_kernel(const float* __restrict__ A, int lda,
                 const float* __restrict__ BT, int ldb,
                 const float* __restrict__ bias,
                 float* __restrict__ C, int ldc, int K, int relu) {
    extern __shared__ float sm[];
    float* Asb[2] = { sm,                     sm + ABUF_F + BBUF_F };
    float* Bsb[2] = { sm + ABUF_F,            sm + 2 * ABUF_F + BBUF_F };

    const int t  = threadIdx.x;
    const int tn = t & 15, tm = t >> 4;
    const int m0 = blockIdx.y * 128, n0 = blockIdx.x * 128;

    // staging indices: thread handles float4 slots p = 2t, 2t+1
    const int ar0 = (2 * t) >> 2,  ac0 = ((2 * t) & 3) * 4;
    const int ar1 = (2 * t + 1) >> 2, ac1 = ((2 * t + 1) & 3) * 4;

    ull acc[8][4];
    #pragma unroll
    for (int i = 0; i < 8; i++)
        #pragma unroll
        for (int j = 0; j < 4; j++) acc[i][j] = 0ull;

    float4 pa0, pa1, pb0, pb1;
    // load chunk 0
    pa0 = *(const float4*)(A + (size_t)(m0 + ar0) * lda + ac0);
    pa1 = *(const float4*)(A + (size_t)(m0 + ar1) * lda + ac1);
    pb0 = *(const float4*)(BT + (size_t)(n0 + ar0) * ldb + ac0);
    pb1 = *(const float4*)(BT + (size_t)(n0 + ar1) * ldb + ac1);
    // stage chunk 0
    {
        float* Ad = Asb[0]; float* Bd = Bsb[0];
        float va0[4] = {pa0.x, pa0.y, pa0.z, pa0.w};
        float va1[4] = {pa1.x, pa1.y, pa1.z, pa1.w};
        float vb0[4] = {pb0.x, pb0.y, pb0.z, pb0.w};
        float vb1[4] = {pb1.x, pb1.y, pb1.z, pb1.w};
        #pragma unroll
        for (int u = 0; u < 4; u++) {
            *(float2*)(Ad + (ac0 + u) * ASTR + 2 * ar0) = make_float2(va0[u], va0[u]);
            *(float2*)(Ad + (ac1 + u) * ASTR + 2 * ar1) = make_float2(va1[u], va1[u]);
            Bd[(ac0 + u) * BSTR + ar0] = vb0[u];
            Bd[(ac1 + u) * BSTR + ar1] = vb1[u];
        }
    }
    __syncthreads();

    const int nch = K >> 4;
    for (int ch = 0; ch < nch; ch++) {
        const int buf = ch & 1;
        if (ch + 1 < nch) {
            const int k0 = (ch + 1) << 4;
            pa0 = *(const float4*)(A + (size_t)(m0 + ar0) * lda + k0 + ac0);
            pa1 = *(const float4*)(A + (size_t)(m0 + ar1) * lda + k0 + ac1);
            pb0 = *(const float4*)(BT + (size_t)(n0 + ar0) * ldb + k0 + ac0);
            pb1 = *(const float4*)(BT + (size_t)(n0 + ar1) * ldb + k0 + ac1);
        }
        const float* ap = Asb[buf] + tm * 16;
        const float* bp = Bsb[buf] + tn * 8;
        #pragma unroll
        for (int k = 0; k < 16; k++) {
            ulonglong2 a01 = *(const ulonglong2*)(ap + k * ASTR);
            ulonglong2 a23 = *(const ulonglong2*)(ap + k * ASTR + 4);
            ulonglong2 a45 = *(const ulonglong2*)(ap + k * ASTR + 8);
            ulonglong2 a67 = *(const ulonglong2*)(ap + k * ASTR + 12);
            ulonglong2 b03 = *(const ulonglong2*)(bp + k * BSTR);
            ulonglong2 b47 = *(const ulonglong2*)(bp + k * BSTR + 4);
            ull aa[8] = {a01.x, a01.y, a23.x, a23.y, a45.x, a45.y, a67.x, a67.y};
            ull bb[4] = {b03.x, b03.y, b47.x, b47.y};
            #pragma unroll
            for (int i = 0; i < 8; i++)
                #pragma unroll
                for (int j = 0; j < 4; j++) FMA2(acc[i][j], aa[i], bb[j]);
        }
        if (ch + 1 < nch) {
            float* Ad = Asb[buf ^ 1]; float* Bd = Bsb[buf ^ 1];
            float va0[4] = {pa0.x, pa0.y, pa0.z, pa0.w};
            float va1[4] = {pa1.x, pa1.y, pa1.z, pa1.w};
            float vb0[4] = {pb0.x, pb0.y, pb0.z, pb0.w};
            float vb1[4] = {pb1.x, pb1.y, pb1.z, pb1.w};
            #pragma unroll
            for (int u = 0; u < 4; u++) {
                *(float2*)(Ad + (ac0 + u) * ASTR + 2 * ar0) = make_float2(va0[u], va0[u]);
                *(float2*)(Ad + (ac1 + u) * ASTR + 2 * ar1) = make_float2(va1[u], va1[u]);
                Bd[(ac0 + u) * BSTR + ar0] = vb0[u];
                Bd[(ac1 + u) * BSTR + ar1] = vb1[u];
            }
            __syncthreads();
        }
    }

    // epilogue
    const int gn = n0 + tn * 8;
    float bias8[8];
    #pragma unroll
    for (int j = 0; j < 8; j++) bias8[j] = bias ? bias[gn + j] : 0.f;
    #pragma unroll
    for (int i = 0; i < 8; i++) {
        const int gm = m0 + tm * 8 + i;
        float o[8];
        #pragma unroll
        for (int j = 0; j < 4; j++) UNPACK2(o[2 * j], o[2 * j + 1], acc[i][j]);
        #pragma unroll
        for (int j = 0; j < 8; j++) {
            o[j] += bias8[j];
            if (relu) o[j] = fmaxf(o[j], 0.f);
        }
        *(float4*)(C + (size_t)gm * ldc + gn)     = make_float4(o[0], o[1], o[2], o[3]);
        *(float4*)(C + (size_t)gm * ldc + gn + 4) = make_float4(o[4], o[5], o[6], o[7]);
    }
}

// ---------------- row squared norms of z ----------------
__global__ void sqnorm_kernel() {
    int r = blockIdx.x;
    float s = 0.f;
    for (int c = threadIdx.x; c < Hd; c += 128) {
        float v = g_z[(size_t)r * Hd + c];
        s += v * v;
    }
    s = blocksum128(s);
    if (threadIdx.x == 0) g_sq[r] = s;
}

// ---------------- masked pairwise distance: g_D = cdist(z,z)*dm ----------------
__global__ __launch_bounds__(256) void dist_kernel(const float* __restrict__ mask) {
    int b  = blockIdx.z;
    int ti = blockIdx.y * 64, tj = blockIdx.x * 64;
    const float* zb = g_z + (size_t)b * Nn * Hd;
    __shared__ float Zi[16][64];
    __shared__ float Zj[16][64];
    int t = threadIdx.x, tx = t & 15, ty = t >> 4;
    float acc[4][4];
    #pragma unroll
    for (int i = 0; i < 4; i++)
        #pragma unroll
        for (int j = 0; j < 4; j++) acc[i][j] = 0.f;

    int l = t * 4, ar = l >> 4, ac = l & 15;
    for (int k0 = 0; k0 < Hd; k0 += 16) {
        #pragma unroll
        for (int u = 0; u < 4; u++) {
            Zi[ac + u][ar] = zb[(size_t)(ti + ar) * Hd + k0 + ac + u];
            Zj[ac + u][ar] = zb[(size_t)(tj + ar) * Hd + k0 + ac + u];
        }
        __syncthreads();
        #pragma unroll
        for (int kk = 0; kk < 16; kk++) {
            float a[4], bb[4];
            #pragma unroll
            for (int i = 0; i < 4; i++) a[i] = Zi[kk][ty * 4 + i];
            #pragma unroll
            for (int j = 0; j < 4; j++) bb[j] = Zj[kk][tx * 4 + j];
            #pragma unroll
            for (int i = 0; i < 4; i++)
                #pragma unroll
                for (int j = 0; j < 4; j++) acc[i][j] = fmaf(a[i], bb[j], acc[i][j]);
        }
        __syncthreads();
    }
    #pragma unroll
    for (int i = 0; i < 4; i++) {
        int gi = ti + ty * 4 + i;
        float sqi = g_sq[b * Nn + gi], mi = mask[b * Nn + gi];
        #pragma unroll
        for (int j = 0; j < 4; j++) {
            int gj = tj + tx * 4 + j;
            float d2 = sqi + g_sq[b * Nn + gj] - 2.f * acc[i][j];
            d2 = fmaxf(d2, 0.f);
            float d  = (d2 > 1e-12f) ? sqrtf(d2) : 0.f;
            float dm = mi * mask[b * Nn + gj];
            g_D[((size_t)b * Nn + gi) * Nn + gj] = d * dm;
        }
    }
}

// ---------------- bias: D = (rowmax - D) masked, diag 0 ----------------
__global__ void distbias_kernel(const float* __restrict__ mask) {
    int r = blockIdx.x;
    int b = r / Nn, i = r - b * Nn;
    float* p = g_D + (size_t)r * Nn;
    int t = threadIdx.x;
    float v  = p[t];
    float bm = blockmax256(v);
    float dm = mask[r] * mask[b * Nn + t];
    p[t] = (t == i) ? 0.f : (bm - v) * dm;
}

// ---------------- scores = QK^T/sqrt(48) + D ----------------
__global__ __launch_bounds__(256) void qk_kernel() {
    int bh = blockIdx.z;
    int b  = bh / NHd, h = bh - b * NHd;
    int ti = blockIdx.y * 64, tj = blockIdx.x * 64;
    const float* qb = g_q + (size_t)b * Nn * Hd + h * DHd;
    const float* kb = g_k + (size_t)b * Nn * Hd + h * DHd;
    __shared__ float Qs[64][49];
    __shared__ float Ks[64][49];
    int t = threadIdx.x, tx = t & 15, ty = t >> 4;
    for (int l = t; l < 64 * 48; l += 256) {
        int r = l / 48, c = l - r * 48;
        Qs[r][c] = qb[(size_t)(ti + r) * Hd + c];
        Ks[r][c] = kb[(size_t)(tj + r) * Hd + c];
    }
    __syncthreads();
    float acc[4][4];
    #pragma unroll
    for (int i = 0; i < 4; i++)
        #pragma unroll
        for (int j = 0; j < 4; j++) acc[i][j] = 0.f;
    #pragma unroll 4
    for (int kk = 0; kk < 48; kk++) {
        float a[4], bb[4];
        #pragma unroll
        for (int i = 0; i < 4; i++) a[i] = Qs[ty * 4 + i][kk];
        #pragma unroll
        for (int j = 0; j < 4; j++) bb[j] = Ks[tx * 4 + j][kk];
        #pragma unroll
        for (int i = 0; i < 4; i++)
            #pragma unroll
            for (int j = 0; j < 4; j++) acc[i][j] = fmaf(a[i], bb[j], acc[i][j]);
    }
    const float scale = 0.144337567297406441f;
    #pragma unroll
    for (int i = 0; i < 4; i++) {
        int gi = ti + ty * 4 + i;
        #pragma unroll
        for (int j = 0; j < 4; j++) {
            int gj = tj + tx * 4 + j;
            g_att[((size_t)bh * Nn + gi) * Nn + gj] =
                acc[i][j] * scale + g_D[((size_t)b * Nn + gi) * Nn + gj];
        }
    }
}

// ---------------- softmax over last dim (rows of 256) ----------------
__global__ void softmax_kernel() {
    float* p = g_att + (size_t)blockIdx.x * Nn;
    int t = threadIdx.x;
    float v  = p[t];
    float bm = blockmax256(v);
    float e  = __expf(v - bm);
    float s  = blocksum256(e);
    p[t] = e / s;
}

// ---------------- y = attn @ V ----------------
__global__ __launch_bounds__(256) void attnv_kernel() {
    int bh = blockIdx.y;
    int b  = bh / NHd, h = bh - b * NHd;
    int ti = blockIdx.x * 64;
    const float* arow = g_att + (size_t)bh * Nn * Nn;
    const float* vb   = g_v + (size_t)b * Nn * Hd + h * DHd;
    __shared__ float As[64][65];
    __shared__ float Vs[64][49];
    int t = threadIdx.x, tx = t & 15, ty = t >> 4;
    float acc[4][3];
    #pragma unroll
    for (int i = 0; i < 4; i++)
        #pragma unroll
        for (int j = 0; j < 3; j++) acc[i][j] = 0.f;

    for (int j0 = 0; j0 < Nn; j0 += 64) {
        for (int l = t; l < 64 * 64; l += 256)
            As[l >> 6][l & 63] = arow[(size_t)(ti + (l >> 6)) * Nn + j0 + (l & 63)];
        for (int l = t; l < 64 * 48; l += 256) {
            int r = l / 48, c = l - r * 48;
            Vs[r][c] = vb[(size_t)(j0 + r) * Hd + c];
        }
        __syncthreads();
        #pragma unroll 4
        for (int kk = 0; kk < 64; kk++) {
            float a[4], bb[3];
            #pragma unroll
            for (int i = 0; i < 4; i++) a[i] = As[ty * 4 + i][kk];
            #pragma unroll
            for (int j = 0; j < 3; j++) bb[j] = Vs[kk][tx * 3 + j];
            #pragma unroll
            for (int i = 0; i < 4; i++)
                #pragma unroll
                for (int j = 0; j < 3; j++) acc[i][j] = fmaf(a[i], bb[j], acc[i][j]);
        }
        __syncthreads();
    }
    #pragma unroll
    for (int i = 0; i < 4; i++) {
        int gi = ti + ty * 4 + i;
        #pragma unroll
        for (int j = 0; j < 3; j++)
            g_y[((size_t)b * Nn + gi) * Hd + h * DHd + tx * 3 + j] = acc[i][j];
    }
}

// ---------------- out = LayerNorm(a + r) ----------------
__global__ void addln_kernel(const float* __restrict__ a, const float* __restrict__ r,
                             const float* __restrict__ g, const float* __restrict__ be,
                             float* __restrict__ out) {
    int row = blockIdx.x;
    int t = threadIdx.x;
    float vals[3];
    float s = 0.f;
    #pragma unroll
    for (int u = 0; u < 3; u++) {
        int c = t + u * 128;
        float v = a[(size_t)row * Hd + c] + r[(size_t)row * Hd + c];
        vals[u] = v;
        s += v;
    }
    float mu = blocksum128(s) * (1.f / Hd);
    float s2 = 0.f;
    #pragma unroll
    for (int u = 0; u < 3; u++) { float d = vals[u] - mu; s2 += d * d; }
    float var  = blocksum128(s2) * (1.f / Hd);
    float rstd = rsqrtf(var + 1e-5f);
    #pragma unroll
    for (int u = 0; u < 3; u++) {
        int c = t + u * 128;
        out[(size_t)row * Hd + c] = (vals[u] - mu) * rstd * g[c] + be[c];
    }
}

// ---------------- masked outputs ----------------
__global__ void out_x_kernel(const float* __restrict__ x, const float* __restrict__ mask,
                             float* __restrict__ out) {
    size_t idx = (size_t)blockIdx.x * blockDim.x + threadIdx.x;
    if (idx >= (size_t)Bn * Nn * XDim) return;
    out[idx] = x[idx] * mask[idx / XDim];
}
__global__ void out_e_kernel(const float* __restrict__ e, const float* __restrict__ mask,
                             float* __restrict__ out) {
    size_t idx = (size_t)blockIdx.x * blockDim.x + threadIdx.x;
    if (idx >= (size_t)Bn * Nn * Nn * EDim) return;
    size_t pair = idx / EDim;
    int j  = (int)(pair % Nn);
    size_t bi = pair / Nn;
    int b  = (int)(bi / Nn);
    out[idx] = e[idx] * mask[bi] * mask[(size_t)b * Nn + j];
}
__global__ void out_z_kernel(const float* __restrict__ mask, float* __restrict__ out) {
    size_t idx = (size_t)blockIdx.x * blockDim.x + threadIdx.x;
    if (idx >= (size_t)Mrows * Hd) return;
    out[idx] = g_z[idx] * mask[idx / Hd];
}

// ---------------- launcher ----------------
extern "C" void kernel_launch(void* const* d_in, const int* in_sizes, int n_in,
                              void* d_out, int out_size) {
    const float* x    = (const float*)d_in[0];
    const float* e    = (const float*)d_in[1];
    const float* mask = (const float*)d_in[2];
    const float* Wemb = (const float*)d_in[3];
    const float* Wq = (const float*)d_in[4];  const float* bq = (const float*)d_in[5];
    const float* Wk = (const float*)d_in[6];  const float* bk = (const float*)d_in[7];
    const float* Wv = (const float*)d_in[8];  const float* bv = (const float*)d_in[9];
    const float* Wo = (const float*)d_in[10]; const float* bo = (const float*)d_in[11];
    const float* g1 = (const float*)d_in[12]; const float* be1 = (const float*)d_in[13];
    const float* W1 = (const float*)d_in[14]; const float* b1  = (const float*)d_in[15];
    const float* W2 = (const float*)d_in[16]; const float* b2  = (const float*)d_in[17];
    const float* g2 = (const float*)d_in[18]; const float* be2 = (const float*)d_in[19];
    float* out = (float*)d_out;

    float *cat, *z, *q, *k, *v, *y, *x1, *ffn;
    float *wembT, *wqT, *wkT, *wvT, *woT, *w1T, *w2T;
    cudaGetSymbolAddress((void**)&cat,   g_cat);
    cudaGetSymbolAddress((void**)&z,     g_z);
    cudaGetSymbolAddress((void**)&q,     g_q);
    cudaGetSymbolAddress((void**)&k,     g_k);
    cudaGetSymbolAddress((void**)&v,     g_v);
    cudaGetSymbolAddress((void**)&y,     g_y);
    cudaGetSymbolAddress((void**)&x1,    g_x1);
    cudaGetSymbolAddress((void**)&ffn,   g_ffn);
    cudaGetSymbolAddress((void**)&wembT, g_wembT);
    cudaGetSymbolAddress((void**)&wqT,   g_wqT);
    cudaGetSymbolAddress((void**)&wkT,   g_wkT);
    cudaGetSymbolAddress((void**)&wvT,   g_wvT);
    cudaGetSymbolAddress((void**)&woT,   g_woT);
    cudaGetSymbolAddress((void**)&w1T,   g_w1T);
    cudaGetSymbolAddress((void**)&w2T,   g_w2T);

    cudaFuncSetAttribute(gemm_kernel,
                         cudaFuncAttributeMaxDynamicSharedMemorySize, GSMEM_B);

    dim3 tb(32, 8);
    // weight transposes into K-major [N][K]
    transpose_kernel<<<dim3(12, 44, 1), tb>>>(Wemb, wembT, KCAT, Hd, KPAD, 0, 0);
    transpose_kernel<<<dim3(12, 12, DEPTH), tb>>>(Wq, wqT, Hd, Hd, Hd,
                                                  (size_t)Hd * Hd, (size_t)Hd * Hd);
    transpose_kernel<<<dim3(12, 12, DEPTH), tb>>>(Wk, wkT, Hd, Hd, Hd,
                                                  (size_t)Hd * Hd, (size_t)Hd * Hd);
    transpose_kernel<<<dim3(12, 12, DEPTH), tb>>>(Wv, wvT, Hd, Hd, Hd,
                                                  (size_t)Hd * Hd, (size_t)Hd * Hd);
    transpose_kernel<<<dim3(12, 12, DEPTH), tb>>>(Wo, woT, Hd, Hd, Hd,
                                                  (size_t)Hd * Hd, (size_t)Hd * Hd);
    transpose_kernel<<<dim3(48, 12, DEPTH), tb>>>(W1, w1T, Hd, DFFd, Hd,
                                                  (size_t)Hd * DFFd, (size_t)DFFd * Hd);
    transpose_kernel<<<dim3(12, 48, DEPTH), tb>>>(W2, w2T, DFFd, Hd, DFFd,
                                                  (size_t)DFFd * Hd, (size_t)Hd * DFFd);

    // embedding
    {
        size_t tot = (size_t)Mrows * KPAD;
        cat_kernel<<<(unsigned)((tot + 255) / 256), 256>>>(x, e);
        gemm_kernel<<<dim3(Hd / 128, Mrows / 128), 256, GSMEM_B>>>(
            cat, KPAD, wembT, KPAD, nullptr, z, Hd, KPAD, 0);
    }

    for (int l = 0; l < DEPTH; l++) {
        const size_t wofs  = (size_t)l * Hd * Hd;
        const size_t w1ofs = (size_t)l * DFFd * Hd;
        // distance bias
        sqnorm_kernel<<<Mrows, 128>>>();
        dist_kernel<<<dim3(4, 4, Bn), 256>>>(mask);
        distbias_kernel<<<Mrows, 256>>>(mask);
        // QKV
        gemm_kernel<<<dim3(Hd / 128, Mrows / 128), 256, GSMEM_B>>>(
            z, Hd, wqT + wofs, Hd, bq + (size_t)l * Hd, q, Hd, Hd, 0);
        gemm_kernel<<<dim3(Hd / 128, Mrows / 128), 256, GSMEM_B>>>(
            z, Hd, wkT + wofs, Hd, bk + (size_t)l * Hd, k, Hd, Hd, 0);
        gemm_kernel<<<dim3(Hd / 128, Mrows / 128), 256, GSMEM_B>>>(
            z, Hd, wvT + wofs, Hd, bv + (size_t)l * Hd, v, Hd, Hd, 0);
        // attention
        qk_kernel<<<dim3(4, 4, Bn * NHd), 256>>>();
        softmax_kernel<<<Bn * NHd * Nn, 256>>>();
        attnv_kernel<<<dim3(4, Bn * NHd), 256>>>();
        // output projection (into q as temp) + AddNorm
        gemm_kernel<<<dim3(Hd / 128, Mrows / 128), 256, GSMEM_B>>>(
            y, Hd, woT + wofs, Hd, bo + (size_t)l * Hd, q, Hd, Hd, 0);
        addln_kernel<<<Mrows, 128>>>(z, q, g1 + (size_t)l * Hd, be1 + (size_t)l * Hd, x1);
        // FFN
        gemm_kernel<<<dim3(DFFd / 128, Mrows / 128), 256, GSMEM_B>>>(
            x1, Hd, w1T + w1ofs, Hd, b1 + (size_t)l * DFFd, ffn, DFFd, Hd, 1);
        gemm_kernel<<<dim3(Hd / 128, Mrows / 128), 256, GSMEM_B>>>(
            ffn, DFFd, w2T + w1ofs, DFFd, b2 + (size_t)l * Hd, q, Hd, DFFd, 0);
        addln_kernel<<<Mrows, 128>>>(x1, q, g2 + (size_t)l * Hd, be2 + (size_t)l * Hd, z);
    }

    // outputs: [X_out | E_out | z_out]
    const size_t XTOT = (size_t)Bn * Nn * XDim;
    const size_t ETOT = (size_t)Bn * Nn * Nn * EDim;
    const size_t ZTOT = (size_t)Mrows * Hd;
    out_x_kernel<<<(unsigned)((XTOT + 255) / 256), 256>>>(x, mask, out);
    out_e_kernel<<<(unsigned)((ETOT + 255) / 256), 256>>>(e, mask, out + XTOT);
    out_z_kernel<<<(unsigned)((ZTOT + 255) / 256), 256>>>(mask, out + XTOT + ETOT);
    (void)in_sizes; (void)n_in; (void)out_size;
}

// round 7
// speedup vs baseline: 3.8963x; 3.5098x over previous
#include <cuda_runtime.h>
#include <cuda_fp16.h>
#include <math.h>
#include <stdint.h>

#define Bn    64
#define Nn    256
#define XDim  118
#define EDim  5
#define Hd    384
#define NHd   8
#define DHd   48
#define DFFd  1536
#define DEPTH 6
#define Mrows (Bn * Nn)            /* 16384 */
#define KCAT  (XDim + Nn * EDim)   /* 1398  */
#define KPAD  1408                 /* KCAT padded (mult of 32) */
#define EROW  (Nn * EDim)          /* 1280  */

// ---------------- scratch (device globals; no allocation) ----------------
__device__ __half g_cath[(size_t)Mrows * KPAD];      // concat, fp16
__device__ float  g_z  [(size_t)Mrows * Hd];
__device__ __half g_zh [(size_t)Mrows * Hd];
__device__ float  g_q  [(size_t)Mrows * Hd];
__device__ float  g_k  [(size_t)Mrows * Hd];
__device__ float  g_v  [(size_t)Mrows * Hd];
__device__ __half g_yh [(size_t)Mrows * Hd];
__device__ float  g_x1 [(size_t)Mrows * Hd];
__device__ __half g_x1h[(size_t)Mrows * Hd];
__device__ __half g_ffnh[(size_t)Mrows * DFFd];
__device__ float  g_att[(size_t)Bn * NHd * Nn * Nn];
__device__ float  g_D  [(size_t)Bn * Nn * Nn];
__device__ float  g_sq [Mrows];
// transposed fp16 weights [N][K] (K-major rows)
__device__ __half g_wembTh[(size_t)Hd * KPAD];
__device__ __half g_wqTh [(size_t)DEPTH * Hd * Hd];
__device__ __half g_wkTh [(size_t)DEPTH * Hd * Hd];
__device__ __half g_wvTh [(size_t)DEPTH * Hd * Hd];
__device__ __half g_woTh [(size_t)DEPTH * Hd * Hd];
__device__ __half g_w1Th [(size_t)DEPTH * DFFd * Hd];
__device__ __half g_w2Th [(size_t)DEPTH * Hd * DFFd];

// ---------------- PTX helpers (all sm_80+ base ISA) ----------------
__device__ __forceinline__ uint32_t smem_to_u32(const void* p) {
    uint32_t a;
    asm("{ .reg .u64 t; cvta.to.shared.u64 t, %1; cvt.u32.u64 %0, t; }"
        : "=r"(a) : "l"(p));
    return a;
}
#define CP_ASYNC16(dst, src) \
    asm volatile("cp.async.cg.shared.global [%0], [%1], 16;" \
                 :: "r"(dst), "l"(src) : "memory")
#define CP_COMMIT() asm volatile("cp.async.commit_group;" ::: "memory")
#define CP_WAIT1()  asm volatile("cp.async.wait_group 1;" ::: "memory")
#define CP_WAIT0()  asm volatile("cp.async.wait_group 0;" ::: "memory")
#define LDSM4(r, addr) \
    asm volatile("ldmatrix.sync.aligned.m8n8.x4.shared.b16 {%0,%1,%2,%3}, [%4];" \
                 : "=r"((r)[0]), "=r"((r)[1]), "=r"((r)[2]), "=r"((r)[3]) \
                 : "r"(addr))
#define MMA16816(d, a, b0_, b1_) \
    asm volatile("mma.sync.aligned.m16n8k16.row.col.f32.f16.f16.f32 " \
                 "{%0,%1,%2,%3}, {%4,%5,%6,%7}, {%8,%9}, {%0,%1,%2,%3};" \
                 : "+f"((d)[0]), "+f"((d)[1]), "+f"((d)[2]), "+f"((d)[3]) \
                 : "r"((a)[0]), "r"((a)[1]), "r"((a)[2]), "r"((a)[3]), \
                   "r"(b0_), "r"(b1_))

// ---------------- reductions ----------------
__device__ __forceinline__ float blockmax256(float v) {
    __shared__ float red[8];
    #pragma unroll
    for (int o = 16; o > 0; o >>= 1) v = fmaxf(v, __shfl_xor_sync(0xffffffffu, v, o));
    if ((threadIdx.x & 31) == 0) red[threadIdx.x >> 5] = v;
    __syncthreads();
    float m = red[0];
    #pragma unroll
    for (int i = 1; i < 8; i++) m = fmaxf(m, red[i]);
    __syncthreads();
    return m;
}
__device__ __forceinline__ float blocksum256(float v) {
    __shared__ float red[8];
    #pragma unroll
    for (int o = 16; o > 0; o >>= 1) v += __shfl_xor_sync(0xffffffffu, v, o);
    if ((threadIdx.x & 31) == 0) red[threadIdx.x >> 5] = v;
    __syncthreads();
    float s = red[0];
    #pragma unroll
    for (int i = 1; i < 8; i++) s += red[i];
    __syncthreads();
    return s;
}
__device__ __forceinline__ float blocksum128(float v) {
    __shared__ float red[4];
    #pragma unroll
    for (int o = 16; o > 0; o >>= 1) v += __shfl_xor_sync(0xffffffffu, v, o);
    if ((threadIdx.x & 31) == 0) red[threadIdx.x >> 5] = v;
    __syncthreads();
    float s = red[0] + red[1] + red[2] + red[3];
    __syncthreads();
    return s;
}

// ---------------- concat [x | e_flat | 0-pad] -> fp16 ----------------
__global__ void cat_kernel(const float* __restrict__ x, const float* __restrict__ e) {
    size_t idx = (size_t)blockIdx.x * blockDim.x + threadIdx.x;
    if (idx >= (size_t)Mrows * KPAD) return;
    size_t r = idx / KPAD;
    int    c = (int)(idx - r * KPAD);
    float v;
    if (c < XDim)      v = x[r * XDim + c];
    else if (c < KCAT) v = e[r * (size_t)EROW + (c - XDim)];
    else               v = 0.f;
    g_cath[idx] = __float2half(v);
}

// ---------------- transpose fp32 -> fp16: out[c][r] = in[r][c], zero-pad ----------------
__global__ void transpose_kernel(const float* __restrict__ in, __half* __restrict__ out,
                                 int R, int C, int outLd,
                                 size_t inStride, size_t outStride) {
    __shared__ float tile[32][33];
    const float* ip = in + (size_t)blockIdx.z * inStride;
    __half* op = out + (size_t)blockIdx.z * outStride;
    int c0 = blockIdx.x * 32, r0 = blockIdx.y * 32;
    int tx = threadIdx.x, ty = threadIdx.y;  // 32 x 8
    #pragma unroll
    for (int i = 0; i < 32; i += 8) {
        int r = r0 + ty + i, c = c0 + tx;
        tile[ty + i][tx] = (r < R && c < C) ? ip[(size_t)r * C + c] : 0.f;
    }
    __syncthreads();
    #pragma unroll
    for (int i = 0; i < 32; i += 8) {
        int oc = c0 + ty + i, orow = r0 + tx;
        if (oc < C && orow < outLd)
            op[(size_t)oc * outLd + orow] = __float2half(tile[tx][ty + i]);
    }
}

// ============================================================================
// fp16 tensor-core GEMM (mma.sync.m16n8k16): C = A[M,K] @ BT[N,K]^T (+bias)(+relu)
// A, BT fp16 K-major. 128x128x32 tiles, 8 warps (32m x 64n each),
// 3-stage cp.async pipeline, stride-40-half smem rows (conflict-free ldmatrix).
// C (fp32) and/or Ch (fp16) outputs, either may be null.
// Requires M%128==0, N%128==0, K%32==0, rows 16B-aligned.
// ============================================================================
#define GK_RS      40                  /* halves per smem row */
#define GK_OPB     (128 * GK_RS * 2)   /* 10240 B per operand */
#define GK_STAGE_B (2 * GK_OPB)        /* 20480 B per stage */
#define GK_SMEM_B  (3 * GK_STAGE_B)    /* 61440 B */

__global__ __launch_bounds__(256)
void gemm_h_kernel(const __half* __restrict__ A, int lda,
                   const __half* __restrict__ BT, int ldb,
                   const float* __restrict__ bias,
                   float* __restrict__ C, __half* __restrict__ Ch,
                   int ldc, int K, int relu) {
    extern __shared__ char smem[];
    const uint32_t sb = smem_to_u32(smem);
    const int t = threadIdx.x, lane = t & 31, wid = t >> 5;
    const int m0 = blockIdx.y * 128, n0 = blockIdx.x * 128;
    const int mW = (wid & 3) * 32, nW = (wid >> 2) * 64;

    // cp.async staging: 512 16B-chunks per operand, 2 per thread
    const int r0 = t >> 2,          q0 = t & 3;
    const int r1 = (t + 256) >> 2,  q1 = (t + 256) & 3;

    // ldmatrix per-lane offsets
    const int lq = lane >> 3, lr = lane & 7;
    const int aRow = (lq & 1) * 8 + lr, aCol = (lq >> 1) * 8;
    const int bRow = (lq >> 1) * 8 + lr, bCol = (lq & 1) * 8;
    const uint32_t aOff = (uint32_t)(((mW + aRow) * GK_RS + aCol) * 2);
    const uint32_t bOff = (uint32_t)(GK_OPB + ((nW + bRow) * GK_RS + bCol) * 2);

    float acc[2][8][4];
    #pragma unroll
    for (int i = 0; i < 2; i++)
        #pragma unroll
        for (int j = 0; j < 8; j++)
            #pragma unroll
            for (int r = 0; r < 4; r++) acc[i][j][r] = 0.f;

    const int nch = K >> 5;
    auto issue = [&](int ch) {
        const uint32_t dstA = sb + (uint32_t)(ch % 3) * GK_STAGE_B;
        const uint32_t dstB = dstA + GK_OPB;
        const __half* sa = A  + (size_t)m0 * lda + ch * 32;
        const __half* sbp = BT + (size_t)n0 * ldb + ch * 32;
        CP_ASYNC16(dstA + (uint32_t)((r0 * GK_RS + q0 * 8) * 2), sa  + (size_t)r0 * lda + q0 * 8);
        CP_ASYNC16(dstA + (uint32_t)((r1 * GK_RS + q1 * 8) * 2), sa  + (size_t)r1 * lda + q1 * 8);
        CP_ASYNC16(dstB + (uint32_t)((r0 * GK_RS + q0 * 8) * 2), sbp + (size_t)r0 * ldb + q0 * 8);
        CP_ASYNC16(dstB + (uint32_t)((r1 * GK_RS + q1 * 8) * 2), sbp + (size_t)r1 * ldb + q1 * 8);
        CP_COMMIT();
    };
    issue(0);
    issue(1);

    for (int ch = 0; ch < nch; ch++) {
        if (ch + 1 < nch) { CP_WAIT1(); } else { CP_WAIT0(); }
        __syncthreads();
        const uint32_t base = sb + (uint32_t)(ch % 3) * GK_STAGE_B;
        #pragma unroll
        for (int ks = 0; ks < 2; ks++) {
            uint32_t a[2][4], b[4][4];
            #pragma unroll
            for (int mt = 0; mt < 2; mt++)
                LDSM4(a[mt], base + aOff + (uint32_t)((mt * 16 * GK_RS + ks * 16) * 2));
            #pragma unroll
            for (int g = 0; g < 4; g++)
                LDSM4(b[g], base + bOff + (uint32_t)((g * 16 * GK_RS + ks * 16) * 2));
            #pragma unroll
            for (int mt = 0; mt < 2; mt++)
                #pragma unroll
                for (int g = 0; g < 4; g++) {
                    MMA16816(acc[mt][2 * g],     a[mt], b[g][0], b[g][1]);
                    MMA16816(acc[mt][2 * g + 1], a[mt], b[g][2], b[g][3]);
                }
        }
        if (ch + 2 < nch) issue(ch + 2);
    }

    // epilogue
    const int rBase = m0 + mW + (lane >> 2);
    const int cBase = n0 + nW + (lane & 3) * 2;
    #pragma unroll
    for (int mt = 0; mt < 2; mt++) {
        #pragma unroll
        for (int nt = 0; nt < 8; nt++) {
            const int c = cBase + nt * 8;
            float b0 = 0.f, b1 = 0.f;
            if (bias) { b0 = bias[c]; b1 = bias[c + 1]; }
            float v00 = acc[mt][nt][0] + b0, v01 = acc[mt][nt][1] + b1;
            float v10 = acc[mt][nt][2] + b0, v11 = acc[mt][nt][3] + b1;
            if (relu) {
                v00 = fmaxf(v00, 0.f); v01 = fmaxf(v01, 0.f);
                v10 = fmaxf(v10, 0.f); v11 = fmaxf(v11, 0.f);
            }
            const int rA = rBase + mt * 16, rB = rA + 8;
            if (C) {
                *(float2*)(C + (size_t)rA * ldc + c) = make_float2(v00, v01);
                *(float2*)(C + (size_t)rB * ldc + c) = make_float2(v10, v11);
            }
            if (Ch) {
                *(__half2*)(Ch + (size_t)rA * ldc + c) = __floats2half2_rn(v00, v01);
                *(__half2*)(Ch + (size_t)rB * ldc + c) = __floats2half2_rn(v10, v11);
            }
        }
    }
}

// ---------------- row squared norms of z ----------------
__global__ void sqnorm_kernel() {
    int r = blockIdx.x;
    float s = 0.f;
    for (int c = threadIdx.x; c < Hd; c += 128) {
        float v = g_z[(size_t)r * Hd + c];
        s += v * v;
    }
    s = blocksum128(s);
    if (threadIdx.x == 0) g_sq[r] = s;
}

// ---------------- masked pairwise distance: g_D = cdist(z,z)*dm ----------------
__global__ __launch_bounds__(256) void dist_kernel(const float* __restrict__ mask) {
    int b  = blockIdx.z;
    int ti = blockIdx.y * 64, tj = blockIdx.x * 64;
    const float* zb = g_z + (size_t)b * Nn * Hd;
    __shared__ float Zi[16][64];
    __shared__ float Zj[16][64];
    int t = threadIdx.x, tx = t & 15, ty = t >> 4;
    float acc[4][4];
    #pragma unroll
    for (int i = 0; i < 4; i++)
        #pragma unroll
        for (int j = 0; j < 4; j++) acc[i][j] = 0.f;

    int l = t * 4, ar = l >> 4, ac = l & 15;
    for (int k0 = 0; k0 < Hd; k0 += 16) {
        #pragma unroll
        for (int u = 0; u < 4; u++) {
            Zi[ac + u][ar] = zb[(size_t)(ti + ar) * Hd + k0 + ac + u];
            Zj[ac + u][ar] = zb[(size_t)(tj + ar) * Hd + k0 + ac + u];
        }
        __syncthreads();
        #pragma unroll
        for (int kk = 0; kk < 16; kk++) {
            float a[4], bb[4];
            #pragma unroll
            for (int i = 0; i < 4; i++) a[i] = Zi[kk][ty * 4 + i];
            #pragma unroll
            for (int j = 0; j < 4; j++) bb[j] = Zj[kk][tx * 4 + j];
            #pragma unroll
            for (int i = 0; i < 4; i++)
                #pragma unroll
                for (int j = 0; j < 4; j++) acc[i][j] = fmaf(a[i], bb[j], acc[i][j]);
        }
        __syncthreads();
    }
    #pragma unroll
    for (int i = 0; i < 4; i++) {
        int gi = ti + ty * 4 + i;
        float sqi = g_sq[b * Nn + gi], mi = mask[b * Nn + gi];
        #pragma unroll
        for (int j = 0; j < 4; j++) {
            int gj = tj + tx * 4 + j;
            float d2 = sqi + g_sq[b * Nn + gj] - 2.f * acc[i][j];
            d2 = fmaxf(d2, 0.f);
            float d  = (d2 > 1e-12f) ? sqrtf(d2) : 0.f;
            float dm = mi * mask[b * Nn + gj];
            g_D[((size_t)b * Nn + gi) * Nn + gj] = d * dm;
        }
    }
}

// ---------------- bias: D = (rowmax - D) masked, diag 0 ----------------
__global__ void distbias_kernel(const float* __restrict__ mask) {
    int r = blockIdx.x;
    int b = r / Nn, i = r - b * Nn;
    float* p = g_D + (size_t)r * Nn;
    int t = threadIdx.x;
    float v  = p[t];
    float bm = blockmax256(v);
    float dm = mask[r] * mask[b * Nn + t];
    p[t] = (t == i) ? 0.f : (bm - v) * dm;
}

// ---------------- scores = QK^T/sqrt(48) + D ----------------
__global__ __launch_bounds__(256) void qk_kernel() {
    int bh = blockIdx.z;
    int b  = bh / NHd, h = bh - b * NHd;
    int ti = blockIdx.y * 64, tj = blockIdx.x * 64;
    const float* qb = g_q + (size_t)b * Nn * Hd + h * DHd;
    const float* kb = g_k + (size_t)b * Nn * Hd + h * DHd;
    __shared__ float Qs[64][49];
    __shared__ float Ks[64][49];
    int t = threadIdx.x, tx = t & 15, ty = t >> 4;
    for (int l = t; l < 64 * 48; l += 256) {
        int r = l / 48, c = l - r * 48;
        Qs[r][c] = qb[(size_t)(ti + r) * Hd + c];
        Ks[r][c] = kb[(size_t)(tj + r) * Hd + c];
    }
    __syncthreads();
    float acc[4][4];
    #pragma unroll
    for (int i = 0; i < 4; i++)
        #pragma unroll
        for (int j = 0; j < 4; j++) acc[i][j] = 0.f;
    #pragma unroll 4
    for (int kk = 0; kk < 48; kk++) {
        float a[4], bb[4];
        #pragma unroll
        for (int i = 0; i < 4; i++) a[i] = Qs[ty * 4 + i][kk];
        #pragma unroll
        for (int j = 0; j < 4; j++) bb[j] = Ks[tx * 4 + j][kk];
        #pragma unroll
        for (int i = 0; i < 4; i++)
            #pragma unroll
            for (int j = 0; j < 4; j++) acc[i][j] = fmaf(a[i], bb[j], acc[i][j]);
    }
    const float scale = 0.144337567297406441f;
    #pragma unroll
    for (int i = 0; i < 4; i++) {
        int gi = ti + ty * 4 + i;
        #pragma unroll
        for (int j = 0; j < 4; j++) {
            int gj = tj + tx * 4 + j;
            g_att[((size_t)bh * Nn + gi) * Nn + gj] =
                acc[i][j] * scale + g_D[((size_t)b * Nn + gi) * Nn + gj];
        }
    }
}

// ---------------- softmax over last dim (rows of 256) ----------------
__global__ void softmax_kernel() {
    float* p = g_att + (size_t)blockIdx.x * Nn;
    int t = threadIdx.x;
    float v  = p[t];
    float bm = blockmax256(v);
    float e  = __expf(v - bm);
    float s  = blocksum256(e);
    p[t] = e / s;
}

// ---------------- y = attn @ V  (writes fp16 yh) ----------------
__global__ __launch_bounds__(256) void attnv_kernel() {
    int bh = blockIdx.y;
    int b  = bh / NHd, h = bh - b * NHd;
    int ti = blockIdx.x * 64;
    const float* arow = g_att + (size_t)bh * Nn * Nn;
    const float* vb   = g_v + (size_t)b * Nn * Hd + h * DHd;
    __shared__ float As[64][65];
    __shared__ float Vs[64][49];
    int t = threadIdx.x, tx = t & 15, ty = t >> 4;
    float acc[4][3];
    #pragma unroll
    for (int i = 0; i < 4; i++)
        #pragma unroll
        for (int j = 0; j < 3; j++) acc[i][j] = 0.f;

    for (int j0 = 0; j0 < Nn; j0 += 64) {
        for (int l = t; l < 64 * 64; l += 256)
            As[l >> 6][l & 63] = arow[(size_t)(ti + (l >> 6)) * Nn + j0 + (l & 63)];
        for (int l = t; l < 64 * 48; l += 256) {
            int r = l / 48, c = l - r * 48;
            Vs[r][c] = vb[(size_t)(j0 + r) * Hd + c];
        }
        __syncthreads();
        #pragma unroll 4
        for (int kk = 0; kk < 64; kk++) {
            float a[4], bb[3];
            #pragma unroll
            for (int i = 0; i < 4; i++) a[i] = As[ty * 4 + i][kk];
            #pragma unroll
            for (int j = 0; j < 3; j++) bb[j] = Vs[kk][tx * 3 + j];
            #pragma unroll
            for (int i = 0; i < 4; i++)
                #pragma unroll
                for (int j = 0; j < 3; j++) acc[i][j] = fmaf(a[i], bb[j], acc[i][j]);
        }
        __syncthreads();
    }
    #pragma unroll
    for (int i = 0; i < 4; i++) {
        int gi = ti + ty * 4 + i;
        #pragma unroll
        for (int j = 0; j < 3; j++)
            g_yh[((size_t)b * Nn + gi) * Hd + h * DHd + tx * 3 + j] =
                __float2half(acc[i][j]);
    }
}

// ---------------- out = LayerNorm(a + r), fp32 + fp16 shadow ----------------
__global__ void addln_kernel(const float* __restrict__ a, const float* __restrict__ r,
                             const float* __restrict__ g, const float* __restrict__ be,
                             float* __restrict__ out, __half* __restrict__ outh) {
    int row = blockIdx.x;
    int t = threadIdx.x;
    float vals[3];
    float s = 0.f;
    #pragma unroll
    for (int u = 0; u < 3; u++) {
        int c = t + u * 128;
        float v = a[(size_t)row * Hd + c] + r[(size_t)row * Hd + c];
        vals[u] = v;
        s += v;
    }
    float mu = blocksum128(s) * (1.f / Hd);
    float s2 = 0.f;
    #pragma unroll
    for (int u = 0; u < 3; u++) { float d = vals[u] - mu; s2 += d * d; }
    float var  = blocksum128(s2) * (1.f / Hd);
    float rstd = rsqrtf(var + 1e-5f);
    #pragma unroll
    for (int u = 0; u < 3; u++) {
        int c = t + u * 128;
        float o = (vals[u] - mu) * rstd * g[c] + be[c];
        out[(size_t)row * Hd + c]  = o;
        outh[(size_t)row * Hd + c] = __float2half(o);
    }
}

// ---------------- masked outputs ----------------
__global__ void out_x_kernel(const float* __restrict__ x, const float* __restrict__ mask,
                             float* __restrict__ out) {
    size_t idx = (size_t)blockIdx.x * blockDim.x + threadIdx.x;
    if (idx >= (size_t)Bn * Nn * XDim) return;
    out[idx] = x[idx] * mask[idx / XDim];
}
__global__ void out_e_kernel(const float* __restrict__ e, const float* __restrict__ mask,
                             float* __restrict__ out) {
    size_t idx = (size_t)blockIdx.x * blockDim.x + threadIdx.x;
    if (idx >= (size_t)Bn * Nn * Nn * EDim) return;
    size_t pair = idx / EDim;
    int j  = (int)(pair % Nn);
    size_t bi = pair / Nn;
    int b  = (int)(bi / Nn);
    out[idx] = e[idx] * mask[bi] * mask[(size_t)b * Nn + j];
}
__global__ void out_z_kernel(const float* __restrict__ mask, float* __restrict__ out) {
    size_t idx = (size_t)blockIdx.x * blockDim.x + threadIdx.x;
    if (idx >= (size_t)Mrows * Hd) return;
    out[idx] = g_z[idx] * mask[idx / Hd];
}

// ---------------- launcher ----------------
extern "C" void kernel_launch(void* const* d_in, const int* in_sizes, int n_in,
                              void* d_out, int out_size) {
    const float* x    = (const float*)d_in[0];
    const float* e    = (const float*)d_in[1];
    const float* mask = (const float*)d_in[2];
    const float* Wemb = (const float*)d_in[3];
    const float* Wq = (const float*)d_in[4];  const float* bq = (const float*)d_in[5];
    const float* Wk = (const float*)d_in[6];  const float* bk = (const float*)d_in[7];
    const float* Wv = (const float*)d_in[8];  const float* bv = (const float*)d_in[9];
    const float* Wo = (const float*)d_in[10]; const float* bo = (const float*)d_in[11];
    const float* g1 = (const float*)d_in[12]; const float* be1 = (const float*)d_in[13];
    const float* W1 = (const float*)d_in[14]; const float* b1  = (const float*)d_in[15];
    const float* W2 = (const float*)d_in[16]; const float* b2  = (const float*)d_in[17];
    const float* g2 = (const float*)d_in[18]; const float* be2 = (const float*)d_in[19];
    float* out = (float*)d_out;

    float  *z, *q, *k, *v, *x1;
    __half *cath, *zh, *x1h, *yh, *ffnh;
    __half *wembTh, *wqTh, *wkTh, *wvTh, *woTh, *w1Th, *w2Th;
    cudaGetSymbolAddress((void**)&cath,  g_cath);
    cudaGetSymbolAddress((void**)&z,     g_z);
    cudaGetSymbolAddress((void**)&zh,    g_zh);
    cudaGetSymbolAddress((void**)&q,     g_q);
    cudaGetSymbolAddress((void**)&k,     g_k);
    cudaGetSymbolAddress((void**)&v,     g_v);
    cudaGetSymbolAddress((void**)&yh,    g_yh);
    cudaGetSymbolAddress((void**)&x1,    g_x1);
    cudaGetSymbolAddress((void**)&x1h,   g_x1h);
    cudaGetSymbolAddress((void**)&ffnh,  g_ffnh);
    cudaGetSymbolAddress((void**)&wembTh, g_wembTh);
    cudaGetSymbolAddress((void**)&wqTh,  g_wqTh);
    cudaGetSymbolAddress((void**)&wkTh,  g_wkTh);
    cudaGetSymbolAddress((void**)&wvTh,  g_wvTh);
    cudaGetSymbolAddress((void**)&woTh,  g_woTh);
    cudaGetSymbolAddress((void**)&w1Th,  g_w1Th);
    cudaGetSymbolAddress((void**)&w2Th,  g_w2Th);

    cudaFuncSetAttribute(gemm_h_kernel,
                         cudaFuncAttributeMaxDynamicSharedMemorySize, GK_SMEM_B);

    dim3 tb(32, 8);
    // launches 1-5, then embed GEMM as launch #6 (ncu captures launch 6)
    {
        size_t tot = (size_t)Mrows * KPAD;
        cat_kernel<<<(unsigned)((tot + 255) / 256), 256>>>(x, e);                    // 1
    }
    transpose_kernel<<<dim3(12, 44, 1), tb>>>(Wemb, wembTh, KCAT, Hd, KPAD, 0, 0);   // 2
    transpose_kernel<<<dim3(12, 12, DEPTH), tb>>>(Wq, wqTh, Hd, Hd, Hd,
                                                  (size_t)Hd * Hd, (size_t)Hd * Hd); // 3
    transpose_kernel<<<dim3(12, 12, DEPTH), tb>>>(Wk, wkTh, Hd, Hd, Hd,
                                                  (size_t)Hd * Hd, (size_t)Hd * Hd); // 4
    transpose_kernel<<<dim3(12, 12, DEPTH), tb>>>(Wv, wvTh, Hd, Hd, Hd,
                                                  (size_t)Hd * Hd, (size_t)Hd * Hd); // 5
    gemm_h_kernel<<<dim3(Hd / 128, Mrows / 128), 256, GK_SMEM_B>>>(                  // 6
        cath, KPAD, wembTh, KPAD, nullptr, z, zh, Hd, KPAD, 0);
    transpose_kernel<<<dim3(12, 12, DEPTH), tb>>>(Wo, woTh, Hd, Hd, Hd,
                                                  (size_t)Hd * Hd, (size_t)Hd * Hd);
    transpose_kernel<<<dim3(48, 12, DEPTH), tb>>>(W1, w1Th, Hd, DFFd, Hd,
                                                  (size_t)Hd * DFFd, (size_t)DFFd * Hd);
    transpose_kernel<<<dim3(12, 48, DEPTH), tb>>>(W2, w2Th, DFFd, Hd, DFFd,
                                                  (size_t)DFFd * Hd, (size_t)Hd * DFFd);

    for (int l = 0; l < DEPTH; l++) {
        const size_t wofs  = (size_t)l * Hd * Hd;
        const size_t w1ofs = (size_t)l * DFFd * Hd;
        // distance bias
        sqnorm_kernel<<<Mrows, 128>>>();
        dist_kernel<<<dim3(4, 4, Bn), 256>>>(mask);
        distbias_kernel<<<Mrows, 256>>>(mask);
        // QKV (fp16 A = zh)
        gemm_h_kernel<<<dim3(Hd / 128, Mrows / 128), 256, GK_SMEM_B>>>(
            zh, Hd, wqTh + wofs, Hd, bq + (size_t)l * Hd, q, nullptr, Hd, Hd, 0);
        gemm_h_kernel<<<dim3(Hd / 128, Mrows / 128), 256, GK_SMEM_B>>>(
            zh, Hd, wkTh + wofs, Hd, bk + (size_t)l * Hd, k, nullptr, Hd, Hd, 0);
        gemm_h_kernel<<<dim3(Hd / 128, Mrows / 128), 256, GK_SMEM_B>>>(
            zh, Hd, wvTh + wofs, Hd, bv + (size_t)l * Hd, v, nullptr, Hd, Hd, 0);
        // attention
        qk_kernel<<<dim3(4, 4, Bn * NHd), 256>>>();
        softmax_kernel<<<Bn * NHd * Nn, 256>>>();
        attnv_kernel<<<dim3(4, Bn * NHd), 256>>>();
        // output projection (into q as fp32 temp) + AddNorm
        gemm_h_kernel<<<dim3(Hd / 128, Mrows / 128), 256, GK_SMEM_B>>>(
            yh, Hd, woTh + wofs, Hd, bo + (size_t)l * Hd, q, nullptr, Hd, Hd, 0);
        addln_kernel<<<Mrows, 128>>>(z, q, g1 + (size_t)l * Hd, be1 + (size_t)l * Hd,
                                     x1, x1h);
        // FFN (FFN1 output only needed as fp16)
        gemm_h_kernel<<<dim3(DFFd / 128, Mrows / 128), 256, GK_SMEM_B>>>(
            x1h, Hd, w1Th + w1ofs, Hd, b1 + (size_t)l * DFFd,
            nullptr, ffnh, DFFd, Hd, 1);
        gemm_h_kernel<<<dim3(Hd / 128, Mrows / 128), 256, GK_SMEM_B>>>(
            ffnh, DFFd, w2Th + w1ofs, DFFd, b2 + (size_t)l * Hd,
            q, nullptr, Hd, DFFd, 0);
        addln_kernel<<<Mrows, 128>>>(x1, q, g2 + (size_t)l * Hd, be2 + (size_t)l * Hd,
                                     z, zh);
    }

    // outputs: [X_out | E_out | z_out]
    const size_t XTOT = (size_t)Bn * Nn * XDim;
    const size_t ETOT = (size_t)Bn * Nn * Nn * EDim;
    const size_t ZTOT = (size_t)Mrows * Hd;
    out_x_kernel<<<(unsigned)((XTOT + 255) / 256), 256>>>(x, mask, out);
    out_e_kernel<<<(unsigned)((ETOT + 255) / 256), 256>>>(e, mask, out + XTOT);
    out_z_kernel<<<(unsigned)((ZTOT + 255) / 256), 256>>>(mask, out + XTOT + ETOT);
    (void)in_sizes; (void)n_in; (void)out_size;
}

// round 8
// speedup vs baseline: 5.8598x; 1.5040x over previous
#include <cuda_runtime.h>
#include <cuda_fp16.h>
#include <math.h>
#include <stdint.h>

#define Bn    64
#define Nn    256
#define XDim  118
#define EDim  5
#define Hd    384
#define NHd   8
#define DHd   48
#define DFFd  1536
#define DEPTH 6
#define Mrows (Bn * Nn)            /* 16384 */
#define KCAT  (XDim + Nn * EDim)   /* 1398  */
#define KPAD  1408                 /* KCAT padded (mult of 32) */
#define EROW  (Nn * EDim)          /* 1280  */

// ---------------- scratch (device globals; zero-init at load, no allocation) ----------------
__device__ __half g_cath[(size_t)Mrows * KPAD];
__device__ float  g_z  [(size_t)Mrows * Hd];
__device__ __half g_zh [(size_t)Mrows * Hd];
__device__ float  g_q  [(size_t)Mrows * Hd];      // fp32 temp (Wo / FFN2 out)
__device__ __half g_yh [(size_t)Mrows * Hd];
__device__ float  g_x1 [(size_t)Mrows * Hd];
__device__ __half g_x1h[(size_t)Mrows * Hd];
__device__ __half g_ffnh[(size_t)Mrows * DFFd];
__device__ float  g_att[(size_t)Bn * NHd * Nn * Nn];   // fp32 scores
__device__ __half g_atth[(size_t)Bn * NHd * Nn * Nn];  // fp16 probs
__device__ float  g_D  [(size_t)Bn * Nn * Nn];
__device__ float  g_sq [Mrows];
// per-head padded Q/K: [b,h,256,64] (cols 48..63 never written -> stay zero)
__device__ __half g_qhp[(size_t)Bn * NHd * Nn * 64];
__device__ __half g_khp[(size_t)Bn * NHd * Nn * 64];
// per-head transposed V: [b,h,48,256]
__device__ __half g_vth[(size_t)Bn * NHd * DHd * Nn];
// transposed fp16 weights [N][K]
__device__ __half g_wembTh[(size_t)Hd * KPAD];
__device__ __half g_wqTh [(size_t)DEPTH * Hd * Hd];
__device__ __half g_wkTh [(size_t)DEPTH * Hd * Hd];
__device__ __half g_wvTh [(size_t)DEPTH * Hd * Hd];
__device__ __half g_woTh [(size_t)DEPTH * Hd * Hd];
__device__ __half g_w1Th [(size_t)DEPTH * DFFd * Hd];
__device__ __half g_w2Th [(size_t)DEPTH * Hd * DFFd];

// ---------------- PTX helpers (sm_80+ base ISA) ----------------
__device__ __forceinline__ uint32_t smem_to_u32(const void* p) {
    uint32_t a;
    asm("{ .reg .u64 t; cvta.to.shared.u64 t, %1; cvt.u32.u64 %0, t; }"
        : "=r"(a) : "l"(p));
    return a;
}
#define CP_ASYNC16(dst, src) \
    asm volatile("cp.async.cg.shared.global [%0], [%1], 16;" \
                 :: "r"(dst), "l"(src) : "memory")
#define CP_COMMIT() asm volatile("cp.async.commit_group;" ::: "memory")
#define CP_WAIT1()  asm volatile("cp.async.wait_group 1;" ::: "memory")
#define CP_WAIT0()  asm volatile("cp.async.wait_group 0;" ::: "memory")
#define LDSM4(r, addr) \
    asm volatile("ldmatrix.sync.aligned.m8n8.x4.shared.b16 {%0,%1,%2,%3}, [%4];" \
                 : "=r"((r)[0]), "=r"((r)[1]), "=r"((r)[2]), "=r"((r)[3]) \
                 : "r"(addr))
#define MMA16816(d, a, b0_, b1_) \
    asm volatile("mma.sync.aligned.m16n8k16.row.col.f32.f16.f16.f32 " \
                 "{%0,%1,%2,%3}, {%4,%5,%6,%7}, {%8,%9}, {%0,%1,%2,%3};" \
                 : "+f"((d)[0]), "+f"((d)[1]), "+f"((d)[2]), "+f"((d)[3]) \
                 : "r"((a)[0]), "r"((a)[1]), "r"((a)[2]), "r"((a)[3]), \
                   "r"(b0_), "r"(b1_))

// ---------------- reductions ----------------
__device__ __forceinline__ float blockmax256(float v) {
    __shared__ float red[8];
    #pragma unroll
    for (int o = 16; o > 0; o >>= 1) v = fmaxf(v, __shfl_xor_sync(0xffffffffu, v, o));
    if ((threadIdx.x & 31) == 0) red[threadIdx.x >> 5] = v;
    __syncthreads();
    float m = red[0];
    #pragma unroll
    for (int i = 1; i < 8; i++) m = fmaxf(m, red[i]);
    __syncthreads();
    return m;
}
__device__ __forceinline__ float blocksum256(float v) {
    __shared__ float red[8];
    #pragma unroll
    for (int o = 16; o > 0; o >>= 1) v += __shfl_xor_sync(0xffffffffu, v, o);
    if ((threadIdx.x & 31) == 0) red[threadIdx.x >> 5] = v;
    __syncthreads();
    float s = red[0];
    #pragma unroll
    for (int i = 1; i < 8; i++) s += red[i];
    __syncthreads();
    return s;
}
__device__ __forceinline__ float blocksum128(float v) {
    __shared__ float red[4];
    #pragma unroll
    for (int o = 16; o > 0; o >>= 1) v += __shfl_xor_sync(0xffffffffu, v, o);
    if ((threadIdx.x & 31) == 0) red[threadIdx.x >> 5] = v;
    __syncthreads();
    float s = red[0] + red[1] + red[2] + red[3];
    __syncthreads();
    return s;
}

// ---------------- concat [x | e_flat | 0-pad] -> fp16 ----------------
__global__ void cat_kernel(const float* __restrict__ x, const float* __restrict__ e) {
    size_t idx = (size_t)blockIdx.x * blockDim.x + threadIdx.x;
    if (idx >= (size_t)Mrows * KPAD) return;
    size_t r = idx / KPAD;
    int    c = (int)(idx - r * KPAD);
    float v;
    if (c < XDim)      v = x[r * XDim + c];
    else if (c < KCAT) v = e[r * (size_t)EROW + (c - XDim)];
    else               v = 0.f;
    g_cath[idx] = __float2half(v);
}

// ---------------- transpose fp32 -> fp16 ----------------
__global__ void transpose_kernel(const float* __restrict__ in, __half* __restrict__ out,
                                 int R, int C, int outLd,
                                 size_t inStride, size_t outStride) {
    __shared__ float tile[32][33];
    const float* ip = in + (size_t)blockIdx.z * inStride;
    __half* op = out + (size_t)blockIdx.z * outStride;
    int c0 = blockIdx.x * 32, r0 = blockIdx.y * 32;
    int tx = threadIdx.x, ty = threadIdx.y;
    #pragma unroll
    for (int i = 0; i < 32; i += 8) {
        int r = r0 + ty + i, c = c0 + tx;
        tile[ty + i][tx] = (r < R && c < C) ? ip[(size_t)r * C + c] : 0.f;
    }
    __syncthreads();
    #pragma unroll
    for (int i = 0; i < 32; i += 8) {
        int oc = c0 + ty + i, orow = r0 + tx;
        if (oc < C && orow < outLd)
            op[(size_t)oc * outLd + orow] = __float2half(tile[tx][ty + i]);
    }
}

// ============================================================================
// fp16 HMMA GEMM, 128x128x32 tiles, 8 warps, 3-stage cp.async.
// mode 0: C fp32 (+Ch fp16 row-major);  mode 1: Ch = padded-head QK layout;
// mode 2: Ch = transposed-head V layout.
// ============================================================================
#define GK_RS      40
#define GK_OPB     (128 * GK_RS * 2)
#define GK_STAGE_B (2 * GK_OPB)
#define GK_SMEM_B  (3 * GK_STAGE_B)   /* 61440 */

__global__ __launch_bounds__(256)
void gemm_h_kernel(const __half* __restrict__ A, int lda,
                   const __half* __restrict__ BT, int ldb,
                   const float* __restrict__ bias,
                   float* __restrict__ C, __half* __restrict__ Ch,
                   int ldc, int K, int relu, int mode) {
    extern __shared__ char smem[];
    const uint32_t sb = smem_to_u32(smem);
    const int t = threadIdx.x, lane = t & 31, wid = t >> 5;
    const int m0 = blockIdx.y * 128, n0 = blockIdx.x * 128;
    const int mW = (wid & 3) * 32, nW = (wid >> 2) * 64;

    const int r0 = t >> 2,          q0 = t & 3;
    const int r1 = (t + 256) >> 2,  q1 = (t + 256) & 3;

    const int lq = lane >> 3, lr = lane & 7;
    const int aRow = (lq & 1) * 8 + lr, aCol = (lq >> 1) * 8;
    const int bRow = (lq >> 1) * 8 + lr, bCol = (lq & 1) * 8;
    const uint32_t aOff = (uint32_t)(((mW + aRow) * GK_RS + aCol) * 2);
    const uint32_t bOff = (uint32_t)(GK_OPB + ((nW + bRow) * GK_RS + bCol) * 2);

    float acc[2][8][4];
    #pragma unroll
    for (int i = 0; i < 2; i++)
        #pragma unroll
        for (int j = 0; j < 8; j++)
            #pragma unroll
            for (int r = 0; r < 4; r++) acc[i][j][r] = 0.f;

    const int nch = K >> 5;
    auto issue = [&](int ch) {
        const uint32_t dstA = sb + (uint32_t)(ch % 3) * GK_STAGE_B;
        const uint32_t dstB = dstA + GK_OPB;
        const __half* sa  = A  + (size_t)m0 * lda + ch * 32;
        const __half* sbp = BT + (size_t)n0 * ldb + ch * 32;
        CP_ASYNC16(dstA + (uint32_t)((r0 * GK_RS + q0 * 8) * 2), sa  + (size_t)r0 * lda + q0 * 8);
        CP_ASYNC16(dstA + (uint32_t)((r1 * GK_RS + q1 * 8) * 2), sa  + (size_t)r1 * lda + q1 * 8);
        CP_ASYNC16(dstB + (uint32_t)((r0 * GK_RS + q0 * 8) * 2), sbp + (size_t)r0 * ldb + q0 * 8);
        CP_ASYNC16(dstB + (uint32_t)((r1 * GK_RS + q1 * 8) * 2), sbp + (size_t)r1 * ldb + q1 * 8);
        CP_COMMIT();
    };
    issue(0);
    issue(1);

    for (int ch = 0; ch < nch; ch++) {
        if (ch + 1 < nch) { CP_WAIT1(); } else { CP_WAIT0(); }
        __syncthreads();
        const uint32_t base = sb + (uint32_t)(ch % 3) * GK_STAGE_B;
        #pragma unroll
        for (int ks = 0; ks < 2; ks++) {
            uint32_t a[2][4], b[4][4];
            #pragma unroll
            for (int mt = 0; mt < 2; mt++)
                LDSM4(a[mt], base + aOff + (uint32_t)((mt * 16 * GK_RS + ks * 16) * 2));
            #pragma unroll
            for (int g = 0; g < 4; g++)
                LDSM4(b[g], base + bOff + (uint32_t)((g * 16 * GK_RS + ks * 16) * 2));
            #pragma unroll
            for (int mt = 0; mt < 2; mt++)
                #pragma unroll
                for (int g = 0; g < 4; g++) {
                    MMA16816(acc[mt][2 * g],     a[mt], b[g][0], b[g][1]);
                    MMA16816(acc[mt][2 * g + 1], a[mt], b[g][2], b[g][3]);
                }
        }
        if (ch + 2 < nch) issue(ch + 2);
    }

    const int rBase = m0 + mW + (lane >> 2);
    const int cBase = n0 + nW + (lane & 3) * 2;
    #pragma unroll
    for (int mt = 0; mt < 2; mt++) {
        #pragma unroll
        for (int nt = 0; nt < 8; nt++) {
            const int c = cBase + nt * 8;
            float b0 = 0.f, b1 = 0.f;
            if (bias) { b0 = bias[c]; b1 = bias[c + 1]; }
            float v00 = acc[mt][nt][0] + b0, v01 = acc[mt][nt][1] + b1;
            float v10 = acc[mt][nt][2] + b0, v11 = acc[mt][nt][3] + b1;
            if (relu) {
                v00 = fmaxf(v00, 0.f); v01 = fmaxf(v01, 0.f);
                v10 = fmaxf(v10, 0.f); v11 = fmaxf(v11, 0.f);
            }
            const int rA = rBase + mt * 16, rB = rA + 8;
            if (mode == 0) {
                if (C) {
                    *(float2*)(C + (size_t)rA * ldc + c) = make_float2(v00, v01);
                    *(float2*)(C + (size_t)rB * ldc + c) = make_float2(v10, v11);
                }
                if (Ch) {
                    *(__half2*)(Ch + (size_t)rA * ldc + c) = __floats2half2_rn(v00, v01);
                    *(__half2*)(Ch + (size_t)rB * ldc + c) = __floats2half2_rn(v10, v11);
                }
            } else {
                const int h = c / DHd, d = c - h * DHd;
                const int bIdx = rA >> 8;  // rA, rB in same 256-block
                if (mode == 1) {
                    size_t p0 = ((((size_t)bIdx * NHd + h) << 8) | (rA & 255)) * 64 + d;
                    size_t p1 = ((((size_t)bIdx * NHd + h) << 8) | (rB & 255)) * 64 + d;
                    *(__half2*)(Ch + p0) = __floats2half2_rn(v00, v01);
                    *(__half2*)(Ch + p1) = __floats2half2_rn(v10, v11);
                } else {
                    size_t hb = ((size_t)bIdx * NHd + h) * DHd;
                    Ch[(hb + d)     * Nn + (rA & 255)] = __float2half(v00);
                    Ch[(hb + d + 1) * Nn + (rA & 255)] = __float2half(v01);
                    Ch[(hb + d)     * Nn + (rB & 255)] = __float2half(v10);
                    Ch[(hb + d + 1) * Nn + (rB & 255)] = __float2half(v11);
                }
            }
        }
    }
}

// ============================================================================
// gram_kernel<MODE>: 128x128 HMMA tiles over per-slice operands.
// MODE 0: dist  (A=B=zh slice, K=384) -> g_D with sqrt/mask epilogue
// MODE 1: qk    (A=qhp, B=khp slices, K=64) -> g_att = acc*scale + D
// ============================================================================
template <int MODE>
__global__ __launch_bounds__(256)
void gram_kernel(const __half* __restrict__ Abase, const __half* __restrict__ Bbase,
                 const float* __restrict__ mask) {
    extern __shared__ char smem[];
    const uint32_t sb = smem_to_u32(smem);
    const int t = threadIdx.x, lane = t & 31, wid = t >> 5;
    const int bz = blockIdx.z;
    const int m0 = blockIdx.y * 128, n0 = blockIdx.x * 128;
    const int mW = (wid & 3) * 32, nW = (wid >> 2) * 64;

    const __half* A;
    const __half* BT;
    int ld, K;
    if (MODE == 0) {
        A  = Abase + (size_t)bz * Nn * Hd;
        BT = A;
        ld = Hd; K = Hd;
    } else {
        A  = Abase + (size_t)bz * Nn * 64;
        BT = Bbase + (size_t)bz * Nn * 64;
        ld = 64; K = 64;
    }

    const int r0 = t >> 2,          q0 = t & 3;
    const int r1 = (t + 256) >> 2,  q1 = (t + 256) & 3;
    const int lq = lane >> 3, lr = lane & 7;
    const int aRow = (lq & 1) * 8 + lr, aCol = (lq >> 1) * 8;
    const int bRow = (lq >> 1) * 8 + lr, bCol = (lq & 1) * 8;
    const uint32_t aOff = (uint32_t)(((mW + aRow) * GK_RS + aCol) * 2);
    const uint32_t bOff = (uint32_t)(GK_OPB + ((nW + bRow) * GK_RS + bCol) * 2);

    float acc[2][8][4];
    #pragma unroll
    for (int i = 0; i < 2; i++)
        #pragma unroll
        for (int j = 0; j < 8; j++)
            #pragma unroll
            for (int r = 0; r < 4; r++) acc[i][j][r] = 0.f;

    const int nch = K >> 5;
    auto issue = [&](int ch) {
        const uint32_t dstA = sb + (uint32_t)(ch % 3) * GK_STAGE_B;
        const uint32_t dstB = dstA + GK_OPB;
        const __half* sa  = A  + (size_t)m0 * ld + ch * 32;
        const __half* sbp = BT + (size_t)n0 * ld + ch * 32;
        CP_ASYNC16(dstA + (uint32_t)((r0 * GK_RS + q0 * 8) * 2), sa  + (size_t)r0 * ld + q0 * 8);
        CP_ASYNC16(dstA + (uint32_t)((r1 * GK_RS + q1 * 8) * 2), sa  + (size_t)r1 * ld + q1 * 8);
        CP_ASYNC16(dstB + (uint32_t)((r0 * GK_RS + q0 * 8) * 2), sbp + (size_t)r0 * ld + q0 * 8);
        CP_ASYNC16(dstB + (uint32_t)((r1 * GK_RS + q1 * 8) * 2), sbp + (size_t)r1 * ld + q1 * 8);
        CP_COMMIT();
    };
    issue(0);
    if (nch > 1) issue(1);

    for (int ch = 0; ch < nch; ch++) {
        if (ch + 1 < nch) { CP_WAIT1(); } else { CP_WAIT0(); }
        __syncthreads();
        const uint32_t base = sb + (uint32_t)(ch % 3) * GK_STAGE_B;
        #pragma unroll
        for (int ks = 0; ks < 2; ks++) {
            uint32_t a[2][4], b[4][4];
            #pragma unroll
            for (int mt = 0; mt < 2; mt++)
                LDSM4(a[mt], base + aOff + (uint32_t)((mt * 16 * GK_RS + ks * 16) * 2));
            #pragma unroll
            for (int g = 0; g < 4; g++)
                LDSM4(b[g], base + bOff + (uint32_t)((g * 16 * GK_RS + ks * 16) * 2));
            #pragma unroll
            for (int mt = 0; mt < 2; mt++)
                #pragma unroll
                for (int g = 0; g < 4; g++) {
                    MMA16816(acc[mt][2 * g],     a[mt], b[g][0], b[g][1]);
                    MMA16816(acc[mt][2 * g + 1], a[mt], b[g][2], b[g][3]);
                }
        }
        if (ch + 2 < nch) issue(ch + 2);
    }

    const int rBase = m0 + mW + (lane >> 2);
    const int cBase = n0 + nW + (lane & 3) * 2;
    #pragma unroll
    for (int mt = 0; mt < 2; mt++) {
        const int gi0 = rBase + mt * 16;
        #pragma unroll
        for (int nt = 0; nt < 8; nt++) {
            const int gj = cBase + nt * 8;
            #pragma unroll
            for (int rr = 0; rr < 2; rr++) {
                const int gi = gi0 + rr * 8;
                float d0 = acc[mt][nt][2 * rr], d1 = acc[mt][nt][2 * rr + 1];
                if (MODE == 0) {
                    float sqi = g_sq[bz * Nn + gi];
                    float mi  = mask[bz * Nn + gi];
                    float out0, out1;
                    {
                        float d2 = sqi + g_sq[bz * Nn + gj] - 2.f * d0;
                        d2 = fmaxf(d2, 0.f);
                        float dd = (d2 > 1e-12f) ? sqrtf(d2) : 0.f;
                        out0 = dd * mi * mask[bz * Nn + gj];
                    }
                    {
                        float d2 = sqi + g_sq[bz * Nn + gj + 1] - 2.f * d1;
                        d2 = fmaxf(d2, 0.f);
                        float dd = (d2 > 1e-12f) ? sqrtf(d2) : 0.f;
                        out1 = dd * mi * mask[bz * Nn + gj + 1];
                    }
                    *(float2*)(g_D + ((size_t)bz * Nn + gi) * Nn + gj) =
                        make_float2(out0, out1);
                } else {
                    const float scale = 0.144337567297406441f;
                    const int b = bz >> 3;
                    float2 Dv = *(const float2*)(g_D + ((size_t)b * Nn + gi) * Nn + gj);
                    *(float2*)(g_att + ((size_t)bz * Nn + gi) * Nn + gj) =
                        make_float2(d0 * scale + Dv.x, d1 * scale + Dv.y);
                }
            }
        }
    }
}

// ============================================================================
// attnv: y[b,h,i,d] = sum_j P[b,h,i,j] * Vt[b,h,d,j]. 128m x 48n x 256k,
// 4 warps, 3-stage cp.async. Writes yh fp16 row-major [M][Hd].
// ============================================================================
#define AV_RS    40
#define AV_ABUF  (128 * AV_RS * 2)   /* 10240 */
#define AV_BBUF  (48 * AV_RS * 2)    /*  3840 */
#define AV_STAGE (AV_ABUF + AV_BBUF) /* 14080 */
#define AV_SMEM  (3 * AV_STAGE)      /* 42240 */

__global__ __launch_bounds__(128)
void attnv_h_kernel() {
    extern __shared__ char smem[];
    const uint32_t sb = smem_to_u32(smem);
    const int t = threadIdx.x, lane = t & 31, wid = t >> 5;
    const int bh = blockIdx.y, m0 = blockIdx.x * 128;
    const __half* A = g_atth + (size_t)bh * Nn * Nn;
    const __half* B = g_vth + (size_t)bh * DHd * Nn;
    const int mW = wid * 32;

    const int lq = lane >> 3, lr = lane & 7;
    const int aRow = (lq & 1) * 8 + lr, aCol = (lq >> 1) * 8;
    const int bRow = (lq >> 1) * 8 + lr, bCol = (lq & 1) * 8;
    const uint32_t aOff = (uint32_t)(((mW + aRow) * AV_RS + aCol) * 2);
    const uint32_t bOff = (uint32_t)(AV_ABUF + (bRow * AV_RS + bCol) * 2);

    float acc[2][6][4];
    #pragma unroll
    for (int i = 0; i < 2; i++)
        #pragma unroll
        for (int j = 0; j < 6; j++)
            #pragma unroll
            for (int r = 0; r < 4; r++) acc[i][j][r] = 0.f;

    auto issue = [&](int ch) {
        const uint32_t dstA = sb + (uint32_t)(ch % 3) * AV_STAGE;
        const uint32_t dstB = dstA + AV_ABUF;
        #pragma unroll
        for (int u = 0; u < 4; u++) {
            int p = t + u * 128, row = p >> 2, seg = p & 3;
            CP_ASYNC16(dstA + (uint32_t)((row * AV_RS + seg * 8) * 2),
                       A + (size_t)(m0 + row) * Nn + ch * 32 + seg * 8);
        }
        #pragma unroll
        for (int u = 0; u < 2; u++) {
            int p = t + u * 128;
            if (p < 192) {
                int row = p >> 2, seg = p & 3;
                CP_ASYNC16(dstB + (uint32_t)((row * AV_RS + seg * 8) * 2),
                           B + (size_t)row * Nn + ch * 32 + seg * 8);
            }
        }
        CP_COMMIT();
    };
    issue(0);
    issue(1);

    const int nch = Nn >> 5;  // 8
    for (int ch = 0; ch < nch; ch++) {
        if (ch + 1 < nch) { CP_WAIT1(); } else { CP_WAIT0(); }
        __syncthreads();
        const uint32_t base = sb + (uint32_t)(ch % 3) * AV_STAGE;
        #pragma unroll
        for (int ks = 0; ks < 2; ks++) {
            uint32_t a[2][4], b[3][4];
            #pragma unroll
            for (int mt = 0; mt < 2; mt++)
                LDSM4(a[mt], base + aOff + (uint32_t)((mt * 16 * AV_RS + ks * 16) * 2));
            #pragma unroll
            for (int g = 0; g < 3; g++)
                LDSM4(b[g], base + bOff + (uint32_t)((g * 16 * AV_RS + ks * 16) * 2));
            #pragma unroll
            for (int mt = 0; mt < 2; mt++)
                #pragma unroll
                for (int g = 0; g < 3; g++) {
                    MMA16816(acc[mt][2 * g],     a[mt], b[g][0], b[g][1]);
                    MMA16816(acc[mt][2 * g + 1], a[mt], b[g][2], b[g][3]);
                }
        }
        if (ch + 2 < nch) issue(ch + 2);
    }

    const int b = bh >> 3, h = bh & 7;
    const int rBase = m0 + mW + (lane >> 2);
    const int cBase = (lane & 3) * 2;
    #pragma unroll
    for (int mt = 0; mt < 2; mt++) {
        #pragma unroll
        for (int nt = 0; nt < 6; nt++) {
            const int c = cBase + nt * 8;
            const int gi = rBase + mt * 16;
            *(__half2*)(g_yh + ((size_t)b * Nn + gi) * Hd + h * DHd + c) =
                __floats2half2_rn(acc[mt][nt][0], acc[mt][nt][1]);
            *(__half2*)(g_yh + ((size_t)b * Nn + gi + 8) * Hd + h * DHd + c) =
                __floats2half2_rn(acc[mt][nt][2], acc[mt][nt][3]);
        }
    }
}

// ---------------- row squared norms of z ----------------
__global__ void sqnorm_kernel() {
    int r = blockIdx.x;
    float s = 0.f;
    for (int c = threadIdx.x; c < Hd; c += 128) {
        float v = g_z[(size_t)r * Hd + c];
        s += v * v;
    }
    s = blocksum128(s);
    if (threadIdx.x == 0) g_sq[r] = s;
}

// ---------------- bias: D = (rowmax - D) masked, diag 0 ----------------
__global__ void distbias_kernel(const float* __restrict__ mask) {
    int r = blockIdx.x;
    int b = r / Nn, i = r - b * Nn;
    float* p = g_D + (size_t)r * Nn;
    int t = threadIdx.x;
    float v  = p[t];
    float bm = blockmax256(v);
    float dm = mask[r] * mask[b * Nn + t];
    p[t] = (t == i) ? 0.f : (bm - v) * dm;
}

// ---------------- softmax: fp32 scores -> fp16 probs ----------------
__global__ void softmax_kernel() {
    const float* p = g_att + (size_t)blockIdx.x * Nn;
    __half* po = g_atth + (size_t)blockIdx.x * Nn;
    int t = threadIdx.x;
    float v  = p[t];
    float bm = blockmax256(v);
    float e  = __expf(v - bm);
    float s  = blocksum256(e);
    po[t] = __float2half(e / s);
}

// ---------------- out = LayerNorm(a + r), fp32 + fp16 shadow ----------------
__global__ void addln_kernel(const float* __restrict__ a, const float* __restrict__ r,
                             const float* __restrict__ g, const float* __restrict__ be,
                             float* __restrict__ out, __half* __restrict__ outh) {
    int row = blockIdx.x;
    int t = threadIdx.x;
    float vals[3];
    float s = 0.f;
    #pragma unroll
    for (int u = 0; u < 3; u++) {
        int c = t + u * 128;
        float v = a[(size_t)row * Hd + c] + r[(size_t)row * Hd + c];
        vals[u] = v;
        s += v;
    }
    float mu = blocksum128(s) * (1.f / Hd);
    float s2 = 0.f;
    #pragma unroll
    for (int u = 0; u < 3; u++) { float d = vals[u] - mu; s2 += d * d; }
    float var  = blocksum128(s2) * (1.f / Hd);
    float rstd = rsqrtf(var + 1e-5f);
    #pragma unroll
    for (int u = 0; u < 3; u++) {
        int c = t + u * 128;
        float o = (vals[u] - mu) * rstd * g[c] + be[c];
        out[(size_t)row * Hd + c]  = o;
        outh[(size_t)row * Hd + c] = __float2half(o);
    }
}

// ---------------- masked outputs ----------------
__global__ void out_x_kernel(const float* __restrict__ x, const float* __restrict__ mask,
                             float* __restrict__ out) {
    size_t idx = (size_t)blockIdx.x * blockDim.x + threadIdx.x;
    if (idx >= (size_t)Bn * Nn * XDim) return;
    out[idx] = x[idx] * mask[idx / XDim];
}
__global__ void out_e_kernel(const float* __restrict__ e, const float* __restrict__ mask,
                             float* __restrict__ out) {
    size_t idx = (size_t)blockIdx.x * blockDim.x + threadIdx.x;
    if (idx >= (size_t)Bn * Nn * Nn * EDim) return;
    size_t pair = idx / EDim;
    int j  = (int)(pair % Nn);
    size_t bi = pair / Nn;
    int b  = (int)(bi / Nn);
    out[idx] = e[idx] * mask[bi] * mask[(size_t)b * Nn + j];
}
__global__ void out_z_kernel(const float* __restrict__ mask, float* __restrict__ out) {
    size_t idx = (size_t)blockIdx.x * blockDim.x + threadIdx.x;
    if (idx >= (size_t)Mrows * Hd) return;
    out[idx] = g_z[idx] * mask[idx / Hd];
}

// ---------------- launcher ----------------
extern "C" void kernel_launch(void* const* d_in, const int* in_sizes, int n_in,
                              void* d_out, int out_size) {
    const float* x    = (const float*)d_in[0];
    const float* e    = (const float*)d_in[1];
    const float* mask = (const float*)d_in[2];
    const float* Wemb = (const float*)d_in[3];
    const float* Wq = (const float*)d_in[4];  const float* bq = (const float*)d_in[5];
    const float* Wk = (const float*)d_in[6];  const float* bk = (const float*)d_in[7];
    const float* Wv = (const float*)d_in[8];  const float* bv = (const float*)d_in[9];
    const float* Wo = (const float*)d_in[10]; const float* bo = (const float*)d_in[11];
    const float* g1 = (const float*)d_in[12]; const float* be1 = (const float*)d_in[13];
    const float* W1 = (const float*)d_in[14]; const float* b1  = (const float*)d_in[15];
    const float* W2 = (const float*)d_in[16]; const float* b2  = (const float*)d_in[17];
    const float* g2 = (const float*)d_in[18]; const float* be2 = (const float*)d_in[19];
    float* out = (float*)d_out;

    float  *z, *q, *x1;
    __half *cath, *zh, *x1h, *yh, *ffnh, *qhp, *khp, *vth;
    __half *wembTh, *wqTh, *wkTh, *wvTh, *woTh, *w1Th, *w2Th;
    cudaGetSymbolAddress((void**)&cath,  g_cath);
    cudaGetSymbolAddress((void**)&z,     g_z);
    cudaGetSymbolAddress((void**)&zh,    g_zh);
    cudaGetSymbolAddress((void**)&q,     g_q);
    cudaGetSymbolAddress((void**)&yh,    g_yh);
    cudaGetSymbolAddress((void**)&x1,    g_x1);
    cudaGetSymbolAddress((void**)&x1h,   g_x1h);
    cudaGetSymbolAddress((void**)&ffnh,  g_ffnh);
    cudaGetSymbolAddress((void**)&qhp,   g_qhp);
    cudaGetSymbolAddress((void**)&khp,   g_khp);
    cudaGetSymbolAddress((void**)&vth,   g_vth);
    cudaGetSymbolAddress((void**)&wembTh, g_wembTh);
    cudaGetSymbolAddress((void**)&wqTh,  g_wqTh);
    cudaGetSymbolAddress((void**)&wkTh,  g_wkTh);
    cudaGetSymbolAddress((void**)&wvTh,  g_wvTh);
    cudaGetSymbolAddress((void**)&woTh,  g_woTh);
    cudaGetSymbolAddress((void**)&w1Th,  g_w1Th);
    cudaGetSymbolAddress((void**)&w2Th,  g_w2Th);

    cudaFuncSetAttribute(gemm_h_kernel,
                         cudaFuncAttributeMaxDynamicSharedMemorySize, GK_SMEM_B);
    cudaFuncSetAttribute(gram_kernel<0>,
                         cudaFuncAttributeMaxDynamicSharedMemorySize, GK_SMEM_B);
    cudaFuncSetAttribute(gram_kernel<1>,
                         cudaFuncAttributeMaxDynamicSharedMemorySize, GK_SMEM_B);
    cudaFuncSetAttribute(attnv_h_kernel,
                         cudaFuncAttributeMaxDynamicSharedMemorySize, AV_SMEM);

    dim3 tb(32, 8);
    {
        size_t tot = (size_t)Mrows * KPAD;
        cat_kernel<<<(unsigned)((tot + 255) / 256), 256>>>(x, e);                    // 1
    }
    transpose_kernel<<<dim3(12, 44, 1), tb>>>(Wemb, wembTh, KCAT, Hd, KPAD, 0, 0);   // 2
    transpose_kernel<<<dim3(12, 12, DEPTH), tb>>>(Wq, wqTh, Hd, Hd, Hd,
                                                  (size_t)Hd * Hd, (size_t)Hd * Hd); // 3
    transpose_kernel<<<dim3(12, 12, DEPTH), tb>>>(Wk, wkTh, Hd, Hd, Hd,
                                                  (size_t)Hd * Hd, (size_t)Hd * Hd); // 4
    transpose_kernel<<<dim3(12, 12, DEPTH), tb>>>(Wv, wvTh, Hd, Hd, Hd,
                                                  (size_t)Hd * Hd, (size_t)Hd * Hd); // 5
    gemm_h_kernel<<<dim3(Hd / 128, Mrows / 128), 256, GK_SMEM_B>>>(                  // 6
        cath, KPAD, wembTh, KPAD, nullptr, z, zh, Hd, KPAD, 0, 0);
    transpose_kernel<<<dim3(12, 12, DEPTH), tb>>>(Wo, woTh, Hd, Hd, Hd,
                                                  (size_t)Hd * Hd, (size_t)Hd * Hd);
    transpose_kernel<<<dim3(48, 12, DEPTH), tb>>>(W1, w1Th, Hd, DFFd, Hd,
                                                  (size_t)Hd * DFFd, (size_t)DFFd * Hd);
    transpose_kernel<<<dim3(12, 48, DEPTH), tb>>>(W2, w2Th, DFFd, Hd, DFFd,
                                                  (size_t)DFFd * Hd, (size_t)Hd * DFFd);

    for (int l = 0; l < DEPTH; l++) {
        const size_t wofs  = (size_t)l * Hd * Hd;
        const size_t w1ofs = (size_t)l * DFFd * Hd;
        // distance bias (tensor gram on zh)
        sqnorm_kernel<<<Mrows, 128>>>();
        gram_kernel<0><<<dim3(2, 2, Bn), 256, GK_SMEM_B>>>(zh, zh, mask);
        distbias_kernel<<<Mrows, 256>>>(mask);
        // QKV into per-head fp16 layouts
        gemm_h_kernel<<<dim3(Hd / 128, Mrows / 128), 256, GK_SMEM_B>>>(
            zh, Hd, wqTh + wofs, Hd, bq + (size_t)l * Hd, nullptr, qhp, Hd, Hd, 0, 1);
        gemm_h_kernel<<<dim3(Hd / 128, Mrows / 128), 256, GK_SMEM_B>>>(
            zh, Hd, wkTh + wofs, Hd, bk + (size_t)l * Hd, nullptr, khp, Hd, Hd, 0, 1);
        gemm_h_kernel<<<dim3(Hd / 128, Mrows / 128), 256, GK_SMEM_B>>>(
            zh, Hd, wvTh + wofs, Hd, bv + (size_t)l * Hd, nullptr, vth, Hd, Hd, 0, 2);
        // attention (all tensor)
        gram_kernel<1><<<dim3(2, 2, Bn * NHd), 256, GK_SMEM_B>>>(qhp, khp, mask);
        softmax_kernel<<<Bn * NHd * Nn, 256>>>();
        attnv_h_kernel<<<dim3(2, Bn * NHd), 128, AV_SMEM>>>();
        // output projection + AddNorm
        gemm_h_kernel<<<dim3(Hd / 128, Mrows / 128), 256, GK_SMEM_B>>>(
            yh, Hd, woTh + wofs, Hd, bo + (size_t)l * Hd, q, nullptr, Hd, Hd, 0, 0);
        addln_kernel<<<Mrows, 128>>>(z, q, g1 + (size_t)l * Hd, be1 + (size_t)l * Hd,
                                     x1, x1h);
        // FFN
        gemm_h_kernel<<<dim3(DFFd / 128, Mrows / 128), 256, GK_SMEM_B>>>(
            x1h, Hd, w1Th + w1ofs, Hd, b1 + (size_t)l * DFFd,
            nullptr, ffnh, DFFd, Hd, 1, 0);
        gemm_h_kernel<<<dim3(Hd / 128, Mrows / 128), 256, GK_SMEM_B>>>(
            ffnh, DFFd, w2Th + w1ofs, DFFd, b2 + (size_t)l * Hd,
            q, nullptr, Hd, DFFd, 0, 0);
        addln_kernel<<<Mrows, 128>>>(x1, q, g2 + (size_t)l * Hd, be2 + (size_t)l * Hd,
                                     z, zh);
    }

    // outputs: [X_out | E_out | z_out]
    const size_t XTOT = (size_t)Bn * Nn * XDim;
    const size_t ETOT = (size_t)Bn * Nn * Nn * EDim;
    const size_t ZTOT = (size_t)Mrows * Hd;
    out_x_kernel<<<(unsigned)((XTOT + 255) / 256), 256>>>(x, mask, out);
    out_e_kernel<<<(unsigned)((ETOT + 255) / 256), 256>>>(e, mask, out + XTOT);
    out_z_kernel<<<(unsigned)((ZTOT + 255) / 256), 256>>>(mask, out + XTOT + ETOT);
    (void)in_sizes; (void)n_in; (void)out_size;
}

// round 9
// speedup vs baseline: 8.2296x; 1.4044x over previous
#include <cuda_runtime.h>
#include <cuda_fp16.h>
#include <math.h>
#include <stdint.h>

#define Bn    64
#define Nn    256
#define XDim  118
#define EDim  5
#define Hd    384
#define NHd   8
#define DHd   48
#define DFFd  1536
#define DEPTH 6
#define Mrows (Bn * Nn)            /* 16384 */
#define KCAT  (XDim + Nn * EDim)   /* 1398  */
#define KPAD  1408
#define EROW  (Nn * EDim)

// ---------------- scratch (device globals; zero-init, no allocation) ----------------
__device__ __half g_cath[(size_t)Mrows * KPAD];
__device__ float  g_z  [(size_t)Mrows * Hd];
__device__ __half g_zh [(size_t)Mrows * Hd];
__device__ float  g_q  [(size_t)Mrows * Hd];
__device__ __half g_yh [(size_t)Mrows * Hd];
__device__ float  g_x1 [(size_t)Mrows * Hd];
__device__ __half g_x1h[(size_t)Mrows * Hd];
__device__ __half g_ffnh[(size_t)Mrows * DFFd];
__device__ __half g_atth[(size_t)Bn * NHd * Nn * Nn];  // fp16 probs
__device__ float  g_D  [(size_t)Bn * Nn * Nn];
__device__ float  g_sq [Mrows];
// per-head padded Q/K: [b,h,256,64] (cols 48..63 stay zero)
__device__ __half g_qhp[(size_t)Bn * NHd * Nn * 64];
__device__ __half g_khp[(size_t)Bn * NHd * Nn * 64];
// per-head transposed V: [b,h,48,256]
__device__ __half g_vth[(size_t)Bn * NHd * DHd * Nn];
// transposed fp16 weights [N][K]
__device__ __half g_wembTh[(size_t)Hd * KPAD];
__device__ __half g_wqTh [(size_t)DEPTH * Hd * Hd];
__device__ __half g_wkTh [(size_t)DEPTH * Hd * Hd];
__device__ __half g_wvTh [(size_t)DEPTH * Hd * Hd];
__device__ __half g_woTh [(size_t)DEPTH * Hd * Hd];
__device__ __half g_w1Th [(size_t)DEPTH * DFFd * Hd];
__device__ __half g_w2Th [(size_t)DEPTH * Hd * DFFd];

// ---------------- PTX helpers (sm_80+ base ISA) ----------------
__device__ __forceinline__ uint32_t smem_to_u32(const void* p) {
    uint32_t a;
    asm("{ .reg .u64 t; cvta.to.shared.u64 t, %1; cvt.u32.u64 %0, t; }"
        : "=r"(a) : "l"(p));
    return a;
}
#define CP_ASYNC16(dst, src) \
    asm volatile("cp.async.cg.shared.global [%0], [%1], 16;" \
                 :: "r"(dst), "l"(src) : "memory")
#define CP_COMMIT() asm volatile("cp.async.commit_group;" ::: "memory")
#define CP_WAIT1()  asm volatile("cp.async.wait_group 1;" ::: "memory")
#define CP_WAIT0()  asm volatile("cp.async.wait_group 0;" ::: "memory")
#define LDSM4(r, addr) \
    asm volatile("ldmatrix.sync.aligned.m8n8.x4.shared.b16 {%0,%1,%2,%3}, [%4];" \
                 : "=r"((r)[0]), "=r"((r)[1]), "=r"((r)[2]), "=r"((r)[3]) \
                 : "r"(addr))
#define MMA16816(d, a, b0_, b1_) \
    asm volatile("mma.sync.aligned.m16n8k16.row.col.f32.f16.f16.f32 " \
                 "{%0,%1,%2,%3}, {%4,%5,%6,%7}, {%8,%9}, {%0,%1,%2,%3};" \
                 : "+f"((d)[0]), "+f"((d)[1]), "+f"((d)[2]), "+f"((d)[3]) \
                 : "r"((a)[0]), "r"((a)[1]), "r"((a)[2]), "r"((a)[3]), \
                   "r"(b0_), "r"(b1_))

// ---------------- reductions ----------------
__device__ __forceinline__ float blockmax256(float v) {
    __shared__ float red[8];
    #pragma unroll
    for (int o = 16; o > 0; o >>= 1) v = fmaxf(v, __shfl_xor_sync(0xffffffffu, v, o));
    if ((threadIdx.x & 31) == 0) red[threadIdx.x >> 5] = v;
    __syncthreads();
    float m = red[0];
    #pragma unroll
    for (int i = 1; i < 8; i++) m = fmaxf(m, red[i]);
    __syncthreads();
    return m;
}
__device__ __forceinline__ float blocksum128(float v) {
    __shared__ float red[4];
    #pragma unroll
    for (int o = 16; o > 0; o >>= 1) v += __shfl_xor_sync(0xffffffffu, v, o);
    if ((threadIdx.x & 31) == 0) red[threadIdx.x >> 5] = v;
    __syncthreads();
    float s = red[0] + red[1] + red[2] + red[3];
    __syncthreads();
    return s;
}

// ---------------- concat [x | e_flat | 0-pad] -> fp16 ----------------
__global__ void cat_kernel(const float* __restrict__ x, const float* __restrict__ e) {
    size_t idx = (size_t)blockIdx.x * blockDim.x + threadIdx.x;
    if (idx >= (size_t)Mrows * KPAD) return;
    size_t r = idx / KPAD;
    int    c = (int)(idx - r * KPAD);
    float v;
    if (c < XDim)      v = x[r * XDim + c];
    else if (c < KCAT) v = e[r * (size_t)EROW + (c - XDim)];
    else               v = 0.f;
    g_cath[idx] = __float2half(v);
}

// ---------------- transpose fp32 -> fp16 ----------------
__global__ void transpose_kernel(const float* __restrict__ in, __half* __restrict__ out,
                                 int R, int C, int outLd,
                                 size_t inStride, size_t outStride) {
    __shared__ float tile[32][33];
    const float* ip = in + (size_t)blockIdx.z * inStride;
    __half* op = out + (size_t)blockIdx.z * outStride;
    int c0 = blockIdx.x * 32, r0 = blockIdx.y * 32;
    int tx = threadIdx.x, ty = threadIdx.y;
    #pragma unroll
    for (int i = 0; i < 32; i += 8) {
        int r = r0 + ty + i, c = c0 + tx;
        tile[ty + i][tx] = (r < R && c < C) ? ip[(size_t)r * C + c] : 0.f;
    }
    __syncthreads();
    #pragma unroll
    for (int i = 0; i < 32; i += 8) {
        int oc = c0 + ty + i, orow = r0 + tx;
        if (oc < C && orow < outLd)
            op[(size_t)oc * outLd + orow] = __float2half(tile[tx][ty + i]);
    }
}

// ============================================================================
// fp16 HMMA GEMM, 128x128x32 tiles, 8 warps, 3-stage cp.async.
// mode 0: C fp32 (+Ch fp16);  mode 1: Ch = padded-head QK;  mode 2: Ch = V^T head.
// ============================================================================
#define GK_RS      40
#define GK_OPB     (128 * GK_RS * 2)
#define GK_STAGE_B (2 * GK_OPB)
#define GK_SMEM_B  (3 * GK_STAGE_B)

__global__ __launch_bounds__(256)
void gemm_h_kernel(const __half* __restrict__ A, int lda,
                   const __half* __restrict__ BT, int ldb,
                   const float* __restrict__ bias,
                   float* __restrict__ C, __half* __restrict__ Ch,
                   int ldc, int K, int relu, int mode) {
    extern __shared__ char smem[];
    const uint32_t sb = smem_to_u32(smem);
    const int t = threadIdx.x, lane = t & 31, wid = t >> 5;
    const int m0 = blockIdx.y * 128, n0 = blockIdx.x * 128;
    const int mW = (wid & 3) * 32, nW = (wid >> 2) * 64;

    const int r0 = t >> 2,          q0 = t & 3;
    const int r1 = (t + 256) >> 2,  q1 = (t + 256) & 3;
    const int lq = lane >> 3, lr = lane & 7;
    const int aRow = (lq & 1) * 8 + lr, aCol = (lq >> 1) * 8;
    const int bRow = (lq >> 1) * 8 + lr, bCol = (lq & 1) * 8;
    const uint32_t aOff = (uint32_t)(((mW + aRow) * GK_RS + aCol) * 2);
    const uint32_t bOff = (uint32_t)(GK_OPB + ((nW + bRow) * GK_RS + bCol) * 2);

    float acc[2][8][4];
    #pragma unroll
    for (int i = 0; i < 2; i++)
        #pragma unroll
        for (int j = 0; j < 8; j++)
            #pragma unroll
            for (int r = 0; r < 4; r++) acc[i][j][r] = 0.f;

    const int nch = K >> 5;
    auto issue = [&](int ch) {
        const uint32_t dstA = sb + (uint32_t)(ch % 3) * GK_STAGE_B;
        const uint32_t dstB = dstA + GK_OPB;
        const __half* sa  = A  + (size_t)m0 * lda + ch * 32;
        const __half* sbp = BT + (size_t)n0 * ldb + ch * 32;
        CP_ASYNC16(dstA + (uint32_t)((r0 * GK_RS + q0 * 8) * 2), sa  + (size_t)r0 * lda + q0 * 8);
        CP_ASYNC16(dstA + (uint32_t)((r1 * GK_RS + q1 * 8) * 2), sa  + (size_t)r1 * lda + q1 * 8);
        CP_ASYNC16(dstB + (uint32_t)((r0 * GK_RS + q0 * 8) * 2), sbp + (size_t)r0 * ldb + q0 * 8);
        CP_ASYNC16(dstB + (uint32_t)((r1 * GK_RS + q1 * 8) * 2), sbp + (size_t)r1 * ldb + q1 * 8);
        CP_COMMIT();
    };
    issue(0);
    issue(1);

    for (int ch = 0; ch < nch; ch++) {
        if (ch + 1 < nch) { CP_WAIT1(); } else { CP_WAIT0(); }
        __syncthreads();
        const uint32_t base = sb + (uint32_t)(ch % 3) * GK_STAGE_B;
        #pragma unroll
        for (int ks = 0; ks < 2; ks++) {
            uint32_t a[2][4], b[4][4];
            #pragma unroll
            for (int mt = 0; mt < 2; mt++)
                LDSM4(a[mt], base + aOff + (uint32_t)((mt * 16 * GK_RS + ks * 16) * 2));
            #pragma unroll
            for (int g = 0; g < 4; g++)
                LDSM4(b[g], base + bOff + (uint32_t)((g * 16 * GK_RS + ks * 16) * 2));
            #pragma unroll
            for (int mt = 0; mt < 2; mt++)
                #pragma unroll
                for (int g = 0; g < 4; g++) {
                    MMA16816(acc[mt][2 * g],     a[mt], b[g][0], b[g][1]);
                    MMA16816(acc[mt][2 * g + 1], a[mt], b[g][2], b[g][3]);
                }
        }
        if (ch + 2 < nch) issue(ch + 2);
    }

    const int rBase = m0 + mW + (lane >> 2);
    const int cBase = n0 + nW + (lane & 3) * 2;
    #pragma unroll
    for (int mt = 0; mt < 2; mt++) {
        #pragma unroll
        for (int nt = 0; nt < 8; nt++) {
            const int c = cBase + nt * 8;
            float b0 = 0.f, b1 = 0.f;
            if (bias) { b0 = bias[c]; b1 = bias[c + 1]; }
            float v00 = acc[mt][nt][0] + b0, v01 = acc[mt][nt][1] + b1;
            float v10 = acc[mt][nt][2] + b0, v11 = acc[mt][nt][3] + b1;
            if (relu) {
                v00 = fmaxf(v00, 0.f); v01 = fmaxf(v01, 0.f);
                v10 = fmaxf(v10, 0.f); v11 = fmaxf(v11, 0.f);
            }
            const int rA = rBase + mt * 16, rB = rA + 8;
            if (mode == 0) {
                if (C) {
                    *(float2*)(C + (size_t)rA * ldc + c) = make_float2(v00, v01);
                    *(float2*)(C + (size_t)rB * ldc + c) = make_float2(v10, v11);
                }
                if (Ch) {
                    *(__half2*)(Ch + (size_t)rA * ldc + c) = __floats2half2_rn(v00, v01);
                    *(__half2*)(Ch + (size_t)rB * ldc + c) = __floats2half2_rn(v10, v11);
                }
            } else {
                const int h = c / DHd, d = c - h * DHd;
                const int bIdx = rA >> 8;
                if (mode == 1) {
                    size_t p0 = ((((size_t)bIdx * NHd + h) << 8) | (rA & 255)) * 64 + d;
                    size_t p1 = ((((size_t)bIdx * NHd + h) << 8) | (rB & 255)) * 64 + d;
                    *(__half2*)(Ch + p0) = __floats2half2_rn(v00, v01);
                    *(__half2*)(Ch + p1) = __floats2half2_rn(v10, v11);
                } else {
                    size_t hb = ((size_t)bIdx * NHd + h) * DHd;
                    Ch[(hb + d)     * Nn + (rA & 255)] = __float2half(v00);
                    Ch[(hb + d + 1) * Nn + (rA & 255)] = __float2half(v01);
                    Ch[(hb + d)     * Nn + (rB & 255)] = __float2half(v10);
                    Ch[(hb + d + 1) * Nn + (rB & 255)] = __float2half(v11);
                }
            }
        }
    }
}

// ============================================================================
// distg: per-batch gram of zh (K=384), sqrt/mask epilogue -> g_D
// ============================================================================
__global__ __launch_bounds__(256)
void distg_kernel(const __half* __restrict__ Z, const float* __restrict__ mask) {
    extern __shared__ char smem[];
    const uint32_t sb = smem_to_u32(smem);
    const int t = threadIdx.x, lane = t & 31, wid = t >> 5;
    const int bz = blockIdx.z;
    const int m0 = blockIdx.y * 128, n0 = blockIdx.x * 128;
    const int mW = (wid & 3) * 32, nW = (wid >> 2) * 64;
    const __half* A = Z + (size_t)bz * Nn * Hd;

    const int r0 = t >> 2,          q0 = t & 3;
    const int r1 = (t + 256) >> 2,  q1 = (t + 256) & 3;
    const int lq = lane >> 3, lr = lane & 7;
    const int aRow = (lq & 1) * 8 + lr, aCol = (lq >> 1) * 8;
    const int bRow = (lq >> 1) * 8 + lr, bCol = (lq & 1) * 8;
    const uint32_t aOff = (uint32_t)(((mW + aRow) * GK_RS + aCol) * 2);
    const uint32_t bOff = (uint32_t)(GK_OPB + ((nW + bRow) * GK_RS + bCol) * 2);

    float acc[2][8][4];
    #pragma unroll
    for (int i = 0; i < 2; i++)
        #pragma unroll
        for (int j = 0; j < 8; j++)
            #pragma unroll
            for (int r = 0; r < 4; r++) acc[i][j][r] = 0.f;

    const int nch = Hd >> 5;  // 12
    auto issue = [&](int ch) {
        const uint32_t dstA = sb + (uint32_t)(ch % 3) * GK_STAGE_B;
        const uint32_t dstB = dstA + GK_OPB;
        const __half* sa  = A + (size_t)m0 * Hd + ch * 32;
        const __half* sbp = A + (size_t)n0 * Hd + ch * 32;
        CP_ASYNC16(dstA + (uint32_t)((r0 * GK_RS + q0 * 8) * 2), sa  + (size_t)r0 * Hd + q0 * 8);
        CP_ASYNC16(dstA + (uint32_t)((r1 * GK_RS + q1 * 8) * 2), sa  + (size_t)r1 * Hd + q1 * 8);
        CP_ASYNC16(dstB + (uint32_t)((r0 * GK_RS + q0 * 8) * 2), sbp + (size_t)r0 * Hd + q0 * 8);
        CP_ASYNC16(dstB + (uint32_t)((r1 * GK_RS + q1 * 8) * 2), sbp + (size_t)r1 * Hd + q1 * 8);
        CP_COMMIT();
    };
    issue(0);
    issue(1);

    for (int ch = 0; ch < nch; ch++) {
        if (ch + 1 < nch) { CP_WAIT1(); } else { CP_WAIT0(); }
        __syncthreads();
        const uint32_t base = sb + (uint32_t)(ch % 3) * GK_STAGE_B;
        #pragma unroll
        for (int ks = 0; ks < 2; ks++) {
            uint32_t a[2][4], b[4][4];
            #pragma unroll
            for (int mt = 0; mt < 2; mt++)
                LDSM4(a[mt], base + aOff + (uint32_t)((mt * 16 * GK_RS + ks * 16) * 2));
            #pragma unroll
            for (int g = 0; g < 4; g++)
                LDSM4(b[g], base + bOff + (uint32_t)((g * 16 * GK_RS + ks * 16) * 2));
            #pragma unroll
            for (int mt = 0; mt < 2; mt++)
                #pragma unroll
                for (int g = 0; g < 4; g++) {
                    MMA16816(acc[mt][2 * g],     a[mt], b[g][0], b[g][1]);
                    MMA16816(acc[mt][2 * g + 1], a[mt], b[g][2], b[g][3]);
                }
        }
        if (ch + 2 < nch) issue(ch + 2);
    }

    const int rBase = m0 + mW + (lane >> 2);
    const int cBase = n0 + nW + (lane & 3) * 2;
    #pragma unroll
    for (int mt = 0; mt < 2; mt++) {
        const int gi0 = rBase + mt * 16;
        #pragma unroll
        for (int nt = 0; nt < 8; nt++) {
            const int gj = cBase + nt * 8;
            #pragma unroll
            for (int rr = 0; rr < 2; rr++) {
                const int gi = gi0 + rr * 8;
                float d0 = acc[mt][nt][2 * rr], d1 = acc[mt][nt][2 * rr + 1];
                float sqi = g_sq[bz * Nn + gi];
                float mi  = mask[bz * Nn + gi];
                float o0, o1;
                {
                    float d2 = fmaxf(sqi + g_sq[bz * Nn + gj] - 2.f * d0, 0.f);
                    float dd = (d2 > 1e-12f) ? sqrtf(d2) : 0.f;
                    o0 = dd * mi * mask[bz * Nn + gj];
                }
                {
                    float d2 = fmaxf(sqi + g_sq[bz * Nn + gj + 1] - 2.f * d1, 0.f);
                    float dd = (d2 > 1e-12f) ? sqrtf(d2) : 0.f;
                    o1 = dd * mi * mask[bz * Nn + gj + 1];
                }
                *(float2*)(g_D + ((size_t)bz * Nn + gi) * Nn + gj) = make_float2(o0, o1);
            }
        }
    }
}

// ============================================================================
// qksm: fused QK^T + D-bias + softmax -> fp16 probs.
// Tile 64m x 256n (full row), K=64, 8 warps (4m x 2n), warp tile 16x128.
// ============================================================================
#define QS_ARS   72                       /* halves per smem row */
#define QS_ABUF  (64 * QS_ARS * 2)        /*  9216 */
#define QS_BBUF  (256 * QS_ARS * 2)       /* 36864 */
#define QS_RED   (QS_ABUF + QS_BBUF)
#define QS_SMEM  (QS_RED + 2 * 128 * 4)   /* + rmax[128], rsum[128] */

__global__ __launch_bounds__(256)
void qksm_kernel(const __half* __restrict__ qhp, const __half* __restrict__ khp,
                 const float* __restrict__ mask) {
    extern __shared__ char smem[];
    const uint32_t sb = smem_to_u32(smem);
    float* rmax = (float*)(smem + QS_RED);
    float* rsum = rmax + 128;
    const int t = threadIdx.x, lane = t & 31, wid = t >> 5;
    const int bh = blockIdx.y, m0 = blockIdx.x * 64;
    const int b = bh >> 3;
    const __half* A = qhp + (size_t)bh * Nn * 64 + (size_t)m0 * 64;
    const __half* B = khp + (size_t)bh * Nn * 64;
    const int mW = (wid & 3) * 16, nW = (wid >> 2) * 128;

    // stage A (64x64) + B (256x64), row stride 72 halves
    #pragma unroll
    for (int u = 0; u < 2; u++) {
        int p = t + u * 256, row = p >> 3, seg = p & 7;
        CP_ASYNC16(sb + (uint32_t)((row * QS_ARS + seg * 8) * 2),
                   A + (size_t)row * 64 + seg * 8);
    }
    #pragma unroll
    for (int u = 0; u < 8; u++) {
        int p = t + u * 256, row = p >> 3, seg = p & 7;
        CP_ASYNC16(sb + (uint32_t)(QS_ABUF + (row * QS_ARS + seg * 8) * 2),
                   B + (size_t)row * 64 + seg * 8);
    }
    CP_COMMIT();
    CP_WAIT0();
    __syncthreads();

    const int lq = lane >> 3, lr = lane & 7;
    const int aRow = (lq & 1) * 8 + lr, aCol = (lq >> 1) * 8;
    const int bRow = (lq >> 1) * 8 + lr, bCol = (lq & 1) * 8;
    const uint32_t aOff = sb + (uint32_t)(((mW + aRow) * QS_ARS + aCol) * 2);
    const uint32_t bOff = sb + (uint32_t)(QS_ABUF + ((nW + bRow) * QS_ARS + bCol) * 2);

    float acc[16][4];
    #pragma unroll
    for (int j = 0; j < 16; j++)
        #pragma unroll
        for (int r = 0; r < 4; r++) acc[j][r] = 0.f;

    #pragma unroll
    for (int ks = 0; ks < 4; ks++) {
        uint32_t a[4];
        LDSM4(a, aOff + (uint32_t)(ks * 16 * 2));
        #pragma unroll
        for (int g = 0; g < 8; g++) {
            uint32_t bf[4];
            LDSM4(bf, bOff + (uint32_t)((g * 16 * QS_ARS + ks * 16) * 2));
            MMA16816(acc[2 * g],     a, bf[0], bf[1]);
            MMA16816(acc[2 * g + 1], a, bf[2], bf[3]);
        }
    }

    // epilogue: score = acc*scale + D ; softmax over 256 cols ; write fp16
    const float scale = 0.144337567297406441f;
    const int rloc0 = mW + (lane >> 2), rloc1 = rloc0 + 8;
    const int gi0 = m0 + rloc0, gi1 = m0 + rloc1;
    const int cB = nW + (lane & 3) * 2;
    #pragma unroll
    for (int nt = 0; nt < 16; nt++) {
        const int gj = cB + nt * 8;
        float2 d0 = *(const float2*)(g_D + ((size_t)b * Nn + gi0) * Nn + gj);
        float2 d1 = *(const float2*)(g_D + ((size_t)b * Nn + gi1) * Nn + gj);
        acc[nt][0] = acc[nt][0] * scale + d0.x;
        acc[nt][1] = acc[nt][1] * scale + d0.y;
        acc[nt][2] = acc[nt][2] * scale + d1.x;
        acc[nt][3] = acc[nt][3] * scale + d1.y;
    }
    float mx0 = -1e30f, mx1 = -1e30f;
    #pragma unroll
    for (int nt = 0; nt < 16; nt++) {
        mx0 = fmaxf(mx0, fmaxf(acc[nt][0], acc[nt][1]));
        mx1 = fmaxf(mx1, fmaxf(acc[nt][2], acc[nt][3]));
    }
    #pragma unroll
    for (int o = 1; o < 4; o <<= 1) {
        mx0 = fmaxf(mx0, __shfl_xor_sync(0xffffffffu, mx0, o));
        mx1 = fmaxf(mx1, __shfl_xor_sync(0xffffffffu, mx1, o));
    }
    const int nw = wid >> 2;
    rmax[nw * 64 + rloc0] = mx0;
    rmax[nw * 64 + rloc1] = mx1;
    __syncthreads();
    const float M0 = fmaxf(rmax[rloc0], rmax[64 + rloc0]);
    const float M1 = fmaxf(rmax[rloc1], rmax[64 + rloc1]);
    float s0 = 0.f, s1 = 0.f;
    #pragma unroll
    for (int nt = 0; nt < 16; nt++) {
        acc[nt][0] = __expf(acc[nt][0] - M0);
        acc[nt][1] = __expf(acc[nt][1] - M0);
        acc[nt][2] = __expf(acc[nt][2] - M1);
        acc[nt][3] = __expf(acc[nt][3] - M1);
        s0 += acc[nt][0] + acc[nt][1];
        s1 += acc[nt][2] + acc[nt][3];
    }
    #pragma unroll
    for (int o = 1; o < 4; o <<= 1) {
        s0 += __shfl_xor_sync(0xffffffffu, s0, o);
        s1 += __shfl_xor_sync(0xffffffffu, s1, o);
    }
    rsum[nw * 64 + rloc0] = s0;
    rsum[nw * 64 + rloc1] = s1;
    __syncthreads();
    const float inv0 = 1.f / (rsum[rloc0] + rsum[64 + rloc0]);
    const float inv1 = 1.f / (rsum[rloc1] + rsum[64 + rloc1]);
    __half* outp = g_atth + (size_t)bh * Nn * Nn;
    #pragma unroll
    for (int nt = 0; nt < 16; nt++) {
        const int gj = cB + nt * 8;
        *(__half2*)(outp + (size_t)gi0 * Nn + gj) =
            __floats2half2_rn(acc[nt][0] * inv0, acc[nt][1] * inv0);
        *(__half2*)(outp + (size_t)gi1 * Nn + gj) =
            __floats2half2_rn(acc[nt][2] * inv1, acc[nt][3] * inv1);
    }
}

// ============================================================================
// attnv: y = P @ V^T per head. 128m x 48n x 256k, 4 warps, 3-stage cp.async.
// ============================================================================
#define AV_RS    40
#define AV_ABUF  (128 * AV_RS * 2)
#define AV_BBUF  (48 * AV_RS * 2)
#define AV_STAGE (AV_ABUF + AV_BBUF)
#define AV_SMEM  (3 * AV_STAGE)

__global__ __launch_bounds__(128)
void attnv_h_kernel() {
    extern __shared__ char smem[];
    const uint32_t sb = smem_to_u32(smem);
    const int t = threadIdx.x, lane = t & 31, wid = t >> 5;
    const int bh = blockIdx.y, m0 = blockIdx.x * 128;
    const __half* A = g_atth + (size_t)bh * Nn * Nn;
    const __half* B = g_vth + (size_t)bh * DHd * Nn;
    const int mW = wid * 32;

    const int lq = lane >> 3, lr = lane & 7;
    const int aRow = (lq & 1) * 8 + lr, aCol = (lq >> 1) * 8;
    const int bRow = (lq >> 1) * 8 + lr, bCol = (lq & 1) * 8;
    const uint32_t aOff = (uint32_t)(((mW + aRow) * AV_RS + aCol) * 2);
    const uint32_t bOff = (uint32_t)(AV_ABUF + (bRow * AV_RS + bCol) * 2);

    float acc[2][6][4];
    #pragma unroll
    for (int i = 0; i < 2; i++)
        #pragma unroll
        for (int j = 0; j < 6; j++)
            #pragma unroll
            for (int r = 0; r < 4; r++) acc[i][j][r] = 0.f;

    auto issue = [&](int ch) {
        const uint32_t dstA = sb + (uint32_t)(ch % 3) * AV_STAGE;
        const uint32_t dstB = dstA + AV_ABUF;
        #pragma unroll
        for (int u = 0; u < 4; u++) {
            int p = t + u * 128, row = p >> 2, seg = p & 3;
            CP_ASYNC16(dstA + (uint32_t)((row * AV_RS + seg * 8) * 2),
                       A + (size_t)(m0 + row) * Nn + ch * 32 + seg * 8);
        }
        #pragma unroll
        for (int u = 0; u < 2; u++) {
            int p = t + u * 128;
            if (p < 192) {
                int row = p >> 2, seg = p & 3;
                CP_ASYNC16(dstB + (uint32_t)((row * AV_RS + seg * 8) * 2),
                           B + (size_t)row * Nn + ch * 32 + seg * 8);
            }
        }
        CP_COMMIT();
    };
    issue(0);
    issue(1);

    const int nch = Nn >> 5;
    for (int ch = 0; ch < nch; ch++) {
        if (ch + 1 < nch) { CP_WAIT1(); } else { CP_WAIT0(); }
        __syncthreads();
        const uint32_t base = sb + (uint32_t)(ch % 3) * AV_STAGE;
        #pragma unroll
        for (int ks = 0; ks < 2; ks++) {
            uint32_t a[2][4], b[3][4];
            #pragma unroll
            for (int mt = 0; mt < 2; mt++)
                LDSM4(a[mt], base + aOff + (uint32_t)((mt * 16 * AV_RS + ks * 16) * 2));
            #pragma unroll
            for (int g = 0; g < 3; g++)
                LDSM4(b[g], base + bOff + (uint32_t)((g * 16 * AV_RS + ks * 16) * 2));
            #pragma unroll
            for (int mt = 0; mt < 2; mt++)
                #pragma unroll
                for (int g = 0; g < 3; g++) {
                    MMA16816(acc[mt][2 * g],     a[mt], b[g][0], b[g][1]);
                    MMA16816(acc[mt][2 * g + 1], a[mt], b[g][2], b[g][3]);
                }
        }
        if (ch + 2 < nch) issue(ch + 2);
    }

    const int b = bh >> 3, h = bh & 7;
    const int rBase = m0 + mW + (lane >> 2);
    const int cBase = (lane & 3) * 2;
    #pragma unroll
    for (int mt = 0; mt < 2; mt++) {
        #pragma unroll
        for (int nt = 0; nt < 6; nt++) {
            const int c = cBase + nt * 8;
            const int gi = rBase + mt * 16;
            *(__half2*)(g_yh + ((size_t)b * Nn + gi) * Hd + h * DHd + c) =
                __floats2half2_rn(acc[mt][nt][0], acc[mt][nt][1]);
            *(__half2*)(g_yh + ((size_t)b * Nn + gi + 8) * Hd + h * DHd + c) =
                __floats2half2_rn(acc[mt][nt][2], acc[mt][nt][3]);
        }
    }
}

// ---------------- row squared norms of z (only needed post-embed) ----------------
__global__ void sqnorm_kernel() {
    int r = blockIdx.x;
    float s = 0.f;
    for (int c = threadIdx.x; c < Hd; c += 128) {
        float v = g_z[(size_t)r * Hd + c];
        s += v * v;
    }
    s = blocksum128(s);
    if (threadIdx.x == 0) g_sq[r] = s;
}

// ---------------- bias: D = (rowmax - D) masked, diag 0 ----------------
__global__ void distbias_kernel(const float* __restrict__ mask) {
    int r = blockIdx.x;
    int b = r / Nn, i = r - b * Nn;
    float* p = g_D + (size_t)r * Nn;
    int t = threadIdx.x;
    float v  = p[t];
    float bm = blockmax256(v);
    float dm = mask[r] * mask[b * Nn + t];
    p[t] = (t == i) ? 0.f : (bm - v) * dm;
}

// ---------------- out = LayerNorm(a + r); optional sq-norm of out ----------------
__global__ void addln_kernel(const float* __restrict__ a, const float* __restrict__ r,
                             const float* __restrict__ g, const float* __restrict__ be,
                             float* __restrict__ out, __half* __restrict__ outh,
                             float* __restrict__ sqout) {
    int row = blockIdx.x;
    int t = threadIdx.x;
    float vals[3];
    float s = 0.f;
    #pragma unroll
    for (int u = 0; u < 3; u++) {
        int c = t + u * 128;
        float v = a[(size_t)row * Hd + c] + r[(size_t)row * Hd + c];
        vals[u] = v;
        s += v;
    }
    float mu = blocksum128(s) * (1.f / Hd);
    float s2 = 0.f;
    #pragma unroll
    for (int u = 0; u < 3; u++) { float d = vals[u] - mu; s2 += d * d; }
    float var  = blocksum128(s2) * (1.f / Hd);
    float rstd = rsqrtf(var + 1e-5f);
    float s3 = 0.f;
    #pragma unroll
    for (int u = 0; u < 3; u++) {
        int c = t + u * 128;
        float o = (vals[u] - mu) * rstd * g[c] + be[c];
        out[(size_t)row * Hd + c]  = o;
        outh[(size_t)row * Hd + c] = __float2half(o);
        s3 += o * o;
    }
    if (sqout) {
        s3 = blocksum128(s3);
        if (t == 0) sqout[row] = s3;
    }
}

// ---------------- masked outputs ----------------
__global__ void out_x_kernel(const float* __restrict__ x, const float* __restrict__ mask,
                             float* __restrict__ out) {
    size_t idx = (size_t)blockIdx.x * blockDim.x + threadIdx.x;
    if (idx >= (size_t)Bn * Nn * XDim) return;
    out[idx] = x[idx] * mask[idx / XDim];
}
__global__ void out_e_kernel(const float* __restrict__ e, const float* __restrict__ mask,
                             float* __restrict__ out) {
    size_t idx = (size_t)blockIdx.x * blockDim.x + threadIdx.x;
    if (idx >= (size_t)Bn * Nn * Nn * EDim) return;
    size_t pair = idx / EDim;
    int j  = (int)(pair % Nn);
    size_t bi = pair / Nn;
    int b  = (int)(bi / Nn);
    out[idx] = e[idx] * mask[bi] * mask[(size_t)b * Nn + j];
}
__global__ void out_z_kernel(const float* __restrict__ mask, float* __restrict__ out) {
    size_t idx = (size_t)blockIdx.x * blockDim.x + threadIdx.x;
    if (idx >= (size_t)Mrows * Hd) return;
    out[idx] = g_z[idx] * mask[idx / Hd];
}

// ---------------- launcher ----------------
extern "C" void kernel_launch(void* const* d_in, const int* in_sizes, int n_in,
                              void* d_out, int out_size) {
    const float* x    = (const float*)d_in[0];
    const float* e    = (const float*)d_in[1];
    const float* mask = (const float*)d_in[2];
    const float* Wemb = (const float*)d_in[3];
    const float* Wq = (const float*)d_in[4];  const float* bq = (const float*)d_in[5];
    const float* Wk = (const float*)d_in[6];  const float* bk = (const float*)d_in[7];
    const float* Wv = (const float*)d_in[8];  const float* bv = (const float*)d_in[9];
    const float* Wo = (const float*)d_in[10]; const float* bo = (const float*)d_in[11];
    const float* g1 = (const float*)d_in[12]; const float* be1 = (const float*)d_in[13];
    const float* W1 = (const float*)d_in[14]; const float* b1  = (const float*)d_in[15];
    const float* W2 = (const float*)d_in[16]; const float* b2  = (const float*)d_in[17];
    const float* g2 = (const float*)d_in[18]; const float* be2 = (const float*)d_in[19];
    float* out = (float*)d_out;

    float  *z, *q, *x1, *sq;
    __half *cath, *zh, *x1h, *yh, *ffnh, *qhp, *khp, *vth;
    __half *wembTh, *wqTh, *wkTh, *wvTh, *woTh, *w1Th, *w2Th;
    cudaGetSymbolAddress((void**)&cath,  g_cath);
    cudaGetSymbolAddress((void**)&z,     g_z);
    cudaGetSymbolAddress((void**)&zh,    g_zh);
    cudaGetSymbolAddress((void**)&q,     g_q);
    cudaGetSymbolAddress((void**)&yh,    g_yh);
    cudaGetSymbolAddress((void**)&x1,    g_x1);
    cudaGetSymbolAddress((void**)&x1h,   g_x1h);
    cudaGetSymbolAddress((void**)&ffnh,  g_ffnh);
    cudaGetSymbolAddress((void**)&qhp,   g_qhp);
    cudaGetSymbolAddress((void**)&khp,   g_khp);
    cudaGetSymbolAddress((void**)&vth,   g_vth);
    cudaGetSymbolAddress((void**)&sq,    g_sq);
    cudaGetSymbolAddress((void**)&wembTh, g_wembTh);
    cudaGetSymbolAddress((void**)&wqTh,  g_wqTh);
    cudaGetSymbolAddress((void**)&wkTh,  g_wkTh);
    cudaGetSymbolAddress((void**)&wvTh,  g_wvTh);
    cudaGetSymbolAddress((void**)&woTh,  g_woTh);
    cudaGetSymbolAddress((void**)&w1Th,  g_w1Th);
    cudaGetSymbolAddress((void**)&w2Th,  g_w2Th);

    cudaFuncSetAttribute(gemm_h_kernel,
                         cudaFuncAttributeMaxDynamicSharedMemorySize, GK_SMEM_B);
    cudaFuncSetAttribute(distg_kernel,
                         cudaFuncAttributeMaxDynamicSharedMemorySize, GK_SMEM_B);
    cudaFuncSetAttribute(qksm_kernel,
                         cudaFuncAttributeMaxDynamicSharedMemorySize, QS_SMEM);
    cudaFuncSetAttribute(attnv_h_kernel,
                         cudaFuncAttributeMaxDynamicSharedMemorySize, AV_SMEM);

    dim3 tb(32, 8);
    {
        size_t tot = (size_t)Mrows * KPAD;
        cat_kernel<<<(unsigned)((tot + 255) / 256), 256>>>(x, e);
    }
    transpose_kernel<<<dim3(12, 44, 1), tb>>>(Wemb, wembTh, KCAT, Hd, KPAD, 0, 0);
    transpose_kernel<<<dim3(12, 12, DEPTH), tb>>>(Wq, wqTh, Hd, Hd, Hd,
                                                  (size_t)Hd * Hd, (size_t)Hd * Hd);
    transpose_kernel<<<dim3(12, 12, DEPTH), tb>>>(Wk, wkTh, Hd, Hd, Hd,
                                                  (size_t)Hd * Hd, (size_t)Hd * Hd);
    transpose_kernel<<<dim3(12, 12, DEPTH), tb>>>(Wv, wvTh, Hd, Hd, Hd,
                                                  (size_t)Hd * Hd, (size_t)Hd * Hd);
    gemm_h_kernel<<<dim3(Hd / 128, Mrows / 128), 256, GK_SMEM_B>>>(
        cath, KPAD, wembTh, KPAD, nullptr, z, zh, Hd, KPAD, 0, 0);
    transpose_kernel<<<dim3(12, 12, DEPTH), tb>>>(Wo, woTh, Hd, Hd, Hd,
                                                  (size_t)Hd * Hd, (size_t)Hd * Hd);
    transpose_kernel<<<dim3(48, 12, DEPTH), tb>>>(W1, w1Th, Hd, DFFd, Hd,
                                                  (size_t)Hd * DFFd, (size_t)DFFd * Hd);
    transpose_kernel<<<dim3(12, 48, DEPTH), tb>>>(W2, w2Th, DFFd, Hd, DFFd,
                                                  (size_t)DFFd * Hd, (size_t)Hd * DFFd);
    sqnorm_kernel<<<Mrows, 128>>>();   // layer-0 row norms

    for (int l = 0; l < DEPTH; l++) {
        const size_t wofs  = (size_t)l * Hd * Hd;
        const size_t w1ofs = (size_t)l * DFFd * Hd;
        // distance bias
        distg_kernel<<<dim3(2, 2, Bn), 256, GK_SMEM_B>>>(zh, mask);
        distbias_kernel<<<Mrows, 256>>>(mask);
        // QKV into per-head fp16 layouts
        gemm_h_kernel<<<dim3(Hd / 128, Mrows / 128), 256, GK_SMEM_B>>>(
            zh, Hd, wqTh + wofs, Hd, bq + (size_t)l * Hd, nullptr, qhp, Hd, Hd, 0, 1);
        gemm_h_kernel<<<dim3(Hd / 128, Mrows / 128), 256, GK_SMEM_B>>>(
            zh, Hd, wkTh + wofs, Hd, bk + (size_t)l * Hd, nullptr, khp, Hd, Hd, 0, 1);
        gemm_h_kernel<<<dim3(Hd / 128, Mrows / 128), 256, GK_SMEM_B>>>(
            zh, Hd, wvTh + wofs, Hd, bv + (size_t)l * Hd, nullptr, vth, Hd, Hd, 0, 2);
        // fused QK^T + bias + softmax, then AV
        qksm_kernel<<<dim3(4, Bn * NHd), 256, QS_SMEM>>>(qhp, khp, mask);
        attnv_h_kernel<<<dim3(2, Bn * NHd), 128, AV_SMEM>>>();
        // output projection + AddNorm
        gemm_h_kernel<<<dim3(Hd / 128, Mrows / 128), 256, GK_SMEM_B>>>(
            yh, Hd, woTh + wofs, Hd, bo + (size_t)l * Hd, q, nullptr, Hd, Hd, 0, 0);
        addln_kernel<<<Mrows, 128>>>(z, q, g1 + (size_t)l * Hd, be1 + (size_t)l * Hd,
                                     x1, x1h, nullptr);
        // FFN
        gemm_h_kernel<<<dim3(DFFd / 128, Mrows / 128), 256, GK_SMEM_B>>>(
            x1h, Hd, w1Th + w1ofs, Hd, b1 + (size_t)l * DFFd,
            nullptr, ffnh, DFFd, Hd, 1, 0);
        gemm_h_kernel<<<dim3(Hd / 128, Mrows / 128), 256, GK_SMEM_B>>>(
            ffnh, DFFd, w2Th + w1ofs, DFFd, b2 + (size_t)l * Hd,
            q, nullptr, Hd, DFFd, 0, 0);
        // final AddNorm also produces next layer's row sq-norms
        addln_kernel<<<Mrows, 128>>>(x1, q, g2 + (size_t)l * Hd, be2 + (size_t)l * Hd,
                                     z, zh, sq);
    }

    // outputs: [X_out | E_out | z_out]
    const size_t XTOT = (size_t)Bn * Nn * XDim;
    const size_t ETOT = (size_t)Bn * Nn * Nn * EDim;
    const size_t ZTOT = (size_t)Mrows * Hd;
    out_x_kernel<<<(unsigned)((XTOT + 255) / 256), 256>>>(x, mask, out);
    out_e_kernel<<<(unsigned)((ETOT + 255) / 256), 256>>>(e, mask, out + XTOT);
    out_z_kernel<<<(unsigned)((ZTOT + 255) / 256), 256>>>(mask, out + XTOT + ETOT);
    (void)in_sizes; (void)n_in; (void)out_size;
}

// round 10
// speedup vs baseline: 8.5388x; 1.0376x over previous
#include <cuda_runtime.h>
#include <cuda_fp16.h>
#include <math.h>
#include <stdint.h>

#define Bn    64
#define Nn    256
#define XDim  118
#define EDim  5
#define Hd    384
#define NHd   8
#define DHd   48
#define DFFd  1536
#define DEPTH 6
#define Mrows (Bn * Nn)            /* 16384 */
#define KCAT  (XDim + Nn * EDim)   /* 1398  */
#define KPAD  1408
#define EROW  (Nn * EDim)
#define H3    (3 * Hd)             /* 1152 */

// ---------------- scratch (device globals; zero-init, no allocation) ----------------
__device__ __half g_cath[(size_t)Mrows * KPAD];
__device__ float  g_z  [(size_t)Mrows * Hd];
__device__ __half g_zh [(size_t)Mrows * Hd];
__device__ float  g_q  [(size_t)Mrows * Hd];
__device__ __half g_yh [(size_t)Mrows * Hd];
__device__ float  g_x1 [(size_t)Mrows * Hd];
__device__ __half g_x1h[(size_t)Mrows * Hd];
__device__ __half g_ffnh[(size_t)Mrows * DFFd];
__device__ __half g_atth[(size_t)Bn * NHd * Nn * Nn];
__device__ float  g_D  [(size_t)Bn * Nn * Nn];
__device__ float  g_sq [Mrows];
// per-head padded Q/K: [b,h,256,64] (cols 48..63 stay zero)
__device__ __half g_qhp[(size_t)Bn * NHd * Nn * 64];
__device__ __half g_khp[(size_t)Bn * NHd * Nn * 64];
// per-head transposed V: [b,h,48,256]
__device__ __half g_vth[(size_t)Bn * NHd * DHd * Nn];
// transposed fp16 weights [N][K]
__device__ __half g_wembTh[(size_t)Hd * KPAD];
__device__ __half g_wqkvT[(size_t)DEPTH * H3 * Hd];
__device__ float  g_bqkv [(size_t)DEPTH * H3];
__device__ __half g_woTh [(size_t)DEPTH * Hd * Hd];
__device__ __half g_w1Th [(size_t)DEPTH * DFFd * Hd];
__device__ __half g_w2Th [(size_t)DEPTH * Hd * DFFd];

// ---------------- PTX helpers (sm_80+ base ISA) ----------------
__device__ __forceinline__ uint32_t smem_to_u32(const void* p) {
    uint32_t a;
    asm("{ .reg .u64 t; cvta.to.shared.u64 t, %1; cvt.u32.u64 %0, t; }"
        : "=r"(a) : "l"(p));
    return a;
}
#define CP_ASYNC16(dst, src) \
    asm volatile("cp.async.cg.shared.global [%0], [%1], 16;" \
                 :: "r"(dst), "l"(src) : "memory")
#define CP_COMMIT() asm volatile("cp.async.commit_group;" ::: "memory")
#define CP_WAIT1()  asm volatile("cp.async.wait_group 1;" ::: "memory")
#define CP_WAIT0()  asm volatile("cp.async.wait_group 0;" ::: "memory")
#define LDSM4(r, addr) \
    asm volatile("ldmatrix.sync.aligned.m8n8.x4.shared.b16 {%0,%1,%2,%3}, [%4];" \
                 : "=r"((r)[0]), "=r"((r)[1]), "=r"((r)[2]), "=r"((r)[3]) \
                 : "r"(addr))
#define MMA16816(d, a, b0_, b1_) \
    asm volatile("mma.sync.aligned.m16n8k16.row.col.f32.f16.f16.f32 " \
                 "{%0,%1,%2,%3}, {%4,%5,%6,%7}, {%8,%9}, {%0,%1,%2,%3};" \
                 : "+f"((d)[0]), "+f"((d)[1]), "+f"((d)[2]), "+f"((d)[3]) \
                 : "r"((a)[0]), "r"((a)[1]), "r"((a)[2]), "r"((a)[3]), \
                   "r"(b0_), "r"(b1_))

// ---------------- reductions ----------------
__device__ __forceinline__ float blocksum128(float v) {
    __shared__ float red[4];
    #pragma unroll
    for (int o = 16; o > 0; o >>= 1) v += __shfl_xor_sync(0xffffffffu, v, o);
    if ((threadIdx.x & 31) == 0) red[threadIdx.x >> 5] = v;
    __syncthreads();
    float s = red[0] + red[1] + red[2] + red[3];
    __syncthreads();
    return s;
}

// ---------------- concat [x | e_flat | 0-pad] -> fp16 ----------------
__global__ void cat_kernel(const float* __restrict__ x, const float* __restrict__ e) {
    size_t idx = (size_t)blockIdx.x * blockDim.x + threadIdx.x;
    if (idx >= (size_t)Mrows * KPAD) return;
    size_t r = idx / KPAD;
    int    c = (int)(idx - r * KPAD);
    float v;
    if (c < XDim)      v = x[r * XDim + c];
    else if (c < KCAT) v = e[r * (size_t)EROW + (c - XDim)];
    else               v = 0.f;
    g_cath[idx] = __float2half(v);
}

// ---------------- transpose fp32 -> fp16 ----------------
__global__ void transpose_kernel(const float* __restrict__ in, __half* __restrict__ out,
                                 int R, int C, int outLd,
                                 size_t inStride, size_t outStride) {
    __shared__ float tile[32][33];
    const float* ip = in + (size_t)blockIdx.z * inStride;
    __half* op = out + (size_t)blockIdx.z * outStride;
    int c0 = blockIdx.x * 32, r0 = blockIdx.y * 32;
    int tx = threadIdx.x, ty = threadIdx.y;
    #pragma unroll
    for (int i = 0; i < 32; i += 8) {
        int r = r0 + ty + i, c = c0 + tx;
        tile[ty + i][tx] = (r < R && c < C) ? ip[(size_t)r * C + c] : 0.f;
    }
    __syncthreads();
    #pragma unroll
    for (int i = 0; i < 32; i += 8) {
        int oc = c0 + ty + i, orow = r0 + tx;
        if (oc < C && orow < outLd)
            op[(size_t)oc * outLd + orow] = __float2half(tile[tx][ty + i]);
    }
}

// ---------------- concat qkv bias ----------------
__global__ void qkvbias_kernel(const float* __restrict__ bq, const float* __restrict__ bk,
                               const float* __restrict__ bv) {
    int i = blockIdx.x * blockDim.x + threadIdx.x;
    if (i >= DEPTH * H3) return;
    int l = i / H3, r = i - l * H3;
    float v;
    if (r < Hd)           v = bq[l * Hd + r];
    else if (r < 2 * Hd)  v = bk[l * Hd + r - Hd];
    else                  v = bv[l * Hd + r - 2 * Hd];
    g_bqkv[i] = v;
}

// ============================================================================
// fp16 HMMA GEMM, 128x128x32 tiles, 8 warps, 3-stage cp.async.
// mode 0: C fp32 (+Ch fp16 row-major)
// mode 3: fused QKV -> qhp/khp/vth head layouts (N = 1152)
// ============================================================================
#define GK_RS      40
#define GK_OPB     (128 * GK_RS * 2)
#define GK_STAGE_B (2 * GK_OPB)
#define GK_SMEM_B  (3 * GK_STAGE_B)

__global__ __launch_bounds__(256)
void gemm_h_kernel(const __half* __restrict__ A, int lda,
                   const __half* __restrict__ BT, int ldb,
                   const float* __restrict__ bias,
                   float* __restrict__ C, __half* __restrict__ Ch,
                   int ldc, int K, int relu, int mode) {
    extern __shared__ char smem[];
    const uint32_t sb = smem_to_u32(smem);
    const int t = threadIdx.x, lane = t & 31, wid = t >> 5;
    const int m0 = blockIdx.y * 128, n0 = blockIdx.x * 128;
    const int mW = (wid & 3) * 32, nW = (wid >> 2) * 64;

    const int r0 = t >> 2,          q0 = t & 3;
    const int r1 = (t + 256) >> 2,  q1 = (t + 256) & 3;
    const int lq = lane >> 3, lr = lane & 7;
    const int aRow = (lq & 1) * 8 + lr, aCol = (lq >> 1) * 8;
    const int bRow = (lq >> 1) * 8 + lr, bCol = (lq & 1) * 8;
    const uint32_t aOff = (uint32_t)(((mW + aRow) * GK_RS + aCol) * 2);
    const uint32_t bOff = (uint32_t)(GK_OPB + ((nW + bRow) * GK_RS + bCol) * 2);

    float acc[2][8][4];
    #pragma unroll
    for (int i = 0; i < 2; i++)
        #pragma unroll
        for (int j = 0; j < 8; j++)
            #pragma unroll
            for (int r = 0; r < 4; r++) acc[i][j][r] = 0.f;

    const int nch = K >> 5;
    auto issue = [&](int ch) {
        const uint32_t dstA = sb + (uint32_t)(ch % 3) * GK_STAGE_B;
        const uint32_t dstB = dstA + GK_OPB;
        const __half* sa  = A  + (size_t)m0 * lda + ch * 32;
        const __half* sbp = BT + (size_t)n0 * ldb + ch * 32;
        CP_ASYNC16(dstA + (uint32_t)((r0 * GK_RS + q0 * 8) * 2), sa  + (size_t)r0 * lda + q0 * 8);
        CP_ASYNC16(dstA + (uint32_t)((r1 * GK_RS + q1 * 8) * 2), sa  + (size_t)r1 * lda + q1 * 8);
        CP_ASYNC16(dstB + (uint32_t)((r0 * GK_RS + q0 * 8) * 2), sbp + (size_t)r0 * ldb + q0 * 8);
        CP_ASYNC16(dstB + (uint32_t)((r1 * GK_RS + q1 * 8) * 2), sbp + (size_t)r1 * ldb + q1 * 8);
        CP_COMMIT();
    };
    issue(0);
    issue(1);

    for (int ch = 0; ch < nch; ch++) {
        if (ch + 1 < nch) { CP_WAIT1(); } else { CP_WAIT0(); }
        __syncthreads();
        const uint32_t base = sb + (uint32_t)(ch % 3) * GK_STAGE_B;
        #pragma unroll
        for (int ks = 0; ks < 2; ks++) {
            uint32_t a[2][4], b[4][4];
            #pragma unroll
            for (int mt = 0; mt < 2; mt++)
                LDSM4(a[mt], base + aOff + (uint32_t)((mt * 16 * GK_RS + ks * 16) * 2));
            #pragma unroll
            for (int g = 0; g < 4; g++)
                LDSM4(b[g], base + bOff + (uint32_t)((g * 16 * GK_RS + ks * 16) * 2));
            #pragma unroll
            for (int mt = 0; mt < 2; mt++)
                #pragma unroll
                for (int g = 0; g < 4; g++) {
                    MMA16816(acc[mt][2 * g],     a[mt], b[g][0], b[g][1]);
                    MMA16816(acc[mt][2 * g + 1], a[mt], b[g][2], b[g][3]);
                }
        }
        if (ch + 2 < nch) issue(ch + 2);
    }

    const int rBase = m0 + mW + (lane >> 2);
    const int cBase = n0 + nW + (lane & 3) * 2;
    #pragma unroll
    for (int mt = 0; mt < 2; mt++) {
        #pragma unroll
        for (int nt = 0; nt < 8; nt++) {
            const int c = cBase + nt * 8;
            float b0 = 0.f, b1 = 0.f;
            if (bias) { b0 = bias[c]; b1 = bias[c + 1]; }
            float v00 = acc[mt][nt][0] + b0, v01 = acc[mt][nt][1] + b1;
            float v10 = acc[mt][nt][2] + b0, v11 = acc[mt][nt][3] + b1;
            if (relu) {
                v00 = fmaxf(v00, 0.f); v01 = fmaxf(v01, 0.f);
                v10 = fmaxf(v10, 0.f); v11 = fmaxf(v11, 0.f);
            }
            const int rA = rBase + mt * 16, rB = rA + 8;
            if (mode == 0) {
                if (C) {
                    *(float2*)(C + (size_t)rA * ldc + c) = make_float2(v00, v01);
                    *(float2*)(C + (size_t)rB * ldc + c) = make_float2(v10, v11);
                }
                if (Ch) {
                    *(__half2*)(Ch + (size_t)rA * ldc + c) = __floats2half2_rn(v00, v01);
                    *(__half2*)(Ch + (size_t)rB * ldc + c) = __floats2half2_rn(v10, v11);
                }
            } else {
                // mode 3: c in [0,1152): sec 0=Q,1=K,2=V
                const int sec = c / Hd;
                const int cc  = c - sec * Hd;
                const int h = cc / DHd, d = cc - h * DHd;
                const int bIdx = rA >> 8;
                if (sec < 2) {
                    __half* dst = (sec == 0) ? g_qhp : g_khp;
                    size_t p0 = ((((size_t)bIdx * NHd + h) << 8) | (rA & 255)) * 64 + d;
                    size_t p1 = ((((size_t)bIdx * NHd + h) << 8) | (rB & 255)) * 64 + d;
                    *(__half2*)(dst + p0) = __floats2half2_rn(v00, v01);
                    *(__half2*)(dst + p1) = __floats2half2_rn(v10, v11);
                } else {
                    size_t hb = ((size_t)bIdx * NHd + h) * DHd;
                    g_vth[(hb + d)     * Nn + (rA & 255)] = __float2half(v00);
                    g_vth[(hb + d + 1) * Nn + (rA & 255)] = __float2half(v01);
                    g_vth[(hb + d)     * Nn + (rB & 255)] = __float2half(v10);
                    g_vth[(hb + d + 1) * Nn + (rB & 255)] = __float2half(v11);
                }
            }
        }
    }
}

// ============================================================================
// distrow: fused gram(zh) + sqrt + mask + rowmax-bias, one pass -> g_D
// Tile 64m x 256n (full row), K=384, 8 warps (4m x 2n), 3-stage cp.async.
// ============================================================================
#define DR_ARS   40
#define DR_ABUF  (64 * DR_ARS * 2)     /*  5120 */
#define DR_BBUF  (256 * DR_ARS * 2)    /* 20480 */
#define DR_STAGE (DR_ABUF + DR_BBUF)   /* 25600 */
#define DR_RED   (3 * DR_STAGE)        /* 76800 */
#define DR_SMEM  (DR_RED + 128 * 4)

__global__ __launch_bounds__(256)
void distrow_kernel(const __half* __restrict__ Z, const float* __restrict__ mask) {
    extern __shared__ char smem[];
    const uint32_t sb = smem_to_u32(smem);
    float* rmax = (float*)(smem + DR_RED);
    const int t = threadIdx.x, lane = t & 31, wid = t >> 5;
    const int bz = blockIdx.y, m0 = blockIdx.x * 64;
    const __half* A = Z + (size_t)bz * Nn * Hd + (size_t)m0 * Hd;
    const __half* B = Z + (size_t)bz * Nn * Hd;
    const int mW = (wid & 3) * 16, nW = (wid >> 2) * 128;

    const int lq = lane >> 3, lr = lane & 7;
    const int aRow = (lq & 1) * 8 + lr, aCol = (lq >> 1) * 8;
    const int bRow = (lq >> 1) * 8 + lr, bCol = (lq & 1) * 8;
    const uint32_t aOff = (uint32_t)(((mW + aRow) * DR_ARS + aCol) * 2);
    const uint32_t bOff = (uint32_t)(DR_ABUF + ((nW + bRow) * DR_ARS + bCol) * 2);

    float acc[16][4];
    #pragma unroll
    for (int j = 0; j < 16; j++)
        #pragma unroll
        for (int r = 0; r < 4; r++) acc[j][r] = 0.f;

    const int sr = t >> 2, sg = t & 3;
    auto issue = [&](int ch) {
        const uint32_t dstA = sb + (uint32_t)(ch % 3) * DR_STAGE;
        const uint32_t dstB = dstA + DR_ABUF;
        {
            int row = sr & 63, half = sr >> 6;   // threads 0..255 -> 64 rows x 4 segs
            // A: 64 rows x 32 halves = 256 chunks, 1 per thread
            (void)half;
        }
        // A: 256 chunks (row = t>>2, seg = t&3)
        CP_ASYNC16(dstA + (uint32_t)(((t >> 2) * DR_ARS + (t & 3) * 8) * 2),
                   A + (size_t)(t >> 2) * Hd + ch * 32 + (t & 3) * 8);
        // B: 1024 chunks, 4 per thread
        #pragma unroll
        for (int u = 0; u < 4; u++) {
            int p = t + u * 256, row = p >> 2, seg = p & 3;
            CP_ASYNC16(dstB + (uint32_t)((row * DR_ARS + seg * 8) * 2),
                       B + (size_t)row * Hd + ch * 32 + seg * 8);
        }
        CP_COMMIT();
    };
    (void)sr; (void)sg;
    issue(0);
    issue(1);

    const int nch = Hd >> 5;  // 12
    for (int ch = 0; ch < nch; ch++) {
        if (ch + 1 < nch) { CP_WAIT1(); } else { CP_WAIT0(); }
        __syncthreads();
        const uint32_t base = sb + (uint32_t)(ch % 3) * DR_STAGE;
        #pragma unroll
        for (int ks = 0; ks < 2; ks++) {
            uint32_t a[4];
            LDSM4(a, base + aOff + (uint32_t)(ks * 16 * 2));
            #pragma unroll
            for (int g = 0; g < 8; g++) {
                uint32_t bf[4];
                LDSM4(bf, base + bOff + (uint32_t)((g * 16 * DR_ARS + ks * 16) * 2));
                MMA16816(acc[2 * g],     a, bf[0], bf[1]);
                MMA16816(acc[2 * g + 1], a, bf[2], bf[3]);
            }
        }
        if (ch + 2 < nch) issue(ch + 2);
    }

    // epilogue: masked distances, rowmax, bias, write
    const int rloc0 = mW + (lane >> 2), rloc1 = rloc0 + 8;
    const int gi0 = m0 + rloc0, gi1 = m0 + rloc1;
    const int cB = nW + (lane & 3) * 2;
    const float sqi0 = g_sq[bz * Nn + gi0], sqi1 = g_sq[bz * Nn + gi1];
    const float mi0 = mask[bz * Nn + gi0],  mi1 = mask[bz * Nn + gi1];
    #pragma unroll
    for (int nt = 0; nt < 16; nt++) {
        const int gj = cB + nt * 8;
        float sj0 = g_sq[bz * Nn + gj], sj1 = g_sq[bz * Nn + gj + 1];
        float mj0 = mask[bz * Nn + gj], mj1 = mask[bz * Nn + gj + 1];
        float d2;
        d2 = fmaxf(sqi0 + sj0 - 2.f * acc[nt][0], 0.f);
        acc[nt][0] = ((d2 > 1e-12f) ? sqrtf(d2) : 0.f) * mi0 * mj0;
        d2 = fmaxf(sqi0 + sj1 - 2.f * acc[nt][1], 0.f);
        acc[nt][1] = ((d2 > 1e-12f) ? sqrtf(d2) : 0.f) * mi0 * mj1;
        d2 = fmaxf(sqi1 + sj0 - 2.f * acc[nt][2], 0.f);
        acc[nt][2] = ((d2 > 1e-12f) ? sqrtf(d2) : 0.f) * mi1 * mj0;
        d2 = fmaxf(sqi1 + sj1 - 2.f * acc[nt][3], 0.f);
        acc[nt][3] = ((d2 > 1e-12f) ? sqrtf(d2) : 0.f) * mi1 * mj1;
    }
    float mx0 = 0.f, mx1 = 0.f;   // distances >= 0
    #pragma unroll
    for (int nt = 0; nt < 16; nt++) {
        mx0 = fmaxf(mx0, fmaxf(acc[nt][0], acc[nt][1]));
        mx1 = fmaxf(mx1, fmaxf(acc[nt][2], acc[nt][3]));
    }
    #pragma unroll
    for (int o = 1; o < 4; o <<= 1) {
        mx0 = fmaxf(mx0, __shfl_xor_sync(0xffffffffu, mx0, o));
        mx1 = fmaxf(mx1, __shfl_xor_sync(0xffffffffu, mx1, o));
    }
    const int nw = wid >> 2;
    rmax[nw * 64 + rloc0] = mx0;
    rmax[nw * 64 + rloc1] = mx1;
    __syncthreads();
    const float M0 = fmaxf(rmax[rloc0], rmax[64 + rloc0]);
    const float M1 = fmaxf(rmax[rloc1], rmax[64 + rloc1]);
    float* Dp = g_D + (size_t)bz * Nn * Nn;
    #pragma unroll
    for (int nt = 0; nt < 16; nt++) {
        const int gj = cB + nt * 8;
        float mj0 = mask[bz * Nn + gj], mj1 = mask[bz * Nn + gj + 1];
        float o00 = (gi0 == gj)     ? 0.f : (M0 - acc[nt][0]) * mi0 * mj0;
        float o01 = (gi0 == gj + 1) ? 0.f : (M0 - acc[nt][1]) * mi0 * mj1;
        float o10 = (gi1 == gj)     ? 0.f : (M1 - acc[nt][2]) * mi1 * mj0;
        float o11 = (gi1 == gj + 1) ? 0.f : (M1 - acc[nt][3]) * mi1 * mj1;
        *(float2*)(Dp + (size_t)gi0 * Nn + gj) = make_float2(o00, o01);
        *(float2*)(Dp + (size_t)gi1 * Nn + gj) = make_float2(o10, o11);
    }
}

// ============================================================================
// qksm: fused QK^T + D-bias + softmax -> fp16 probs. 64m x 256n, K=64.
// ============================================================================
#define QS_ARS   72
#define QS_ABUF  (64 * QS_ARS * 2)
#define QS_BBUF  (256 * QS_ARS * 2)
#define QS_RED   (QS_ABUF + QS_BBUF)
#define QS_SMEM  (QS_RED + 2 * 128 * 4)

__global__ __launch_bounds__(256)
void qksm_kernel(const __half* __restrict__ qhp, const __half* __restrict__ khp) {
    extern __shared__ char smem[];
    const uint32_t sb = smem_to_u32(smem);
    float* rmax = (float*)(smem + QS_RED);
    float* rsum = rmax + 128;
    const int t = threadIdx.x, lane = t & 31, wid = t >> 5;
    const int bh = blockIdx.y, m0 = blockIdx.x * 64;
    const int b = bh >> 3;
    const __half* A = qhp + (size_t)bh * Nn * 64 + (size_t)m0 * 64;
    const __half* B = khp + (size_t)bh * Nn * 64;
    const int mW = (wid & 3) * 16, nW = (wid >> 2) * 128;

    #pragma unroll
    for (int u = 0; u < 2; u++) {
        int p = t + u * 256, row = p >> 3, seg = p & 7;
        CP_ASYNC16(sb + (uint32_t)((row * QS_ARS + seg * 8) * 2),
                   A + (size_t)row * 64 + seg * 8);
    }
    #pragma unroll
    for (int u = 0; u < 8; u++) {
        int p = t + u * 256, row = p >> 3, seg = p & 7;
        CP_ASYNC16(sb + (uint32_t)(QS_ABUF + (row * QS_ARS + seg * 8) * 2),
                   B + (size_t)row * 64 + seg * 8);
    }
    CP_COMMIT();
    CP_WAIT0();
    __syncthreads();

    const int lq = lane >> 3, lr = lane & 7;
    const int aRow = (lq & 1) * 8 + lr, aCol = (lq >> 1) * 8;
    const int bRow = (lq >> 1) * 8 + lr, bCol = (lq & 1) * 8;
    const uint32_t aOff = sb + (uint32_t)(((mW + aRow) * QS_ARS + aCol) * 2);
    const uint32_t bOff = sb + (uint32_t)(QS_ABUF + ((nW + bRow) * QS_ARS + bCol) * 2);

    float acc[16][4];
    #pragma unroll
    for (int j = 0; j < 16; j++)
        #pragma unroll
        for (int r = 0; r < 4; r++) acc[j][r] = 0.f;

    #pragma unroll
    for (int ks = 0; ks < 4; ks++) {
        uint32_t a[4];
        LDSM4(a, aOff + (uint32_t)(ks * 16 * 2));
        #pragma unroll
        for (int g = 0; g < 8; g++) {
            uint32_t bf[4];
            LDSM4(bf, bOff + (uint32_t)((g * 16 * QS_ARS + ks * 16) * 2));
            MMA16816(acc[2 * g],     a, bf[0], bf[1]);
            MMA16816(acc[2 * g + 1], a, bf[2], bf[3]);
        }
    }

    const float scale = 0.144337567297406441f;
    const int rloc0 = mW + (lane >> 2), rloc1 = rloc0 + 8;
    const int gi0 = m0 + rloc0, gi1 = m0 + rloc1;
    const int cB = nW + (lane & 3) * 2;
    #pragma unroll
    for (int nt = 0; nt < 16; nt++) {
        const int gj = cB + nt * 8;
        float2 d0 = *(const float2*)(g_D + ((size_t)b * Nn + gi0) * Nn + gj);
        float2 d1 = *(const float2*)(g_D + ((size_t)b * Nn + gi1) * Nn + gj);
        acc[nt][0] = acc[nt][0] * scale + d0.x;
        acc[nt][1] = acc[nt][1] * scale + d0.y;
        acc[nt][2] = acc[nt][2] * scale + d1.x;
        acc[nt][3] = acc[nt][3] * scale + d1.y;
    }
    float mx0 = -1e30f, mx1 = -1e30f;
    #pragma unroll
    for (int nt = 0; nt < 16; nt++) {
        mx0 = fmaxf(mx0, fmaxf(acc[nt][0], acc[nt][1]));
        mx1 = fmaxf(mx1, fmaxf(acc[nt][2], acc[nt][3]));
    }
    #pragma unroll
    for (int o = 1; o < 4; o <<= 1) {
        mx0 = fmaxf(mx0, __shfl_xor_sync(0xffffffffu, mx0, o));
        mx1 = fmaxf(mx1, __shfl_xor_sync(0xffffffffu, mx1, o));
    }
    const int nw = wid >> 2;
    rmax[nw * 64 + rloc0] = mx0;
    rmax[nw * 64 + rloc1] = mx1;
    __syncthreads();
    const float M0 = fmaxf(rmax[rloc0], rmax[64 + rloc0]);
    const float M1 = fmaxf(rmax[rloc1], rmax[64 + rloc1]);
    float s0 = 0.f, s1 = 0.f;
    #pragma unroll
    for (int nt = 0; nt < 16; nt++) {
        acc[nt][0] = __expf(acc[nt][0] - M0);
        acc[nt][1] = __expf(acc[nt][1] - M0);
        acc[nt][2] = __expf(acc[nt][2] - M1);
        acc[nt][3] = __expf(acc[nt][3] - M1);
        s0 += acc[nt][0] + acc[nt][1];
        s1 += acc[nt][2] + acc[nt][3];
    }
    #pragma unroll
    for (int o = 1; o < 4; o <<= 1) {
        s0 += __shfl_xor_sync(0xffffffffu, s0, o);
        s1 += __shfl_xor_sync(0xffffffffu, s1, o);
    }
    rsum[nw * 64 + rloc0] = s0;
    rsum[nw * 64 + rloc1] = s1;
    __syncthreads();
    const float inv0 = 1.f / (rsum[rloc0] + rsum[64 + rloc0]);
    const float inv1 = 1.f / (rsum[rloc1] + rsum[64 + rloc1]);
    __half* outp = g_atth + (size_t)bh * Nn * Nn;
    #pragma unroll
    for (int nt = 0; nt < 16; nt++) {
        const int gj = cB + nt * 8;
        *(__half2*)(outp + (size_t)gi0 * Nn + gj) =
            __floats2half2_rn(acc[nt][0] * inv0, acc[nt][1] * inv0);
        *(__half2*)(outp + (size_t)gi1 * Nn + gj) =
            __floats2half2_rn(acc[nt][2] * inv1, acc[nt][3] * inv1);
    }
}

// ============================================================================
// attnv: y = P @ V^T per head. 128m x 48n x 256k, 4 warps, 3-stage cp.async.
// ============================================================================
#define AV_RS    40
#define AV_ABUF  (128 * AV_RS * 2)
#define AV_BBUF  (48 * AV_RS * 2)
#define AV_STAGE (AV_ABUF + AV_BBUF)
#define AV_SMEM  (3 * AV_STAGE)

__global__ __launch_bounds__(128)
void attnv_h_kernel() {
    extern __shared__ char smem[];
    const uint32_t sb = smem_to_u32(smem);
    const int t = threadIdx.x, lane = t & 31, wid = t >> 5;
    const int bh = blockIdx.y, m0 = blockIdx.x * 128;
    const __half* A = g_atth + (size_t)bh * Nn * Nn;
    const __half* B = g_vth + (size_t)bh * DHd * Nn;
    const int mW = wid * 32;

    const int lq = lane >> 3, lr = lane & 7;
    const int aRow = (lq & 1) * 8 + lr, aCol = (lq >> 1) * 8;
    const int bRow = (lq >> 1) * 8 + lr, bCol = (lq & 1) * 8;
    const uint32_t aOff = (uint32_t)(((mW + aRow) * AV_RS + aCol) * 2);
    const uint32_t bOff = (uint32_t)(AV_ABUF + (bRow * AV_RS + bCol) * 2);

    float acc[2][6][4];
    #pragma unroll
    for (int i = 0; i < 2; i++)
        #pragma unroll
        for (int j = 0; j < 6; j++)
            #pragma unroll
            for (int r = 0; r < 4; r++) acc[i][j][r] = 0.f;

    auto issue = [&](int ch) {
        const uint32_t dstA = sb + (uint32_t)(ch % 3) * AV_STAGE;
        const uint32_t dstB = dstA + AV_ABUF;
        #pragma unroll
        for (int u = 0; u < 4; u++) {
            int p = t + u * 128, row = p >> 2, seg = p & 3;
            CP_ASYNC16(dstA + (uint32_t)((row * AV_RS + seg * 8) * 2),
                       A + (size_t)(m0 + row) * Nn + ch * 32 + seg * 8);
        }
        #pragma unroll
        for (int u = 0; u < 2; u++) {
            int p = t + u * 128;
            if (p < 192) {
                int row = p >> 2, seg = p & 3;
                CP_ASYNC16(dstB + (uint32_t)((row * AV_RS + seg * 8) * 2),
                           B + (size_t)row * Nn + ch * 32 + seg * 8);
            }
        }
        CP_COMMIT();
    };
    issue(0);
    issue(1);

    const int nch = Nn >> 5;
    for (int ch = 0; ch < nch; ch++) {
        if (ch + 1 < nch) { CP_WAIT1(); } else { CP_WAIT0(); }
        __syncthreads();
        const uint32_t base = sb + (uint32_t)(ch % 3) * AV_STAGE;
        #pragma unroll
        for (int ks = 0; ks < 2; ks++) {
            uint32_t a[2][4], b[3][4];
            #pragma unroll
            for (int mt = 0; mt < 2; mt++)
                LDSM4(a[mt], base + aOff + (uint32_t)((mt * 16 * AV_RS + ks * 16) * 2));
            #pragma unroll
            for (int g = 0; g < 3; g++)
                LDSM4(b[g], base + bOff + (uint32_t)((g * 16 * AV_RS + ks * 16) * 2));
            #pragma unroll
            for (int mt = 0; mt < 2; mt++)
                #pragma unroll
                for (int g = 0; g < 3; g++) {
                    MMA16816(acc[mt][2 * g],     a[mt], b[g][0], b[g][1]);
                    MMA16816(acc[mt][2 * g + 1], a[mt], b[g][2], b[g][3]);
                }
        }
        if (ch + 2 < nch) issue(ch + 2);
    }

    const int b = bh >> 3, h = bh & 7;
    const int rBase = m0 + mW + (lane >> 2);
    const int cBase = (lane & 3) * 2;
    #pragma unroll
    for (int mt = 0; mt < 2; mt++) {
        #pragma unroll
        for (int nt = 0; nt < 6; nt++) {
            const int c = cBase + nt * 8;
            const int gi = rBase + mt * 16;
            *(__half2*)(g_yh + ((size_t)b * Nn + gi) * Hd + h * DHd + c) =
                __floats2half2_rn(acc[mt][nt][0], acc[mt][nt][1]);
            *(__half2*)(g_yh + ((size_t)b * Nn + gi + 8) * Hd + h * DHd + c) =
                __floats2half2_rn(acc[mt][nt][2], acc[mt][nt][3]);
        }
    }
}

// ---------------- row squared norms of z (post-embed only) ----------------
__global__ void sqnorm_kernel() {
    int r = blockIdx.x;
    float s = 0.f;
    for (int c = threadIdx.x; c < Hd; c += 128) {
        float v = g_z[(size_t)r * Hd + c];
        s += v * v;
    }
    s = blocksum128(s);
    if (threadIdx.x == 0) g_sq[r] = s;
}

// ---------------- out = LayerNorm(a + r); optional sq-norm of out ----------------
__global__ void addln_kernel(const float* __restrict__ a, const float* __restrict__ r,
                             const float* __restrict__ g, const float* __restrict__ be,
                             float* __restrict__ out, __half* __restrict__ outh,
                             float* __restrict__ sqout) {
    int row = blockIdx.x;
    int t = threadIdx.x;
    float vals[3];
    float s = 0.f;
    #pragma unroll
    for (int u = 0; u < 3; u++) {
        int c = t + u * 128;
        float v = a[(size_t)row * Hd + c] + r[(size_t)row * Hd + c];
        vals[u] = v;
        s += v;
    }
    float mu = blocksum128(s) * (1.f / Hd);
    float s2 = 0.f;
    #pragma unroll
    for (int u = 0; u < 3; u++) { float d = vals[u] - mu; s2 += d * d; }
    float var  = blocksum128(s2) * (1.f / Hd);
    float rstd = rsqrtf(var + 1e-5f);
    float s3 = 0.f;
    #pragma unroll
    for (int u = 0; u < 3; u++) {
        int c = t + u * 128;
        float o = (vals[u] - mu) * rstd * g[c] + be[c];
        out[(size_t)row * Hd + c]  = o;
        outh[(size_t)row * Hd + c] = __float2half(o);
        s3 += o * o;
    }
    if (sqout) {
        s3 = blocksum128(s3);
        if (t == 0) sqout[row] = s3;
    }
}

// ---------------- masked outputs ----------------
__global__ void out_x_kernel(const float* __restrict__ x, const float* __restrict__ mask,
                             float* __restrict__ out) {
    size_t idx = (size_t)blockIdx.x * blockDim.x + threadIdx.x;
    if (idx >= (size_t)Bn * Nn * XDim) return;
    out[idx] = x[idx] * mask[idx / XDim];
}
__global__ void out_e_kernel(const float* __restrict__ e, const float* __restrict__ mask,
                             float* __restrict__ out) {
    size_t idx = (size_t)blockIdx.x * blockDim.x + threadIdx.x;
    if (idx >= (size_t)Bn * Nn * Nn * EDim) return;
    size_t pair = idx / EDim;
    int j  = (int)(pair % Nn);
    size_t bi = pair / Nn;
    int b  = (int)(bi / Nn);
    out[idx] = e[idx] * mask[bi] * mask[(size_t)b * Nn + j];
}
__global__ void out_z_kernel(const float* __restrict__ mask, float* __restrict__ out) {
    size_t idx = (size_t)blockIdx.x * blockDim.x + threadIdx.x;
    if (idx >= (size_t)Mrows * Hd) return;
    out[idx] = g_z[idx] * mask[idx / Hd];
}

// ---------------- launcher ----------------
extern "C" void kernel_launch(void* const* d_in, const int* in_sizes, int n_in,
                              void* d_out, int out_size) {
    const float* x    = (const float*)d_in[0];
    const float* e    = (const float*)d_in[1];
    const float* mask = (const float*)d_in[2];
    const float* Wemb = (const float*)d_in[3];
    const float* Wq = (const float*)d_in[4];  const float* bq = (const float*)d_in[5];
    const float* Wk = (const float*)d_in[6];  const float* bk = (const float*)d_in[7];
    const float* Wv = (const float*)d_in[8];  const float* bv = (const float*)d_in[9];
    const float* Wo = (const float*)d_in[10]; const float* bo = (const float*)d_in[11];
    const float* g1 = (const float*)d_in[12]; const float* be1 = (const float*)d_in[13];
    const float* W1 = (const float*)d_in[14]; const float* b1  = (const float*)d_in[15];
    const float* W2 = (const float*)d_in[16]; const float* b2  = (const float*)d_in[17];
    const float* g2 = (const float*)d_in[18]; const float* be2 = (const float*)d_in[19];
    float* out = (float*)d_out;

    float  *z, *q, *x1, *sq, *bqkv;
    __half *cath, *zh, *x1h, *yh, *ffnh, *qhp, *khp;
    __half *wembTh, *wqkvT, *woTh, *w1Th, *w2Th;
    cudaGetSymbolAddress((void**)&cath,  g_cath);
    cudaGetSymbolAddress((void**)&z,     g_z);
    cudaGetSymbolAddress((void**)&zh,    g_zh);
    cudaGetSymbolAddress((void**)&q,     g_q);
    cudaGetSymbolAddress((void**)&yh,    g_yh);
    cudaGetSymbolAddress((void**)&x1,    g_x1);
    cudaGetSymbolAddress((void**)&x1h,   g_x1h);
    cudaGetSymbolAddress((void**)&ffnh,  g_ffnh);
    cudaGetSymbolAddress((void**)&qhp,   g_qhp);
    cudaGetSymbolAddress((void**)&khp,   g_khp);
    cudaGetSymbolAddress((void**)&sq,    g_sq);
    cudaGetSymbolAddress((void**)&bqkv,  g_bqkv);
    cudaGetSymbolAddress((void**)&wembTh, g_wembTh);
    cudaGetSymbolAddress((void**)&wqkvT, g_wqkvT);
    cudaGetSymbolAddress((void**)&woTh,  g_woTh);
    cudaGetSymbolAddress((void**)&w1Th,  g_w1Th);
    cudaGetSymbolAddress((void**)&w2Th,  g_w2Th);

    cudaFuncSetAttribute(gemm_h_kernel,
                         cudaFuncAttributeMaxDynamicSharedMemorySize, GK_SMEM_B);
    cudaFuncSetAttribute(distrow_kernel,
                         cudaFuncAttributeMaxDynamicSharedMemorySize, DR_SMEM);
    cudaFuncSetAttribute(qksm_kernel,
                         cudaFuncAttributeMaxDynamicSharedMemorySize, QS_SMEM);
    cudaFuncSetAttribute(attnv_h_kernel,
                         cudaFuncAttributeMaxDynamicSharedMemorySize, AV_SMEM);

    dim3 tb(32, 8);
    {
        size_t tot = (size_t)Mrows * KPAD;
        cat_kernel<<<(unsigned)((tot + 255) / 256), 256>>>(x, e);
    }
    transpose_kernel<<<dim3(12, 44, 1), tb>>>(Wemb, wembTh, KCAT, Hd, KPAD, 0, 0);
    // QKV weights -> concatenated [1152][384] per layer
    transpose_kernel<<<dim3(12, 12, DEPTH), tb>>>(Wq, wqkvT, Hd, Hd, Hd,
                                                  (size_t)Hd * Hd, (size_t)H3 * Hd);
    transpose_kernel<<<dim3(12, 12, DEPTH), tb>>>(Wk, wqkvT + (size_t)Hd * Hd, Hd, Hd, Hd,
                                                  (size_t)Hd * Hd, (size_t)H3 * Hd);
    transpose_kernel<<<dim3(12, 12, DEPTH), tb>>>(Wv, wqkvT + 2 * (size_t)Hd * Hd, Hd, Hd, Hd,
                                                  (size_t)Hd * Hd, (size_t)H3 * Hd);
    qkvbias_kernel<<<(DEPTH * H3 + 255) / 256, 256>>>(bq, bk, bv);
    gemm_h_kernel<<<dim3(Hd / 128, Mrows / 128), 256, GK_SMEM_B>>>(
        cath, KPAD, wembTh, KPAD, nullptr, z, zh, Hd, KPAD, 0, 0);
    transpose_kernel<<<dim3(12, 12, DEPTH), tb>>>(Wo, woTh, Hd, Hd, Hd,
                                                  (size_t)Hd * Hd, (size_t)Hd * Hd);
    transpose_kernel<<<dim3(48, 12, DEPTH), tb>>>(W1, w1Th, Hd, DFFd, Hd,
                                                  (size_t)Hd * DFFd, (size_t)DFFd * Hd);
    transpose_kernel<<<dim3(12, 48, DEPTH), tb>>>(W2, w2Th, DFFd, Hd, DFFd,
                                                  (size_t)DFFd * Hd, (size_t)Hd * DFFd);
    sqnorm_kernel<<<Mrows, 128>>>();

    for (int l = 0; l < DEPTH; l++) {
        const size_t wofs  = (size_t)l * Hd * Hd;
        const size_t w1ofs = (size_t)l * DFFd * Hd;
        // fused distance-bias (gram + sqrt + rowmax bias in one pass)
        distrow_kernel<<<dim3(4, Bn), 256, DR_SMEM>>>(zh, mask);
        // fused QKV GEMM (N = 1152) into per-head layouts
        gemm_h_kernel<<<dim3(H3 / 128, Mrows / 128), 256, GK_SMEM_B>>>(
            zh, Hd, wqkvT + (size_t)l * H3 * Hd, Hd, bqkv + (size_t)l * H3,
            nullptr, nullptr, 0, Hd, 0, 3);
        // attention
        qksm_kernel<<<dim3(4, Bn * NHd), 256, QS_SMEM>>>(qhp, khp);
        attnv_h_kernel<<<dim3(2, Bn * NHd), 128, AV_SMEM>>>();
        // output projection + AddNorm
        gemm_h_kernel<<<dim3(Hd / 128, Mrows / 128), 256, GK_SMEM_B>>>(
            yh, Hd, woTh + wofs, Hd, bo + (size_t)l * Hd, q, nullptr, Hd, Hd, 0, 0);
        addln_kernel<<<Mrows, 128>>>(z, q, g1 + (size_t)l * Hd, be1 + (size_t)l * Hd,
                                     x1, x1h, nullptr);
        // FFN
        gemm_h_kernel<<<dim3(DFFd / 128, Mrows / 128), 256, GK_SMEM_B>>>(
            x1h, Hd, w1Th + w1ofs, Hd, b1 + (size_t)l * DFFd,
            nullptr, ffnh, DFFd, Hd, 1, 0);
        gemm_h_kernel<<<dim3(Hd / 128, Mrows / 128), 256, GK_SMEM_B>>>(
            ffnh, DFFd, w2Th + w1ofs, DFFd, b2 + (size_t)l * Hd,
            q, nullptr, Hd, DFFd, 0, 0);
        addln_kernel<<<Mrows, 128>>>(x1, q, g2 + (size_t)l * Hd, be2 + (size_t)l * Hd,
                                     z, zh, sq);
    }

    // outputs: [X_out | E_out | z_out]
    const size_t XTOT = (size_t)Bn * Nn * XDim;
    const size_t ETOT = (size_t)Bn * Nn * Nn * EDim;
    const size_t ZTOT = (size_t)Mrows * Hd;
    out_x_kernel<<<(unsigned)((XTOT + 255) / 256), 256>>>(x, mask, out);
    out_e_kernel<<<(unsigned)((ETOT + 255) / 256), 256>>>(e, mask, out + XTOT);
    out_z_kernel<<<(unsigned)((ZTOT + 255) / 256), 256>>>(mask, out + XTOT + ETOT);
    (void)in_sizes; (void)n_in; (void)out_size;
}